// round 11
// baseline (speedup 1.0000x reference)
#include <cuda_runtime.h>
#include <cuda_fp16.h>
#include <math.h>
#include <stdint.h>

#define Hd    256
#define Wdim  256
#define HWd   65536
#define Cd    192
#define Bd    4
#define NHd   6
#define HDd   32
#define NWINd 4096
#define MTOKd 262144
#define HIDd  768
#define QSCALE 0.17677669529663687f

// -------- scratch --------
__device__ __half g_biash[NHd * 64 * 64];
__device__ __half w_qh [36864];
__device__ __half w_kvh[73728];
__device__ __half w_ch [36864];     // combined merge@proj weight
__device__ float  g_bc [192];       // combined bias m_w @ p_b
__device__ __half w_f1h[147456];
__device__ __half w_f2h[147456];

__device__ __forceinline__ float warp_sum(float v) {
#pragma unroll
    for (int o = 16; o; o >>= 1) v += __shfl_xor_sync(0xffffffffu, v, o);
    return v;
}
__device__ __forceinline__ unsigned h2u(__half2 h) {
    return *reinterpret_cast<unsigned*>(&h);
}
__device__ __forceinline__ float gelu_f(float v) {
    return 0.5f * v * (1.f + erff(v * 0.70710678118654752f));
}
__device__ __forceinline__ void mma16(float* c, const unsigned* a, unsigned b0, unsigned b1) {
    asm volatile(
        "mma.sync.aligned.m16n8k16.row.col.f32.f16.f16.f32 "
        "{%0,%1,%2,%3}, {%4,%5,%6,%7}, {%8,%9}, {%0,%1,%2,%3};"
        : "+f"(c[0]), "+f"(c[1]), "+f"(c[2]), "+f"(c[3])
        : "r"(a[0]), "r"(a[1]), "r"(a[2]), "r"(a[3]), "r"(b0), "r"(b1));
}
__device__ __forceinline__ void ldsm4(unsigned* r, const __half* p) {
    uint32_t a = (uint32_t)__cvta_generic_to_shared(p);
    asm volatile("ldmatrix.sync.aligned.m8n8.x4.shared.b16 {%0,%1,%2,%3}, [%4];"
                 : "=r"(r[0]), "=r"(r[1]), "=r"(r[2]), "=r"(r[3]) : "r"(a));
}
__device__ __forceinline__ void ldsm2(unsigned* r, const __half* p) {
    uint32_t a = (uint32_t)__cvta_generic_to_shared(p);
    asm volatile("ldmatrix.sync.aligned.m8n8.x2.shared.b16 {%0,%1}, [%2];"
                 : "=r"(r[0]), "=r"(r[1]) : "r"(a));
}

// ======================= prep kernels (split for ncu launch indexing) ===========
__global__ void k_prepw1(const float* __restrict__ qw, const float* __restrict__ kvw) {
    int i = blockIdx.x * 256 + threadIdx.x;
    if (i < 36864)        w_qh [i]         = __float2half_rn(qw[i] * QSCALE);
    else if (i < 110592)  w_kvh[i - 36864] = __float2half_rn(kvw[i - 36864]);
}
__global__ void k_prepw2(const float* __restrict__ f1w, const float* __restrict__ f2w) {
    int i = blockIdx.x * 256 + threadIdx.x;
    if (i < 147456)       w_f1h[i]          = __float2half_rn(f1w[i]);
    else if (i < 294912)  w_f2h[i - 147456] = __float2half_rn(f2w[i - 147456]);
}
__global__ void k_wcomb(const float* __restrict__ mw, const float* __restrict__ pw) {
    int e = blockIdx.x * 256 + threadIdx.x;
    if (e < 36864) {
        int i = e / 192, j = e - (e / 192) * 192;
        float acc = 0.f;
        for (int k = 0; k < 192; k++) acc += mw[i * 192 + k] * pw[k * 192 + j];
        w_ch[e] = __float2half_rn(acc);
    }
}
__global__ void k_bc(const float* __restrict__ mw, const float* __restrict__ pb) {
    int e = threadIdx.x;
    if (e < 192) {
        float acc = 0.f;
        for (int k = 0; k < 192; k++) acc += mw[e * 192 + k] * pb[k];
        g_bc[e] = acc;
    }
}
__global__ void k_bias(const int* __restrict__ relidx, const float* __restrict__ table) {
    int idx = blockIdx.x * 256 + threadIdx.x;
    if (idx < NHd * 4096) {
        int h = idx >> 12, r = idx & 4095;
        g_biash[idx] = __float2half_rn(table[relidx[r] * NHd + h]);
    }
}

// ======================= MEGA kernel =======================
// smem halves (52224 total = 104448 B):
//   phase A: smA [0,15360) | Kh [15360,30720) | Vt [30720,44544) | smB [44544,52224)
//   phase B (proj GEMM): Wc dbuf overlays Kh; St fp32 overlays halves [15360,40960)
//   phase C (MLP): smA = x1h | B1 dbuf [15360,23040) | H [23040,30720) | B2 dbuf [30720,46080)
__global__ void __launch_bounds__(256, 2) k_mega(
    const float* __restrict__ x, const float* __restrict__ feat,
    const float* __restrict__ q_b, const float* __restrict__ kv_b,
    const float* __restrict__ n1g, const float* __restrict__ n1b,
    const float* __restrict__ b1h, const float* __restrict__ b2,
    const float* __restrict__ g2, const float* __restrict__ bb2,
    float* __restrict__ out)
{
    extern __shared__ float smf[];
    __half* smA = (__half*)smf;
    __half* Kh  = smA + 15360;
    __half* Vt  = smA + 30720;
    __half* smB = smA + 44544;
    __half* smB2 = Kh;
    float*  St  = smf + 7680;
    __half* smB1m = smA + 15360;
    __half* smHm  = smA + 23040;
    __half* smB2m = smA + 30720;
    int win = blockIdx.x;
    int tid = threadIdx.x;
    int lane = tid & 31, w = tid >> 5;
    int g = lane >> 2, tg = lane & 3;
    int mi = w & 3, hp = w >> 2;
    const int r0 = tid >> 3, c4 = 4 * (tid & 7);
    const int stsO = r0 * 40 + c4;
    const int wr = (w & 1) * 32, wc = (w >> 1) * 48;
    const int wc1 = (w >> 1) * 24;

    // ldmatrix per-lane offsets (halves)
    const int aoff  = (lane & 15) * 40 + (lane >> 4) * 8;
    const int boff  = ((lane & 7) + ((lane >> 4) & 1) * 8) * 40 + ((lane >> 3) & 1) * 8;
    const int b2off = (lane & 7) * 40 + ((lane >> 3) & 1) * 8;
    const int voff  = ((lane & 7) + ((lane >> 4) & 1) * 8) * 72 + ((lane >> 3) & 1) * 8;

    int bI = win >> 10, wh = (win >> 5) & 31, ww = win & 31;

    // gather geometry: thread (cl, hr) covers channel cl+32u, tokens hr*8..hr*8+7
    const int cl = tid & 31, hr = tid >> 5;
    const int hpix = (wh * 8 + hr + 4) & 255;
    const int wp0  = ww * 8 + 4;           // <= 252, no wrap within float4
    const int wp4  = (ww * 8 + 8) & 255;   // wraps to 0 only at ww=31 (4-aligned)
    const float* xb = x    + (size_t)bI * Cd * HWd + (size_t)hpix * Wdim;
    const float* fb = feat + (size_t)bI * Cd * HWd + (size_t)hpix * Wdim;

    // ---------- gather xw -> smA (fp16, A-layout); stage Wq chunk 0 ----------
#pragma unroll
    for (int u = 0; u < 6; u++) {
        const float* p = xb + (size_t)(u * 32 + cl) * HWd;
        float4 v0 = *(const float4*)(p + wp0);
        float4 v1 = *(const float4*)(p + wp4);
        __half* d = smA + u * 2560 + (hr * 8) * 40 + cl;
        d[0]   = __float2half_rn(v0.x);  d[40]  = __float2half_rn(v0.y);
        d[80]  = __float2half_rn(v0.z);  d[120] = __float2half_rn(v0.w);
        d[160] = __float2half_rn(v1.x);  d[200] = __float2half_rn(v1.y);
        d[240] = __float2half_rn(v1.z);  d[280] = __float2half_rn(v1.w);
    }
    uint2 rb[6];
#pragma unroll
    for (int i = 0; i < 6; i++)
        rb[i] = *(const uint2*)(w_qh + (size_t)(r0 + 32 * i) * 192 + c4);
#pragma unroll
    for (int i = 0; i < 6; i++) *(uint2*)(smB + stsO + 1280 * i) = rb[i];
    __syncthreads();

    // ---------- Q GEMM: rows 16mi..+16, heads {hp,2+hp,4+hp} ----------
    float qacc[3][4][4];
#pragma unroll
    for (int t = 0; t < 3; t++)
#pragma unroll
        for (int nq = 0; nq < 4; nq++)
#pragma unroll
            for (int e = 0; e < 4; e++) qacc[t][nq][e] = 0.f;
#pragma unroll 1
    for (int kc = 0; kc < 6; kc++) {
        if (kc + 1 < 6)
#pragma unroll
            for (int i = 0; i < 6; i++)
                rb[i] = *(const uint2*)(w_qh + (size_t)(r0 + 32 * i) * 192 + (kc + 1) * 32 + c4);
#pragma unroll
        for (int kk = 0; kk < 32; kk += 16) {
            unsigned af[4];
            ldsm4(af, smA + kc * 2560 + 16 * mi * 40 + kk + aoff);
#pragma unroll
            for (int t = 0; t < 3; t++) {
                unsigned bq0[4], bq1[4];
                ldsm4(bq0, smB + (32 * (2 * t + hp)) * 40 + kk + boff);
                ldsm4(bq1, smB + (32 * (2 * t + hp) + 16) * 40 + kk + boff);
                mma16(qacc[t][0], af, bq0[0], bq0[1]);
                mma16(qacc[t][1], af, bq0[2], bq0[3]);
                mma16(qacc[t][2], af, bq1[0], bq1[1]);
                mma16(qacc[t][3], af, bq1[2], bq1[3]);
            }
        }
        __syncthreads();
        if (kc + 1 < 6) {
#pragma unroll
            for (int i = 0; i < 6; i++)
                *(uint2*)(smB + stsO + 1280 * i) = rb[i];
            __syncthreads();
        }
    }

    // ---------- repack Q: C-frag -> A-frag, + scaled bias ----------
    unsigned aq[3][2][4];
#pragma unroll
    for (int t = 0; t < 3; t++) {
        int h = 2 * t + hp;
#pragma unroll
        for (int ks = 0; ks < 2; ks++) {
            float2 b0 = *(const float2*)(q_b + 32 * h + 16 * ks + 2 * tg);
            float2 b1 = *(const float2*)(q_b + 32 * h + 16 * ks + 8 + 2 * tg);
            b0.x *= QSCALE; b0.y *= QSCALE; b1.x *= QSCALE; b1.y *= QSCALE;
            aq[t][ks][0] = h2u(__floats2half2_rn(qacc[t][2*ks][0] + b0.x, qacc[t][2*ks][1] + b0.y));
            aq[t][ks][1] = h2u(__floats2half2_rn(qacc[t][2*ks][2] + b0.x, qacc[t][2*ks][3] + b0.y));
            aq[t][ks][2] = h2u(__floats2half2_rn(qacc[t][2*ks+1][0] + b1.x, qacc[t][2*ks+1][1] + b1.y));
            aq[t][ks][3] = h2u(__floats2half2_rn(qacc[t][2*ks+1][2] + b1.x, qacc[t][2*ks+1][3] + b1.y));
        }
    }

    // ---------- gather fw (overwrite smA); stage Wk chunk 0 ----------
#pragma unroll
    for (int u = 0; u < 6; u++) {
        const float* p = fb + (size_t)(u * 32 + cl) * HWd;
        float4 v0 = *(const float4*)(p + wp0);
        float4 v1 = *(const float4*)(p + wp4);
        __half* d = smA + u * 2560 + (hr * 8) * 40 + cl;
        d[0]   = __float2half_rn(v0.x);  d[40]  = __float2half_rn(v0.y);
        d[80]  = __float2half_rn(v0.z);  d[120] = __float2half_rn(v0.w);
        d[160] = __float2half_rn(v1.x);  d[200] = __float2half_rn(v1.y);
        d[240] = __float2half_rn(v1.z);  d[280] = __float2half_rn(v1.w);
    }
#pragma unroll
    for (int i = 0; i < 6; i++)
        rb[i] = *(const uint2*)(w_kvh + (size_t)(r0 + 32 * i) * 192 + c4);
#pragma unroll
    for (int i = 0; i < 6; i++) *(uint2*)(smB + stsO + 1280 * i) = rb[i];
    __syncthreads();

    // ---------- K GEMM -> Kh, then V GEMM -> Vt ----------
#pragma unroll 1
    for (int kv = 0; kv < 2; kv++) {
        const __half* W = w_kvh + (size_t)kv * 36864;
        float acc[2][6][4];
#pragma unroll
        for (int a = 0; a < 2; a++)
#pragma unroll
            for (int b_ = 0; b_ < 6; b_++)
#pragma unroll
                for (int e = 0; e < 4; e++) acc[a][b_][e] = 0.f;
#pragma unroll 1
        for (int kc = 0; kc < 6; kc++) {
            if (kc + 1 < 6) {
#pragma unroll
                for (int i = 0; i < 6; i++)
                    rb[i] = *(const uint2*)(W + (size_t)(r0 + 32 * i) * 192 + (kc + 1) * 32 + c4);
            } else if (kv == 0) {
#pragma unroll
                for (int i = 0; i < 6; i++)
                    rb[i] = *(const uint2*)(w_kvh + 36864 + (size_t)(r0 + 32 * i) * 192 + c4);
            }
#pragma unroll
            for (int kk = 0; kk < 32; kk += 16) {
                unsigned af[2][4], bb[3][4];
                ldsm4(af[0], smA + kc * 2560 + wr * 40 + kk + aoff);
                ldsm4(af[1], smA + kc * 2560 + (wr + 16) * 40 + kk + aoff);
#pragma unroll
                for (int p = 0; p < 3; p++)
                    ldsm4(bb[p], smB + (wc + 16 * p) * 40 + kk + boff);
#pragma unroll
                for (int m2 = 0; m2 < 2; m2++)
#pragma unroll
                    for (int ni = 0; ni < 6; ni++)
                        mma16(acc[m2][ni], af[m2], bb[ni >> 1][(ni & 1) * 2], bb[ni >> 1][(ni & 1) * 2 + 1]);
            }
            __syncthreads();
            if (kc + 1 < 6 || kv == 0) {
#pragma unroll
                for (int i = 0; i < 6; i++)
                    *(uint2*)(smB + stsO + 1280 * i) = rb[i];
                __syncthreads();
            }
        }
#pragma unroll
        for (int m2 = 0; m2 < 2; m2++)
#pragma unroll
            for (int ni = 0; ni < 6; ni++) {
                int c = wc + 8 * ni + 2 * tg;
                int h = c >> 5, d = c & 31;
                float2 bv = *(const float2*)(kv_b + kv * 192 + c);
                int row = wr + 16 * m2 + g;
                if (kv == 0) {
                    *(__half2*)(Kh + h * 2560 + row * 40 + d) =
                        __floats2half2_rn(acc[m2][ni][0] + bv.x, acc[m2][ni][1] + bv.y);
                    *(__half2*)(Kh + h * 2560 + (row + 8) * 40 + d) =
                        __floats2half2_rn(acc[m2][ni][2] + bv.x, acc[m2][ni][3] + bv.y);
                } else {
                    __half* vb = Vt + h * 2304 + d * 72;
                    vb[row]          = __float2half_rn(acc[m2][ni][0] + bv.x);
                    vb[72 + row]     = __float2half_rn(acc[m2][ni][1] + bv.y);
                    vb[row + 8]      = __float2half_rn(acc[m2][ni][2] + bv.x);
                    vb[72 + row + 8] = __float2half_rn(acc[m2][ni][3] + bv.y);
                }
            }
    }
    __syncthreads();

    // ---------- attention ----------
    int i0 = 16 * mi + g;
    int w10 = win & 1023;
    bool eh = ((w10 >> 5) == 31), ew = ((w10 & 31) == 31);
    bool edge = eh || ew;
    int ri0 = 0, ri1 = 0, rj0a[8], rj1a[8];
    if (edge) {
        auto region = [&](int n) {
            int a = eh ? (((n >> 3) >= 4) ? 2 : 1) : 0;
            int b = ew ? (((n & 7)  >= 4) ? 2 : 1) : 0;
            return a * 3 + b;
        };
        ri0 = region(i0); ri1 = region(i0 + 8);
#pragma unroll
        for (int ni = 0; ni < 8; ni++) {
            int j0 = 8 * ni + 2 * tg;
            rj0a[ni] = region(j0);
            rj1a[ni] = region(j0 + 1);
        }
    }

#pragma unroll 1
    for (int t = 0; t < 3; t++) {
        int h = 2 * t + hp;
        float s[8][4];
#pragma unroll
        for (int ni = 0; ni < 8; ni++)
#pragma unroll
            for (int e = 0; e < 4; e++) s[ni][e] = 0.f;
        const __half* Khh = Kh + h * 2560;
#pragma unroll
        for (int p = 0; p < 4; p++) {
            unsigned kb0[4], kb1[4];
            ldsm4(kb0, Khh + (16 * p) * 40 + boff);
            ldsm4(kb1, Khh + (16 * p) * 40 + 16 + boff);
            mma16(s[2*p],     aq[t][0], kb0[0], kb0[1]);
            mma16(s[2*p],     aq[t][1], kb1[0], kb1[1]);
            mma16(s[2*p + 1], aq[t][0], kb0[2], kb0[3]);
            mma16(s[2*p + 1], aq[t][1], kb1[2], kb1[3]);
        }
        const __half* bb0 = g_biash + (h * 64 + i0) * 64;
#pragma unroll
        for (int ni = 0; ni < 8; ni++) {
            int j0 = 8 * ni + 2 * tg;
            float2 f0 = __half22float2(*(const __half2*)(bb0 + j0));
            float2 f1 = __half22float2(*(const __half2*)(bb0 + 512 + j0));
            s[ni][0] += f0.x; s[ni][1] += f0.y;
            s[ni][2] += f1.x; s[ni][3] += f1.y;
        }
        if (edge) {
#pragma unroll
            for (int ni = 0; ni < 8; ni++) {
                if (rj0a[ni] != ri0) s[ni][0] -= 100.f;
                if (rj1a[ni] != ri0) s[ni][1] -= 100.f;
                if (rj0a[ni] != ri1) s[ni][2] -= 100.f;
                if (rj1a[ni] != ri1) s[ni][3] -= 100.f;
            }
        }
        float m0 = -1e30f, m1 = -1e30f;
#pragma unroll
        for (int ni = 0; ni < 8; ni++) {
            m0 = fmaxf(m0, fmaxf(s[ni][0], s[ni][1]));
            m1 = fmaxf(m1, fmaxf(s[ni][2], s[ni][3]));
        }
        m0 = fmaxf(m0, __shfl_xor_sync(0xffffffffu, m0, 1));
        m0 = fmaxf(m0, __shfl_xor_sync(0xffffffffu, m0, 2));
        m1 = fmaxf(m1, __shfl_xor_sync(0xffffffffu, m1, 1));
        m1 = fmaxf(m1, __shfl_xor_sync(0xffffffffu, m1, 2));
        float s0 = 0.f, s1 = 0.f;
#pragma unroll
        for (int ni = 0; ni < 8; ni++) {
            s[ni][0] = __expf(s[ni][0] - m0); s0 += s[ni][0];
            s[ni][1] = __expf(s[ni][1] - m0); s0 += s[ni][1];
            s[ni][2] = __expf(s[ni][2] - m1); s1 += s[ni][2];
            s[ni][3] = __expf(s[ni][3] - m1); s1 += s[ni][3];
        }
        s0 += __shfl_xor_sync(0xffffffffu, s0, 1);
        s0 += __shfl_xor_sync(0xffffffffu, s0, 2);
        s1 += __shfl_xor_sync(0xffffffffu, s1, 1);
        s1 += __shfl_xor_sync(0xffffffffu, s1, 2);
        float inv0 = 1.f / s0, inv1 = 1.f / s1;
        unsigned pv[4][4];
#pragma unroll
        for (int js = 0; js < 4; js++) {
            pv[js][0] = h2u(__floats2half2_rn(s[2*js][0]   * inv0, s[2*js][1]   * inv0));
            pv[js][1] = h2u(__floats2half2_rn(s[2*js][2]   * inv1, s[2*js][3]   * inv1));
            pv[js][2] = h2u(__floats2half2_rn(s[2*js+1][0] * inv0, s[2*js+1][1] * inv0));
            pv[js][3] = h2u(__floats2half2_rn(s[2*js+1][2] * inv1, s[2*js+1][3] * inv1));
        }
        float o[4][4];
#pragma unroll
        for (int nd = 0; nd < 4; nd++)
#pragma unroll
            for (int e = 0; e < 4; e++) o[nd][e] = 0.f;
        const __half* Vth = Vt + h * 2304;
#pragma unroll
        for (int p = 0; p < 2; p++)
#pragma unroll
            for (int js = 0; js < 4; js++) {
                unsigned vb[4];
                ldsm4(vb, Vth + (16 * p) * 72 + 16 * js + voff);
                mma16(o[2*p],     pv[js], vb[0], vb[1]);
                mma16(o[2*p + 1], pv[js], vb[2], vb[3]);
            }
#pragma unroll
        for (int nd = 0; nd < 4; nd++) {
            int d0 = 8 * nd + 2 * tg;
            *(__half2*)(smA + h * 2560 + i0 * 40 + d0) =
                __floats2half2_rn(o[nd][0], o[nd][1]);
            *(__half2*)(smA + h * 2560 + (i0 + 8) * 40 + d0) =
                __floats2half2_rn(o[nd][2], o[nd][3]);
        }
    }

    // ---------- fused proj+merge GEMM: 64x192 = smA @ Wc^T ----------
#pragma unroll
    for (int i = 0; i < 6; i++)
        rb[i] = *(const uint2*)(w_ch + (size_t)(r0 + 32 * i) * 192 + c4);
    __syncthreads();
#pragma unroll
    for (int i = 0; i < 6; i++)
        *(uint2*)(smB2 + stsO + 1280 * i) = rb[i];
    __syncthreads();

    {
        float acc[2][6][4];
#pragma unroll
        for (int a = 0; a < 2; a++)
#pragma unroll
            for (int b_ = 0; b_ < 6; b_++)
#pragma unroll
                for (int e = 0; e < 4; e++) acc[a][b_][e] = 0.f;

#pragma unroll 1
        for (int kc = 0; kc < 6; kc++) {
            if (kc + 1 < 6)
#pragma unroll
                for (int i = 0; i < 6; i++)
                    rb[i] = *(const uint2*)(w_ch + (size_t)(r0 + 32 * i) * 192 + (kc + 1) * 32 + c4);
            const __half* Ab = smA + kc * 2560;
            const __half* Bb = smB2 + (kc & 1) * 7680;
#pragma unroll
            for (int kk = 0; kk < 32; kk += 16) {
                unsigned af[2][4], bb[3][4];
                ldsm4(af[0], Ab + wr * 40 + kk + aoff);
                ldsm4(af[1], Ab + (wr + 16) * 40 + kk + aoff);
#pragma unroll
                for (int p = 0; p < 3; p++)
                    ldsm4(bb[p], Bb + (wc + 16 * p) * 40 + kk + boff);
#pragma unroll
                for (int m2 = 0; m2 < 2; m2++)
#pragma unroll
                    for (int ni = 0; ni < 6; ni++)
                        mma16(acc[m2][ni], af[m2], bb[ni >> 1][(ni & 1) * 2], bb[ni >> 1][(ni & 1) * 2 + 1]);
            }
            if (kc + 1 < 6)
#pragma unroll
                for (int i = 0; i < 6; i++)
                    *(uint2*)(smB2 + ((kc + 1) & 1) * 7680 + stsO + 1280 * i) = rb[i];
            __syncthreads();
        }

#pragma unroll
        for (int m2 = 0; m2 < 2; m2++)
#pragma unroll
            for (int ni = 0; ni < 6; ni++) {
                int row = wr + 16 * m2 + g;
                int col = wc + 8 * ni + 2 * tg;
                St[row * 200 + col]           = acc[m2][ni][0];
                St[row * 200 + col + 1]       = acc[m2][ni][1];
                St[(row + 8) * 200 + col]     = acc[m2][ni][2];
                St[(row + 8) * 200 + col + 1] = acc[m2][ni][3];
            }
    }
    __syncthreads();

    // ---------- LN1 + shortcut (re-gather x, fp32) -> x1h into smA ----------
    int wp = tid >> 5, l = tid & 31;
    float4 xs0[6], xs1[6];
#pragma unroll
    for (int u = 0; u < 6; u++) {
        const float* p = xb + (size_t)(u * 32 + l) * HWd;   // hr == wp, cl == l
        xs0[u] = *(const float4*)(p + wp0);
        xs1[u] = *(const float4*)(p + wp4);
    }
#pragma unroll
    for (int rr = 0; rr < 8; rr++) {
        int n = wp * 8 + rr;
        float vv[6]; float su = 0.f;
#pragma unroll
        for (int u = 0; u < 6; u++) {
            int c = l + 32 * u;
            vv[u] = St[n * 200 + c] + g_bc[c];
            su += vv[u];
        }
        su = warp_sum(su);
        float mean = su * (1.f / 192.f);
        float sq = 0.f;
#pragma unroll
        for (int u = 0; u < 6; u++) { float d = vv[u] - mean; sq += d * d; }
        sq = warp_sum(sq);
        float rstd = rsqrtf(sq * (1.f / 192.f) + 1e-5f);
#pragma unroll
        for (int u = 0; u < 6; u++) {
            float xv;
            if (rr == 0) xv = xs0[u].x; else if (rr == 1) xv = xs0[u].y;
            else if (rr == 2) xv = xs0[u].z; else if (rr == 3) xv = xs0[u].w;
            else if (rr == 4) xv = xs1[u].x; else if (rr == 5) xv = xs1[u].y;
            else if (rr == 6) xv = xs1[u].z; else xv = xs1[u].w;
            int c = l + 32 * u;
            float y = (vv[u] - mean) * rstd * n1g[c] + n1b[c] + xv;
            smA[u * 2560 + n * 40 + l] = __float2half_rn(y);
        }
    }
    __syncthreads();

    // ---------- MLP: fc1 + GELU + fc2 (A = x1h in smA) ----------
    float acc2[2][6][4];
#pragma unroll
    for (int a = 0; a < 2; a++)
#pragma unroll
        for (int b_ = 0; b_ < 6; b_++)
#pragma unroll
            for (int cc = 0; cc < 4; cc++) acc2[a][b_][cc] = 0.f;

#pragma unroll 1
    for (int oc = 0; oc < 8; oc++) {
        const __half* W1 = w_f1h + (size_t)(oc * 96) * 192;
        uint2 rb1[3];
#pragma unroll
        for (int i = 0; i < 3; i++)
            rb1[i] = *(const uint2*)(W1 + (size_t)(r0 + 32 * i) * 192 + c4);
#pragma unroll
        for (int i = 0; i < 3; i++)
            *(uint2*)(smB1m + stsO + 1280 * i) = rb1[i];
        __syncthreads();

        float acc1[2][3][4];
#pragma unroll
        for (int a = 0; a < 2; a++)
#pragma unroll
            for (int b_ = 0; b_ < 3; b_++)
#pragma unroll
                for (int cc = 0; cc < 4; cc++) acc1[a][b_][cc] = 0.f;

#pragma unroll 1
        for (int kc = 0; kc < 6; kc++) {
            if (kc + 1 < 6)
#pragma unroll
                for (int i = 0; i < 3; i++)
                    rb1[i] = *(const uint2*)(W1 + (size_t)(r0 + 32 * i) * 192 + (kc + 1) * 32 + c4);
            const __half* Ab = smA + kc * 2560;
            const __half* Bb = smB1m + (kc & 1) * 3840;
#pragma unroll
            for (int kk = 0; kk < 32; kk += 16) {
                unsigned af[2][4], b1r[4], b1s[2];
                ldsm4(af[0], Ab + wr * 40 + kk + aoff);
                ldsm4(af[1], Ab + (wr + 16) * 40 + kk + aoff);
                ldsm4(b1r, Bb + wc1 * 40 + kk + boff);
                ldsm2(b1s, Bb + (wc1 + 16) * 40 + kk + b2off);
#pragma unroll
                for (int m2 = 0; m2 < 2; m2++) {
                    mma16(acc1[m2][0], af[m2], b1r[0], b1r[1]);
                    mma16(acc1[m2][1], af[m2], b1r[2], b1r[3]);
                    mma16(acc1[m2][2], af[m2], b1s[0], b1s[1]);
                }
            }
            if (kc + 1 < 6)
#pragma unroll
                for (int i = 0; i < 3; i++)
                    *(uint2*)(smB1m + ((kc + 1) & 1) * 3840 + stsO + 1280 * i) = rb1[i];
            __syncthreads();
        }

#pragma unroll
        for (int m2 = 0; m2 < 2; m2++)
#pragma unroll
            for (int ni = 0; ni < 3; ni++) {
                int row = wr + 16 * m2 + g;
                int col = wc1 + 8 * ni + 2 * tg;
                float2 bv = *(const float2*)(b1h + oc * 96 + col);
                __half* hp0 = smHm + (col >> 5) * 2560 + row * 40 + (col & 31);
                *(__half2*)hp0 = __floats2half2_rn(
                    gelu_f(acc1[m2][ni][0] + bv.x), gelu_f(acc1[m2][ni][1] + bv.y));
                *(__half2*)(hp0 + 320) = __floats2half2_rn(
                    gelu_f(acc1[m2][ni][2] + bv.x), gelu_f(acc1[m2][ni][3] + bv.y));
            }

        const __half* W2 = w_f2h;
        uint2 rb2[6];
#pragma unroll
        for (int i = 0; i < 6; i++)
            rb2[i] = *(const uint2*)(W2 + (size_t)(r0 + 32 * i) * 768 + oc * 96 + c4);
#pragma unroll
        for (int i = 0; i < 6; i++)
            *(uint2*)(smB2m + stsO + 1280 * i) = rb2[i];
        __syncthreads();

#pragma unroll 1
        for (int kc = 0; kc < 3; kc++) {
            if (kc + 1 < 3)
#pragma unroll
                for (int i = 0; i < 6; i++)
                    rb2[i] = *(const uint2*)(W2 + (size_t)(r0 + 32 * i) * 768 + oc * 96 + (kc + 1) * 32 + c4);
            const __half* Ab = smHm + kc * 2560;
            const __half* Bb = smB2m + (kc & 1) * 7680;
#pragma unroll
            for (int kk = 0; kk < 32; kk += 16) {
                unsigned af[2][4], bb[3][4];
                ldsm4(af[0], Ab + wr * 40 + kk + aoff);
                ldsm4(af[1], Ab + (wr + 16) * 40 + kk + aoff);
#pragma unroll
                for (int p = 0; p < 3; p++)
                    ldsm4(bb[p], Bb + (wc + 16 * p) * 40 + kk + boff);
#pragma unroll
                for (int m2 = 0; m2 < 2; m2++)
#pragma unroll
                    for (int ni = 0; ni < 6; ni++)
                        mma16(acc2[m2][ni], af[m2], bb[ni >> 1][(ni & 1) * 2], bb[ni >> 1][(ni & 1) * 2 + 1]);
            }
            if (kc + 1 < 3)
#pragma unroll
                for (int i = 0; i < 6; i++)
                    *(uint2*)(smB2m + ((kc + 1) & 1) * 7680 + stsO + 1280 * i) = rb2[i];
            __syncthreads();
        }
    }

    // ---------- final: bias + LN2 + residual(x1h) + pixel scatter ----------
#pragma unroll
    for (int m2 = 0; m2 < 2; m2++)
#pragma unroll
        for (int ni = 0; ni < 6; ni++) {
            int row = wr + 16 * m2 + g;
            int col = wc + 8 * ni + 2 * tg;
            St[row * 200 + col]           = acc2[m2][ni][0];
            St[row * 200 + col + 1]       = acc2[m2][ni][1];
            St[(row + 8) * 200 + col]     = acc2[m2][ni][2];
            St[(row + 8) * 200 + col + 1] = acc2[m2][ni][3];
        }
    __syncthreads();
#pragma unroll 1
    for (int rr = 0; rr < 8; rr++) {
        int n = wp * 8 + rr;
        int hpx = (wh * 8 + (n >> 3) + 4) & 255;
        int wpx = (ww * 8 + (n & 7) + 4) & 255;
        size_t row = ((size_t)bI * HWd + hpx * Wdim + wpx) * Cd;
        float vv[6]; float su = 0.f;
#pragma unroll
        for (int u = 0; u < 6; u++) {
            int c = l + 32 * u;
            vv[u] = St[n * 200 + c] + b2[c];
            su += vv[u];
        }
        su = warp_sum(su);
        float mean = su * (1.f / 192.f);
        float sq = 0.f;
#pragma unroll
        for (int u = 0; u < 6; u++) { float d = vv[u] - mean; sq += d * d; }
        sq = warp_sum(sq);
        float rstd = rsqrtf(sq * (1.f / 192.f) + 1e-5f);
#pragma unroll
        for (int u = 0; u < 6; u++) {
            int c = l + 32 * u;
            float x1v = __half2float(smA[u * 2560 + n * 40 + l]);
            out[row + c] = x1v + (vv[u] - mean) * rstd * g2[c] + bb2[c];
        }
    }
}

// ======================= host =======================
extern "C" void kernel_launch(void* const* d_in, const int* in_sizes, int n_in,
                              void* d_out, int out_size)
{
    const float* x    = (const float*)d_in[0];
    const float* feat = (const float*)d_in[1];
    const int*   ridx = (const int*)  d_in[3];
    const float* rtab = (const float*)d_in[4];
    const float* q_w  = (const float*)d_in[5];
    const float* q_b  = (const float*)d_in[6];
    const float* kv_w = (const float*)d_in[7];
    const float* kv_b = (const float*)d_in[8];
    const float* p_w  = (const float*)d_in[9];
    const float* p_b  = (const float*)d_in[10];
    const float* m_w  = (const float*)d_in[11];
    const float* n1g  = (const float*)d_in[12];
    const float* n1b  = (const float*)d_in[13];
    const float* n2g  = (const float*)d_in[14];
    const float* n2b  = (const float*)d_in[15];
    const float* f1w  = (const float*)d_in[16];
    const float* f1b  = (const float*)d_in[17];
    const float* f2w  = (const float*)d_in[18];
    const float* f2b  = (const float*)d_in[19];
    float* out = (float*)d_out;

    const int smMega = 52224 * 2;                        // 104448
    cudaFuncSetAttribute(k_mega, cudaFuncAttributeMaxDynamicSharedMemorySize, smMega);

    k_prepw1<<<432, 256>>>(q_w, kv_w);                                // 0
    k_prepw2<<<1152, 256>>>(f1w, f2w);                                // 1
    k_wcomb <<<144, 256>>>(m_w, p_w);                                 // 2
    k_bc    <<<1, 192>>>(m_w, p_b);                                   // 3
    k_bias  <<<96, 256>>>(ridx, rtab);                                // 4
    k_mega  <<<NWINd, 256, smMega>>>(x, feat, q_b, kv_b, n1g, n1b,
                                     f1b, f2b, n2g, n2b, out);        // 5
}

// round 13
// speedup vs baseline: 1.0406x; 1.0406x over previous
#include <cuda_runtime.h>
#include <cuda_fp16.h>
#include <math.h>
#include <stdint.h>

#define Hd    256
#define Wdim  256
#define HWd   65536
#define Cd    192
#define Bd    4
#define NHd   6
#define HDd   32
#define NWINd 4096
#define MTOKd 262144
#define HIDd  768
#define QSCALE 0.17677669529663687f

// -------- scratch --------
__device__ __half g_xth [(size_t)MTOKd * Cd];           // fp16 WINDOW-order (also shortcut)
__device__ __half g_fth [(size_t)MTOKd * Cd];           // fp16 WINDOW-order
__device__ __half g_biash[NHd * 64 * 64];
__device__ __half w_qh [36864];
__device__ __half w_kvh[73728];
__device__ __half w_ch [36864];
__device__ float  g_bc [192];
__device__ __half w_f1h[147456];
__device__ __half w_f2h[147456];

__device__ __forceinline__ float warp_sum(float v) {
#pragma unroll
    for (int o = 16; o; o >>= 1) v += __shfl_xor_sync(0xffffffffu, v, o);
    return v;
}
__device__ __forceinline__ unsigned h2u(__half2 h) {
    return *reinterpret_cast<unsigned*>(&h);
}
__device__ __forceinline__ float gelu_f(float v) {
    return 0.5f * v * (1.f + erff(v * 0.70710678118654752f));
}
__device__ __forceinline__ void mma16(float* c, const unsigned* a, unsigned b0, unsigned b1) {
    asm volatile(
        "mma.sync.aligned.m16n8k16.row.col.f32.f16.f16.f32 "
        "{%0,%1,%2,%3}, {%4,%5,%6,%7}, {%8,%9}, {%0,%1,%2,%3};"
        : "+f"(c[0]), "+f"(c[1]), "+f"(c[2]), "+f"(c[3])
        : "r"(a[0]), "r"(a[1]), "r"(a[2]), "r"(a[3]), "r"(b0), "r"(b1));
}
__device__ __forceinline__ void ldsm4(unsigned* r, const __half* p) {
    uint32_t a = (uint32_t)__cvta_generic_to_shared(p);
    asm volatile("ldmatrix.sync.aligned.m8n8.x4.shared.b16 {%0,%1,%2,%3}, [%4];"
                 : "=r"(r[0]), "=r"(r[1]), "=r"(r[2]), "=r"(r[3]) : "r"(a));
}
__device__ __forceinline__ void ldsm2(unsigned* r, const __half* p) {
    uint32_t a = (uint32_t)__cvta_generic_to_shared(p);
    asm volatile("ldmatrix.sync.aligned.m8n8.x2.shared.b16 {%0,%1}, [%2];"
                 : "=r"(r[0]), "=r"(r[1]) : "r"(a));
}

// ======================= prep kernels =======================
__global__ void k_prepw(const float* __restrict__ qw, const float* __restrict__ kvw,
                        const float* __restrict__ f1w, const float* __restrict__ f2w) {
    int i = blockIdx.x * 256 + threadIdx.x;
    if (i < 36864)        w_qh [i]          = __float2half_rn(qw[i] * QSCALE);
    else if (i < 110592)  w_kvh[i - 36864]  = __float2half_rn(kvw[i - 36864]);
    else if (i < 258048)  w_f1h[i - 110592] = __float2half_rn(f1w[i - 110592]);
    else if (i < 405504)  w_f2h[i - 258048] = __float2half_rn(f2w[i - 258048]);
}
__global__ void k_wcomb(const float* __restrict__ mw, const float* __restrict__ pw,
                        const float* __restrict__ pb) {
    int e = blockIdx.x * 256 + threadIdx.x;
    if (e < 36864) {
        int i = e / 192, j = e - (e / 192) * 192;
        float acc = 0.f;
        for (int k = 0; k < 192; k++) acc += mw[i * 192 + k] * pw[k * 192 + j];
        w_ch[e] = __float2half_rn(acc);
    }
    if (e < 192) {
        float acc = 0.f;
        for (int k = 0; k < 192; k++) acc += mw[e * 192 + k] * pb[k];
        g_bc[e] = acc;
    }
}
__global__ void k_bias(const int* __restrict__ relidx, const float* __restrict__ table) {
    int idx = blockIdx.x * 256 + threadIdx.x;
    if (idx < NHd * 4096) {
        int h = idx >> 12, r = idx & 4095;
        g_biash[idx] = __float2half_rn(table[relidx[r] * NHd + h]);
    }
}

// ======================= K0: transpose one tensor -> fp16 WINDOW order ==========
__global__ void k_transpose(const float* __restrict__ src0, __half* __restrict__ dst0) {
    __shared__ float t[32][33];
    int b  = blockIdx.z;
    int c0 = blockIdx.x << 5;
    int p0 = blockIdx.y << 5;
    const float* src = src0 + (size_t)b * Cd * HWd;
    int tx = threadIdx.x, ty = threadIdx.y;
#pragma unroll
    for (int i = ty; i < 32; i += 8)
        t[i][tx] = src[(size_t)(c0 + i) * HWd + p0 + tx];
    __syncthreads();
    int h  = p0 >> 8;
    int h2 = (h - 4) & 255;
    int whp = ((h2 >> 3) << 5);
    int nh8 = (h2 & 7) << 3;
    __half* dh = dst0 + (size_t)b * HWd * Cd;
#pragma unroll
    for (int i = ty; i < 32; i += 8) {
        int wv = ((p0 & 255) + i);
        int w2 = (wv - 4) & 255;
        int tok = ((whp + (w2 >> 3)) << 6) + nh8 + (w2 & 7);
        dh[(size_t)tok * Cd + c0 + tx] = __float2half_rn(t[tx][i]);
    }
}

// ======================= MEGA kernel =======================
// smem halves (52224): smA [0,15360) | Kh [15360,30720) | Vt [30720,44544) | smB [44544,52224)
__global__ void __launch_bounds__(256, 2) k_mega(
    const float* __restrict__ q_b, const float* __restrict__ kv_b,
    const float* __restrict__ n1g, const float* __restrict__ n1b,
    const float* __restrict__ b1h, const float* __restrict__ b2,
    const float* __restrict__ g2, const float* __restrict__ bb2,
    float* __restrict__ out)
{
    extern __shared__ float smf[];
    __half* smA = (__half*)smf;
    __half* Kh  = smA + 15360;
    __half* Vt  = smA + 30720;
    __half* smB = smA + 44544;
    __half* QB  = Kh;                  // Q weight dbuf (2x7680)
    __half* smB2 = Kh;                 // Wc dbuf (2x7680)
    float*  St  = smf + 7680;
    __half* smB1m = smA + 15360;
    __half* smHm  = smA + 23040;
    __half* smB2m = smA + 30720;
    int win = blockIdx.x;
    int tid = threadIdx.x;
    int lane = tid & 31, w = tid >> 5;
    int g = lane >> 2, tg = lane & 3;
    int mi = w & 3, hp = w >> 2;
    const int r0 = tid >> 3, c4 = 4 * (tid & 7);
    const int stsO = r0 * 40 + c4;
    const int wr = (w & 1) * 32, wc = (w >> 1) * 48;
    const int wc1 = (w >> 1) * 24;

    const int aoff  = (lane & 15) * 40 + (lane >> 4) * 8;
    const int boff  = ((lane & 7) + ((lane >> 4) & 1) * 8) * 40 + ((lane >> 3) & 1) * 8;
    const int b2off = (lane & 7) * 40 + ((lane >> 3) & 1) * 8;
    const int voff  = ((lane & 7) + ((lane >> 4) & 1) * 8) * 72 + ((lane >> 3) & 1) * 8;

    int bI = win >> 10, wh = (win >> 5) & 31, ww = win & 31;

    // ---------- load xw; stage Wq chunk 0 into QB buf0 ----------
    const __half* xsrc = g_xth + (size_t)win * 64 * 192;
#pragma unroll
    for (int c = 0; c < 6; c++)
#pragma unroll
        for (int i = 0; i < 2; i++) {
            uint2 v = *(const uint2*)(xsrc + (size_t)(r0 + 32 * i) * 192 + c * 32 + c4);
            *(uint2*)(smA + c * 2560 + stsO + 1280 * i) = v;
        }
    uint2 rb[6];
#pragma unroll
    for (int i = 0; i < 6; i++)
        rb[i] = *(const uint2*)(w_qh + (size_t)(r0 + 32 * i) * 192 + c4);
#pragma unroll
    for (int i = 0; i < 6; i++) *(uint2*)(QB + stsO + 1280 * i) = rb[i];
    __syncthreads();

    // ---------- Q GEMM (double-buffered weights in QB, 1 sync/chunk) ----------
    float qacc[3][4][4];
#pragma unroll
    for (int t = 0; t < 3; t++)
#pragma unroll
        for (int nq = 0; nq < 4; nq++)
#pragma unroll
            for (int e = 0; e < 4; e++) qacc[t][nq][e] = 0.f;
#pragma unroll 1
    for (int kc = 0; kc < 6; kc++) {
        if (kc + 1 < 6)
#pragma unroll
            for (int i = 0; i < 6; i++)
                rb[i] = *(const uint2*)(w_qh + (size_t)(r0 + 32 * i) * 192 + (kc + 1) * 32 + c4);
        const __half* Bb = QB + (kc & 1) * 7680;
#pragma unroll
        for (int kk = 0; kk < 32; kk += 16) {
            unsigned af[4];
            ldsm4(af, smA + kc * 2560 + 16 * mi * 40 + kk + aoff);
#pragma unroll
            for (int t = 0; t < 3; t++) {
                unsigned bq0[4], bq1[4];
                ldsm4(bq0, Bb + (32 * (2 * t + hp)) * 40 + kk + boff);
                ldsm4(bq1, Bb + (32 * (2 * t + hp) + 16) * 40 + kk + boff);
                mma16(qacc[t][0], af, bq0[0], bq0[1]);
                mma16(qacc[t][1], af, bq0[2], bq0[3]);
                mma16(qacc[t][2], af, bq1[0], bq1[1]);
                mma16(qacc[t][3], af, bq1[2], bq1[3]);
            }
        }
        if (kc + 1 < 6)
#pragma unroll
            for (int i = 0; i < 6; i++)
                *(uint2*)(QB + ((kc + 1) & 1) * 7680 + stsO + 1280 * i) = rb[i];
        __syncthreads();
    }

    // ---------- repack Q ----------
    unsigned aq[3][2][4];
#pragma unroll
    for (int t = 0; t < 3; t++) {
        int h = 2 * t + hp;
#pragma unroll
        for (int ks = 0; ks < 2; ks++) {
            float2 b0 = *(const float2*)(q_b + 32 * h + 16 * ks + 2 * tg);
            float2 b1 = *(const float2*)(q_b + 32 * h + 16 * ks + 8 + 2 * tg);
            b0.x *= QSCALE; b0.y *= QSCALE; b1.x *= QSCALE; b1.y *= QSCALE;
            aq[t][ks][0] = h2u(__floats2half2_rn(qacc[t][2*ks][0] + b0.x, qacc[t][2*ks][1] + b0.y));
            aq[t][ks][1] = h2u(__floats2half2_rn(qacc[t][2*ks][2] + b0.x, qacc[t][2*ks][3] + b0.y));
            aq[t][ks][2] = h2u(__floats2half2_rn(qacc[t][2*ks+1][0] + b1.x, qacc[t][2*ks+1][1] + b1.y));
            aq[t][ks][3] = h2u(__floats2half2_rn(qacc[t][2*ks+1][2] + b1.x, qacc[t][2*ks+1][3] + b1.y));
        }
    }

    // ---------- load fw (overwrite smA); stage Wk chunk 0 into smB ----------
    const __half* fsrc = g_fth + (size_t)win * 64 * 192;
#pragma unroll
    for (int c = 0; c < 6; c++)
#pragma unroll
        for (int i = 0; i < 2; i++) {
            uint2 v = *(const uint2*)(fsrc + (size_t)(r0 + 32 * i) * 192 + c * 32 + c4);
            *(uint2*)(smA + c * 2560 + stsO + 1280 * i) = v;
        }
#pragma unroll
    for (int i = 0; i < 6; i++)
        rb[i] = *(const uint2*)(w_kvh + (size_t)(r0 + 32 * i) * 192 + c4);
#pragma unroll
    for (int i = 0; i < 6; i++) *(uint2*)(smB + stsO + 1280 * i) = rb[i];
    __syncthreads();

    // ---------- K GEMM -> Kh, V GEMM -> Vt (dbuf: smB <-> Vt-start, 1 sync/chunk) ----------
#pragma unroll 1
    for (int kv = 0; kv < 2; kv++) {
        float acc[2][6][4];
#pragma unroll
        for (int a = 0; a < 2; a++)
#pragma unroll
            for (int b_ = 0; b_ < 6; b_++)
#pragma unroll
                for (int e = 0; e < 4; e++) acc[a][b_][e] = 0.f;
#pragma unroll 1
        for (int kc = 0; kc < 6; kc++) {
            int idx = kv * 6 + kc;
            if (idx + 1 < 12) {
                int gn = idx + 1, kvn = gn / 6, kcn = gn - kvn * 6;
#pragma unroll
                for (int i = 0; i < 6; i++)
                    rb[i] = *(const uint2*)(w_kvh + (size_t)kvn * 36864
                                            + (size_t)(r0 + 32 * i) * 192 + kcn * 32 + c4);
            }
            const __half* Bb = (idx & 1) ? (smA + 30720) : smB;
#pragma unroll
            for (int kk = 0; kk < 32; kk += 16) {
                unsigned af[2][4], bbf[3][4];
                ldsm4(af[0], smA + kc * 2560 + wr * 40 + kk + aoff);
                ldsm4(af[1], smA + kc * 2560 + (wr + 16) * 40 + kk + aoff);
#pragma unroll
                for (int p = 0; p < 3; p++)
                    ldsm4(bbf[p], Bb + (wc + 16 * p) * 40 + kk + boff);
#pragma unroll
                for (int m2 = 0; m2 < 2; m2++)
#pragma unroll
                    for (int ni = 0; ni < 6; ni++)
                        mma16(acc[m2][ni], af[m2], bbf[ni >> 1][(ni & 1) * 2], bbf[ni >> 1][(ni & 1) * 2 + 1]);
            }
            if (idx + 1 < 12) {
                __half* Db = ((idx + 1) & 1) ? (smA + 30720) : smB;
#pragma unroll
                for (int i = 0; i < 6; i++)
                    *(uint2*)(Db + stsO + 1280 * i) = rb[i];
            }
            __syncthreads();
        }
#pragma unroll
        for (int m2 = 0; m2 < 2; m2++)
#pragma unroll
            for (int ni = 0; ni < 6; ni++) {
                int c = wc + 8 * ni + 2 * tg;
                int h = c >> 5, d = c & 31;
                float2 bv = *(const float2*)(kv_b + kv * 192 + c);
                int row = wr + 16 * m2 + g;
                if (kv == 0) {
                    *(__half2*)(Kh + h * 2560 + row * 40 + d) =
                        __floats2half2_rn(acc[m2][ni][0] + bv.x, acc[m2][ni][1] + bv.y);
                    *(__half2*)(Kh + h * 2560 + (row + 8) * 40 + d) =
                        __floats2half2_rn(acc[m2][ni][2] + bv.x, acc[m2][ni][3] + bv.y);
                } else {
                    __half* vb = Vt + h * 2304 + d * 72;
                    vb[row]          = __float2half_rn(acc[m2][ni][0] + bv.x);
                    vb[72 + row]     = __float2half_rn(acc[m2][ni][1] + bv.y);
                    vb[row + 8]      = __float2half_rn(acc[m2][ni][2] + bv.x);
                    vb[72 + row + 8] = __float2half_rn(acc[m2][ni][3] + bv.y);
                }
            }
    }
    __syncthreads();

    // ---------- attention ----------
    int i0 = 16 * mi + g;
    int w10 = win & 1023;
    bool eh = ((w10 >> 5) == 31), ew = ((w10 & 31) == 31);
    bool edge = eh || ew;
    int ri0 = 0, ri1 = 0, rj0a[8], rj1a[8];
    if (edge) {
        auto region = [&](int n) {
            int a = eh ? (((n >> 3) >= 4) ? 2 : 1) : 0;
            int b = ew ? (((n & 7)  >= 4) ? 2 : 1) : 0;
            return a * 3 + b;
        };
        ri0 = region(i0); ri1 = region(i0 + 8);
#pragma unroll
        for (int ni = 0; ni < 8; ni++) {
            int j0 = 8 * ni + 2 * tg;
            rj0a[ni] = region(j0);
            rj1a[ni] = region(j0 + 1);
        }
    }

#pragma unroll 1
    for (int t = 0; t < 3; t++) {
        int h = 2 * t + hp;
        float s[8][4];
#pragma unroll
        for (int ni = 0; ni < 8; ni++)
#pragma unroll
            for (int e = 0; e < 4; e++) s[ni][e] = 0.f;
        const __half* Khh = Kh + h * 2560;
#pragma unroll
        for (int p = 0; p < 4; p++) {
            unsigned kb0[4], kb1[4];
            ldsm4(kb0, Khh + (16 * p) * 40 + boff);
            ldsm4(kb1, Khh + (16 * p) * 40 + 16 + boff);
            mma16(s[2*p],     aq[t][0], kb0[0], kb0[1]);
            mma16(s[2*p],     aq[t][1], kb1[0], kb1[1]);
            mma16(s[2*p + 1], aq[t][0], kb0[2], kb0[3]);
            mma16(s[2*p + 1], aq[t][1], kb1[2], kb1[3]);
        }
        const __half* bb0 = g_biash + (h * 64 + i0) * 64;
#pragma unroll
        for (int ni = 0; ni < 8; ni++) {
            int j0 = 8 * ni + 2 * tg;
            float2 f0 = __half22float2(*(const __half2*)(bb0 + j0));
            float2 f1 = __half22float2(*(const __half2*)(bb0 + 512 + j0));
            s[ni][0] += f0.x; s[ni][1] += f0.y;
            s[ni][2] += f1.x; s[ni][3] += f1.y;
        }
        if (edge) {
#pragma unroll
            for (int ni = 0; ni < 8; ni++) {
                if (rj0a[ni] != ri0) s[ni][0] -= 100.f;
                if (rj1a[ni] != ri0) s[ni][1] -= 100.f;
                if (rj0a[ni] != ri1) s[ni][2] -= 100.f;
                if (rj1a[ni] != ri1) s[ni][3] -= 100.f;
            }
        }
        float m0 = -1e30f, m1 = -1e30f;
#pragma unroll
        for (int ni = 0; ni < 8; ni++) {
            m0 = fmaxf(m0, fmaxf(s[ni][0], s[ni][1]));
            m1 = fmaxf(m1, fmaxf(s[ni][2], s[ni][3]));
        }
        m0 = fmaxf(m0, __shfl_xor_sync(0xffffffffu, m0, 1));
        m0 = fmaxf(m0, __shfl_xor_sync(0xffffffffu, m0, 2));
        m1 = fmaxf(m1, __shfl_xor_sync(0xffffffffu, m1, 1));
        m1 = fmaxf(m1, __shfl_xor_sync(0xffffffffu, m1, 2));
        float s0 = 0.f, s1 = 0.f;
#pragma unroll
        for (int ni = 0; ni < 8; ni++) {
            s[ni][0] = __expf(s[ni][0] - m0); s0 += s[ni][0];
            s[ni][1] = __expf(s[ni][1] - m0); s0 += s[ni][1];
            s[ni][2] = __expf(s[ni][2] - m1); s1 += s[ni][2];
            s[ni][3] = __expf(s[ni][3] - m1); s1 += s[ni][3];
        }
        s0 += __shfl_xor_sync(0xffffffffu, s0, 1);
        s0 += __shfl_xor_sync(0xffffffffu, s0, 2);
        s1 += __shfl_xor_sync(0xffffffffu, s1, 1);
        s1 += __shfl_xor_sync(0xffffffffu, s1, 2);
        float inv0 = 1.f / s0, inv1 = 1.f / s1;
        unsigned pv[4][4];
#pragma unroll
        for (int js = 0; js < 4; js++) {
            pv[js][0] = h2u(__floats2half2_rn(s[2*js][0]   * inv0, s[2*js][1]   * inv0));
            pv[js][1] = h2u(__floats2half2_rn(s[2*js][2]   * inv1, s[2*js][3]   * inv1));
            pv[js][2] = h2u(__floats2half2_rn(s[2*js+1][0] * inv0, s[2*js+1][1] * inv0));
            pv[js][3] = h2u(__floats2half2_rn(s[2*js+1][2] * inv1, s[2*js+1][3] * inv1));
        }
        float o[4][4];
#pragma unroll
        for (int nd = 0; nd < 4; nd++)
#pragma unroll
            for (int e = 0; e < 4; e++) o[nd][e] = 0.f;
        const __half* Vth = Vt + h * 2304;
#pragma unroll
        for (int p = 0; p < 2; p++)
#pragma unroll
            for (int js = 0; js < 4; js++) {
                unsigned vb[4];
                ldsm4(vb, Vth + (16 * p) * 72 + 16 * js + voff);
                mma16(o[2*p],     pv[js], vb[0], vb[1]);
                mma16(o[2*p + 1], pv[js], vb[2], vb[3]);
            }
#pragma unroll
        for (int nd = 0; nd < 4; nd++) {
            int d0 = 8 * nd + 2 * tg;
            *(__half2*)(smA + h * 2560 + i0 * 40 + d0) =
                __floats2half2_rn(o[nd][0], o[nd][1]);
            *(__half2*)(smA + h * 2560 + (i0 + 8) * 40 + d0) =
                __floats2half2_rn(o[nd][2], o[nd][3]);
        }
    }

    // ---------- fused proj+merge GEMM ----------
#pragma unroll
    for (int i = 0; i < 6; i++)
        rb[i] = *(const uint2*)(w_ch + (size_t)(r0 + 32 * i) * 192 + c4);
    __syncthreads();
#pragma unroll
    for (int i = 0; i < 6; i++)
        *(uint2*)(smB2 + stsO + 1280 * i) = rb[i];
    __syncthreads();

    {
        float acc[2][6][4];
#pragma unroll
        for (int a = 0; a < 2; a++)
#pragma unroll
            for (int b_ = 0; b_ < 6; b_++)
#pragma unroll
                for (int e = 0; e < 4; e++) acc[a][b_][e] = 0.f;

#pragma unroll 1
        for (int kc = 0; kc < 6; kc++) {
            if (kc + 1 < 6)
#pragma unroll
                for (int i = 0; i < 6; i++)
                    rb[i] = *(const uint2*)(w_ch + (size_t)(r0 + 32 * i) * 192 + (kc + 1) * 32 + c4);
            const __half* Ab = smA + kc * 2560;
            const __half* Bb = smB2 + (kc & 1) * 7680;
#pragma unroll
            for (int kk = 0; kk < 32; kk += 16) {
                unsigned af[2][4], bbf[3][4];
                ldsm4(af[0], Ab + wr * 40 + kk + aoff);
                ldsm4(af[1], Ab + (wr + 16) * 40 + kk + aoff);
#pragma unroll
                for (int p = 0; p < 3; p++)
                    ldsm4(bbf[p], Bb + (wc + 16 * p) * 40 + kk + boff);
#pragma unroll
                for (int m2 = 0; m2 < 2; m2++)
#pragma unroll
                    for (int ni = 0; ni < 6; ni++)
                        mma16(acc[m2][ni], af[m2], bbf[ni >> 1][(ni & 1) * 2], bbf[ni >> 1][(ni & 1) * 2 + 1]);
            }
            if (kc + 1 < 6)
#pragma unroll
                for (int i = 0; i < 6; i++)
                    *(uint2*)(smB2 + ((kc + 1) & 1) * 7680 + stsO + 1280 * i) = rb[i];
            __syncthreads();
        }

#pragma unroll
        for (int m2 = 0; m2 < 2; m2++)
#pragma unroll
            for (int ni = 0; ni < 6; ni++) {
                int row = wr + 16 * m2 + g;
                int col = wc + 8 * ni + 2 * tg;
                St[row * 200 + col]           = acc[m2][ni][0];
                St[row * 200 + col + 1]       = acc[m2][ni][1];
                St[(row + 8) * 200 + col]     = acc[m2][ni][2];
                St[(row + 8) * 200 + col + 1] = acc[m2][ni][3];
            }
    }
    __syncthreads();

    // ---------- LN1 + shortcut -> x1h into smA; W1 oc0 chunk0 LDG hoisted ----------
    int wp = tid >> 5, l = tid & 31;
    uint2 rbw1[3];
#pragma unroll
    for (int i = 0; i < 3; i++)
        rbw1[i] = *(const uint2*)(w_f1h + (size_t)(r0 + 32 * i) * 192 + c4);
#pragma unroll 1
    for (int rr = 0; rr < 8; rr++) {
        int n = wp * 8 + rr;
        float vv[6]; float su = 0.f;
#pragma unroll
        for (int u = 0; u < 6; u++) {
            int c = l + 32 * u;
            vv[u] = St[n * 200 + c] + g_bc[c];
            su += vv[u];
        }
        su = warp_sum(su);
        float mean = su * (1.f / 192.f);
        float sq = 0.f;
#pragma unroll
        for (int u = 0; u < 6; u++) { float d = vv[u] - mean; sq += d * d; }
        sq = warp_sum(sq);
        float rstd = rsqrtf(sq * (1.f / 192.f) + 1e-5f);
#pragma unroll
        for (int u = 0; u < 6; u++) {
            int c = l + 32 * u;
            float y = (vv[u] - mean) * rstd * n1g[c] + n1b[c]
                      + __half2float(xsrc[(size_t)n * 192 + c]);
            smA[u * 2560 + n * 40 + l] = __float2half_rn(y);
        }
    }
    __syncthreads();   // all St reads retired before smB1m (aliases St) is written
#pragma unroll
    for (int i = 0; i < 3; i++)
        *(uint2*)(smB1m + stsO + 1280 * i) = rbw1[i];
    __syncthreads();

    // ---------- MLP: fc1 + GELU + fc2 ----------
    float acc2[2][6][4];
#pragma unroll
    for (int a = 0; a < 2; a++)
#pragma unroll
        for (int b_ = 0; b_ < 6; b_++)
#pragma unroll
            for (int cc = 0; cc < 4; cc++) acc2[a][b_][cc] = 0.f;

#pragma unroll 1
    for (int oc = 0; oc < 8; oc++) {
        const __half* W1 = w_f1h + (size_t)(oc * 96) * 192;

        float acc1[2][3][4];
#pragma unroll
        for (int a = 0; a < 2; a++)
#pragma unroll
            for (int b_ = 0; b_ < 3; b_++)
#pragma unroll
                for (int cc = 0; cc < 4; cc++) acc1[a][b_][cc] = 0.f;

#pragma unroll 1
        for (int kc = 0; kc < 6; kc++) {
            uint2 rb1[3];
            if (kc + 1 < 6)
#pragma unroll
                for (int i = 0; i < 3; i++)
                    rb1[i] = *(const uint2*)(W1 + (size_t)(r0 + 32 * i) * 192 + (kc + 1) * 32 + c4);
            const __half* Ab = smA + kc * 2560;
            const __half* Bb = smB1m + (kc & 1) * 3840;
#pragma unroll
            for (int kk = 0; kk < 32; kk += 16) {
                unsigned af[2][4], b1r[4], b1s[2];
                ldsm4(af[0], Ab + wr * 40 + kk + aoff);
                ldsm4(af[1], Ab + (wr + 16) * 40 + kk + aoff);
                ldsm4(b1r, Bb + wc1 * 40 + kk + boff);
                ldsm2(b1s, Bb + (wc1 + 16) * 40 + kk + b2off);
#pragma unroll
                for (int m2 = 0; m2 < 2; m2++) {
                    mma16(acc1[m2][0], af[m2], b1r[0], b1r[1]);
                    mma16(acc1[m2][1], af[m2], b1r[2], b1r[3]);
                    mma16(acc1[m2][2], af[m2], b1s[0], b1s[1]);
                }
            }
            if (kc + 1 < 6)
#pragma unroll
                for (int i = 0; i < 3; i++)
                    *(uint2*)(smB1m + ((kc + 1) & 1) * 3840 + stsO + 1280 * i) = rb1[i];
            __syncthreads();
        }

#pragma unroll
        for (int m2 = 0; m2 < 2; m2++)
#pragma unroll
            for (int ni = 0; ni < 3; ni++) {
                int row = wr + 16 * m2 + g;
                int col = wc1 + 8 * ni + 2 * tg;
                float2 bv = *(const float2*)(b1h + oc * 96 + col);
                __half* hp0 = smHm + (col >> 5) * 2560 + row * 40 + (col & 31);
                *(__half2*)hp0 = __floats2half2_rn(
                    gelu_f(acc1[m2][ni][0] + bv.x), gelu_f(acc1[m2][ni][1] + bv.y));
                *(__half2*)(hp0 + 320) = __floats2half2_rn(
                    gelu_f(acc1[m2][ni][2] + bv.x), gelu_f(acc1[m2][ni][3] + bv.y));
            }

        const __half* W2 = w_f2h;
        uint2 rb2[6];
#pragma unroll
        for (int i = 0; i < 6; i++)
            rb2[i] = *(const uint2*)(W2 + (size_t)(r0 + 32 * i) * 768 + oc * 96 + c4);
#pragma unroll
        for (int i = 0; i < 6; i++)
            *(uint2*)(smB2m + stsO + 1280 * i) = rb2[i];
        __syncthreads();

#pragma unroll 1
        for (int kc = 0; kc < 3; kc++) {
            bool w1pre = (kc == 2) && (oc + 1 < 8);
            if (kc + 1 < 3) {
#pragma unroll
                for (int i = 0; i < 6; i++)
                    rb2[i] = *(const uint2*)(W2 + (size_t)(r0 + 32 * i) * 768 + oc * 96 + (kc + 1) * 32 + c4);
            } else if (w1pre) {
#pragma unroll
                for (int i = 0; i < 3; i++)
                    rb2[i] = *(const uint2*)(w_f1h + (size_t)((oc + 1) * 96 + r0 + 32 * i) * 192 + c4);
            }
            const __half* Ab = smHm + kc * 2560;
            const __half* Bb = smB2m + (kc & 1) * 7680;
#pragma unroll
            for (int kk = 0; kk < 32; kk += 16) {
                unsigned af[2][4], bbf[3][4];
                ldsm4(af[0], Ab + wr * 40 + kk + aoff);
                ldsm4(af[1], Ab + (wr + 16) * 40 + kk + aoff);
#pragma unroll
                for (int p = 0; p < 3; p++)
                    ldsm4(bbf[p], Bb + (wc + 16 * p) * 40 + kk + boff);
#pragma unroll
                for (int m2 = 0; m2 < 2; m2++)
#pragma unroll
                    for (int ni = 0; ni < 6; ni++)
                        mma16(acc2[m2][ni], af[m2], bbf[ni >> 1][(ni & 1) * 2], bbf[ni >> 1][(ni & 1) * 2 + 1]);
            }
            if (kc + 1 < 3) {
#pragma unroll
                for (int i = 0; i < 6; i++)
                    *(uint2*)(smB2m + ((kc + 1) & 1) * 7680 + stsO + 1280 * i) = rb2[i];
            } else if (w1pre) {
#pragma unroll
                for (int i = 0; i < 3; i++)
                    *(uint2*)(smB1m + stsO + 1280 * i) = rb2[i];
            }
            __syncthreads();
        }
    }

    // ---------- final: bias + LN2 + residual(x1h) + pixel scatter ----------
#pragma unroll
    for (int m2 = 0; m2 < 2; m2++)
#pragma unroll
        for (int ni = 0; ni < 6; ni++) {
            int row = wr + 16 * m2 + g;
            int col = wc + 8 * ni + 2 * tg;
            St[row * 200 + col]           = acc2[m2][ni][0];
            St[row * 200 + col + 1]       = acc2[m2][ni][1];
            St[(row + 8) * 200 + col]     = acc2[m2][ni][2];
            St[(row + 8) * 200 + col + 1] = acc2[m2][ni][3];
        }
    __syncthreads();
#pragma unroll 1
    for (int rr = 0; rr < 8; rr++) {
        int n = wp * 8 + rr;
        int hpx = (wh * 8 + (n >> 3) + 4) & 255;
        int wpx = (ww * 8 + (n & 7) + 4) & 255;
        size_t row = ((size_t)bI * HWd + hpx * Wdim + wpx) * Cd;
        float vv[6]; float su = 0.f;
#pragma unroll
        for (int u = 0; u < 6; u++) {
            int c = l + 32 * u;
            vv[u] = St[n * 200 + c] + b2[c];
            su += vv[u];
        }
        su = warp_sum(su);
        float mean = su * (1.f / 192.f);
        float sq = 0.f;
#pragma unroll
        for (int u = 0; u < 6; u++) { float d = vv[u] - mean; sq += d * d; }
        sq = warp_sum(sq);
        float rstd = rsqrtf(sq * (1.f / 192.f) + 1e-5f);
#pragma unroll
        for (int u = 0; u < 6; u++) {
            int c = l + 32 * u;
            float x1v = __half2float(smA[u * 2560 + n * 40 + l]);
            out[row + c] = x1v + (vv[u] - mean) * rstd * g2[c] + bb2[c];
        }
    }
}

// ======================= host =======================
extern "C" void kernel_launch(void* const* d_in, const int* in_sizes, int n_in,
                              void* d_out, int out_size)
{
    const float* x    = (const float*)d_in[0];
    const float* feat = (const float*)d_in[1];
    const int*   ridx = (const int*)  d_in[3];
    const float* rtab = (const float*)d_in[4];
    const float* q_w  = (const float*)d_in[5];
    const float* q_b  = (const float*)d_in[6];
    const float* kv_w = (const float*)d_in[7];
    const float* kv_b = (const float*)d_in[8];
    const float* p_w  = (const float*)d_in[9];
    const float* p_b  = (const float*)d_in[10];
    const float* m_w  = (const float*)d_in[11];
    const float* n1g  = (const float*)d_in[12];
    const float* n1b  = (const float*)d_in[13];
    const float* n2g  = (const float*)d_in[14];
    const float* n2b  = (const float*)d_in[15];
    const float* f1w  = (const float*)d_in[16];
    const float* f1b  = (const float*)d_in[17];
    const float* f2w  = (const float*)d_in[18];
    const float* f2b  = (const float*)d_in[19];
    float* out = (float*)d_out;

    __half *dxth, *dfth;
    cudaGetSymbolAddress((void**)&dxth, g_xth);
    cudaGetSymbolAddress((void**)&dfth, g_fth);

    const int smMega = 52224 * 2;                        // 104448
    cudaFuncSetAttribute(k_mega, cudaFuncAttributeMaxDynamicSharedMemorySize, smMega);

    k_prepw<<<1584, 256>>>(q_w, kv_w, f1w, f2w);                      // 0
    k_wcomb<<<144, 256>>>(m_w, p_w, p_b);                             // 1
    k_bias <<<96, 256>>>(ridx, rtab);                                 // 2
    k_transpose<<<dim3(6, 2048, 4), dim3(32, 8)>>>(x, dxth);          // 3
    k_transpose<<<dim3(6, 2048, 4), dim3(32, 8)>>>(feat, dfth);       // 4
    k_mega <<<NWINd, 256, smMega>>>(q_b, kv_b, n1g, n1b, f1b, f2b, n2g, n2b, out);  // 5
}

// round 14
// speedup vs baseline: 1.0756x; 1.0337x over previous
#include <cuda_runtime.h>
#include <cuda_fp16.h>
#include <math.h>
#include <stdint.h>

#define Hd    256
#define Wdim  256
#define HWd   65536
#define Cd    192
#define Bd    4
#define NHd   6
#define HDd   32
#define NWINd 4096
#define MTOKd 262144
#define HIDd  768
#define QSCALE 0.17677669529663687f

// -------- scratch --------
__device__ __half g_xth [(size_t)MTOKd * Cd];
__device__ __half g_fth [(size_t)MTOKd * Cd];
__device__ __half g_biash[NHd * 64 * 64];
__device__ __half w_qh [36864];
__device__ __half w_kvh[73728];
__device__ __half w_ch [36864];
__device__ float  g_bc [192];
__device__ __half w_f1h[147456];
__device__ __half w_f2h[147456];

__device__ __forceinline__ float warp_sum(float v) {
#pragma unroll
    for (int o = 16; o; o >>= 1) v += __shfl_xor_sync(0xffffffffu, v, o);
    return v;
}
__device__ __forceinline__ unsigned h2u(__half2 h) {
    return *reinterpret_cast<unsigned*>(&h);
}
__device__ __forceinline__ float gelu_f(float v) {
    return 0.5f * v * (1.f + erff(v * 0.70710678118654752f));
}
__device__ __forceinline__ void mma16(float* c, const unsigned* a, unsigned b0, unsigned b1) {
    asm volatile(
        "mma.sync.aligned.m16n8k16.row.col.f32.f16.f16.f32 "
        "{%0,%1,%2,%3}, {%4,%5,%6,%7}, {%8,%9}, {%0,%1,%2,%3};"
        : "+f"(c[0]), "+f"(c[1]), "+f"(c[2]), "+f"(c[3])
        : "r"(a[0]), "r"(a[1]), "r"(a[2]), "r"(a[3]), "r"(b0), "r"(b1));
}
__device__ __forceinline__ void ldsm4(unsigned* r, const __half* p) {
    uint32_t a = (uint32_t)__cvta_generic_to_shared(p);
    asm volatile("ldmatrix.sync.aligned.m8n8.x4.shared.b16 {%0,%1,%2,%3}, [%4];"
                 : "=r"(r[0]), "=r"(r[1]), "=r"(r[2]), "=r"(r[3]) : "r"(a));
}
__device__ __forceinline__ void ldsm2(unsigned* r, const __half* p) {
    uint32_t a = (uint32_t)__cvta_generic_to_shared(p);
    asm volatile("ldmatrix.sync.aligned.m8n8.x2.shared.b16 {%0,%1}, [%2];"
                 : "=r"(r[0]), "=r"(r[1]) : "r"(a));
}
__device__ __forceinline__ void cpa16(__half* dst, const __half* src) {
    uint32_t d = (uint32_t)__cvta_generic_to_shared(dst);
    asm volatile("cp.async.cg.shared.global [%0], [%1], 16;" :: "r"(d), "l"(src));
}
__device__ __forceinline__ void cpa8(__half* dst, const __half* src) {
    uint32_t d = (uint32_t)__cvta_generic_to_shared(dst);
    asm volatile("cp.async.ca.shared.global [%0], [%1], 8;" :: "r"(d), "l"(src));
}
__device__ __forceinline__ void cp_commit() {
    asm volatile("cp.async.commit_group;" ::: "memory");
}
__device__ __forceinline__ void cp_wait0() {
    asm volatile("cp.async.wait_group 0;" ::: "memory");
}

// ======================= prep kernels =======================
__global__ void k_prepw(const float* __restrict__ qw, const float* __restrict__ kvw,
                        const float* __restrict__ f1w, const float* __restrict__ f2w) {
    int i = blockIdx.x * 256 + threadIdx.x;
    if (i < 36864)        w_qh [i]          = __float2half_rn(qw[i] * QSCALE);
    else if (i < 110592)  w_kvh[i - 36864]  = __float2half_rn(kvw[i - 36864]);
    else if (i < 258048)  w_f1h[i - 110592] = __float2half_rn(f1w[i - 110592]);
    else if (i < 405504)  w_f2h[i - 258048] = __float2half_rn(f2w[i - 258048]);
}
__global__ void k_wcomb(const float* __restrict__ mw, const float* __restrict__ pw,
                        const float* __restrict__ pb) {
    int e = blockIdx.x * 256 + threadIdx.x;
    if (e < 36864) {
        int i = e / 192, j = e - (e / 192) * 192;
        float acc = 0.f;
        for (int k = 0; k < 192; k++) acc += mw[i * 192 + k] * pw[k * 192 + j];
        w_ch[e] = __float2half_rn(acc);
    }
    if (e < 192) {
        float acc = 0.f;
        for (int k = 0; k < 192; k++) acc += mw[e * 192 + k] * pb[k];
        g_bc[e] = acc;
    }
}
__global__ void k_bias(const int* __restrict__ relidx, const float* __restrict__ table) {
    int idx = blockIdx.x * 256 + threadIdx.x;
    if (idx < NHd * 4096) {
        int h = idx >> 12, r = idx & 4095;
        g_biash[idx] = __float2half_rn(table[relidx[r] * NHd + h]);
    }
}

// ======================= K0: transpose both tensors -> fp16 WINDOW order ========
__global__ void k_transpose(const float* __restrict__ x, const float* __restrict__ feat) {
    __shared__ float t[32][33];
    int z = blockIdx.z;
    int b = z & 3, which = z >> 2;
    int c0 = blockIdx.x << 5;
    int p0 = blockIdx.y << 5;
    const float* src = (which ? feat : x) + (size_t)b * Cd * HWd;
    int tx = threadIdx.x, ty = threadIdx.y;
#pragma unroll
    for (int i = ty; i < 32; i += 8)
        t[i][tx] = src[(size_t)(c0 + i) * HWd + p0 + tx];
    __syncthreads();
    int h  = p0 >> 8;
    int h2 = (h - 4) & 255;
    int whp = ((h2 >> 3) << 5);
    int nh8 = (h2 & 7) << 3;
    __half* dh = (which ? g_fth : g_xth) + (size_t)b * HWd * Cd;
#pragma unroll
    for (int i = ty; i < 32; i += 8) {
        int wv = ((p0 & 255) + i);
        int w2 = (wv - 4) & 255;
        int tok = ((whp + (w2 >> 3)) << 6) + nh8 + (w2 & 7);
        dh[(size_t)tok * Cd + c0 + tx] = __float2half_rn(t[tx][i]);
    }
}

// ======================= MEGA kernel =======================
// smem halves (52224): smA [0,15360) | Kh [15360,30720) | Vt [30720,44544) | smB [44544,52224)
__global__ void __launch_bounds__(256, 2) k_mega(
    const float* __restrict__ q_b, const float* __restrict__ kv_b,
    const float* __restrict__ n1g, const float* __restrict__ n1b,
    const float* __restrict__ b1h, const float* __restrict__ b2,
    const float* __restrict__ g2, const float* __restrict__ bb2,
    float* __restrict__ out)
{
    extern __shared__ float smf[];
    __half* smA = (__half*)smf;
    __half* Kh  = smA + 15360;
    __half* Vt  = smA + 30720;
    __half* smB = smA + 44544;
    __half* QB  = Kh;                  // Q weight dbuf (2x7680)
    __half* smB2 = Kh;                 // Wc dbuf (2x7680)
    float*  St  = smf + 7680;
    __half* smB1m = smA + 15360;
    __half* smHm  = smA + 23040;
    __half* smB2m = smA + 30720;
    int win = blockIdx.x;
    int tid = threadIdx.x;
    int lane = tid & 31, w = tid >> 5;
    int g = lane >> 2, tg = lane & 3;
    int mi = w & 3, hp = w >> 2;
    const int r0 = tid >> 3, c4 = 4 * (tid & 7);
    const int stsO = r0 * 40 + c4;
    const int r16 = tid >> 2, q8 = 8 * (tid & 3);
    const int a16 = r16 * 40 + q8;
    const int wr = (w & 1) * 32, wc = (w >> 1) * 48;
    const int wc1 = (w >> 1) * 24;

    const int aoff  = (lane & 15) * 40 + (lane >> 4) * 8;
    const int boff  = ((lane & 7) + ((lane >> 4) & 1) * 8) * 40 + ((lane >> 3) & 1) * 8;
    const int b2off = (lane & 7) * 40 + ((lane >> 3) & 1) * 8;
    const int voff  = ((lane & 7) + ((lane >> 4) & 1) * 8) * 72 + ((lane >> 3) & 1) * 8;

    int bI = win >> 10, wh = (win >> 5) & 31, ww = win & 31;

    // ---------- async load xw + Wq chunk0 ----------
    const __half* xsrc = g_xth + (size_t)win * 64 * 192;
#pragma unroll
    for (int c = 0; c < 6; c++)
        cpa16(smA + c * 2560 + a16, xsrc + (size_t)r16 * 192 + c * 32 + q8);
#pragma unroll
    for (int i = 0; i < 3; i++)
        cpa16(QB + a16 + 2560 * i, w_qh + (size_t)(r16 + 64 * i) * 192 + q8);
    cp_commit();
    cp_wait0();
    __syncthreads();

    // ---------- Q GEMM ----------
    float qacc[3][4][4];
#pragma unroll
    for (int t = 0; t < 3; t++)
#pragma unroll
        for (int nq = 0; nq < 4; nq++)
#pragma unroll
            for (int e = 0; e < 4; e++) qacc[t][nq][e] = 0.f;
#pragma unroll 1
    for (int kc = 0; kc < 6; kc++) {
        if (kc + 1 < 6) {
#pragma unroll
            for (int i = 0; i < 3; i++)
                cpa16(QB + ((kc + 1) & 1) * 7680 + a16 + 2560 * i,
                      w_qh + (size_t)(r16 + 64 * i) * 192 + (kc + 1) * 32 + q8);
            cp_commit();
        }
        const __half* Bb = QB + (kc & 1) * 7680;
#pragma unroll
        for (int kk = 0; kk < 32; kk += 16) {
            unsigned af[4];
            ldsm4(af, smA + kc * 2560 + 16 * mi * 40 + kk + aoff);
#pragma unroll
            for (int t = 0; t < 3; t++) {
                unsigned bq0[4], bq1[4];
                ldsm4(bq0, Bb + (32 * (2 * t + hp)) * 40 + kk + boff);
                ldsm4(bq1, Bb + (32 * (2 * t + hp) + 16) * 40 + kk + boff);
                mma16(qacc[t][0], af, bq0[0], bq0[1]);
                mma16(qacc[t][1], af, bq0[2], bq0[3]);
                mma16(qacc[t][2], af, bq1[0], bq1[1]);
                mma16(qacc[t][3], af, bq1[2], bq1[3]);
            }
        }
        cp_wait0();
        __syncthreads();
    }

    // ---------- async load fw + Wk chunk0 (smA reads done); repack Q meanwhile ----------
    const __half* fsrc = g_fth + (size_t)win * 64 * 192;
#pragma unroll
    for (int c = 0; c < 6; c++)
        cpa16(smA + c * 2560 + a16, fsrc + (size_t)r16 * 192 + c * 32 + q8);
#pragma unroll
    for (int i = 0; i < 3; i++)
        cpa16(smB + a16 + 2560 * i, w_kvh + (size_t)(r16 + 64 * i) * 192 + q8);
    cp_commit();

    unsigned aq[3][2][4];
#pragma unroll
    for (int t = 0; t < 3; t++) {
        int h = 2 * t + hp;
#pragma unroll
        for (int ks = 0; ks < 2; ks++) {
            float2 b0 = *(const float2*)(q_b + 32 * h + 16 * ks + 2 * tg);
            float2 b1 = *(const float2*)(q_b + 32 * h + 16 * ks + 8 + 2 * tg);
            b0.x *= QSCALE; b0.y *= QSCALE; b1.x *= QSCALE; b1.y *= QSCALE;
            aq[t][ks][0] = h2u(__floats2half2_rn(qacc[t][2*ks][0] + b0.x, qacc[t][2*ks][1] + b0.y));
            aq[t][ks][1] = h2u(__floats2half2_rn(qacc[t][2*ks][2] + b0.x, qacc[t][2*ks][3] + b0.y));
            aq[t][ks][2] = h2u(__floats2half2_rn(qacc[t][2*ks+1][0] + b1.x, qacc[t][2*ks+1][1] + b1.y));
            aq[t][ks][3] = h2u(__floats2half2_rn(qacc[t][2*ks+1][2] + b1.x, qacc[t][2*ks+1][3] + b1.y));
        }
    }
    cp_wait0();
    __syncthreads();

    // ---------- K GEMM -> Kh, V GEMM -> Vt (dbuf: smB <-> Vt-start) ----------
#pragma unroll 1
    for (int kv = 0; kv < 2; kv++) {
        float acc[2][6][4];
#pragma unroll
        for (int a = 0; a < 2; a++)
#pragma unroll
            for (int b_ = 0; b_ < 6; b_++)
#pragma unroll
                for (int e = 0; e < 4; e++) acc[a][b_][e] = 0.f;
#pragma unroll 1
        for (int kc = 0; kc < 6; kc++) {
            int idx = kv * 6 + kc;
            if (idx + 1 < 12) {
                int gn = idx + 1, kvn = gn / 6, kcn = gn - kvn * 6;
                __half* Db = ((idx + 1) & 1) ? (smA + 30720) : smB;
#pragma unroll
                for (int i = 0; i < 3; i++)
                    cpa16(Db + a16 + 2560 * i,
                          w_kvh + (size_t)kvn * 36864 + (size_t)(r16 + 64 * i) * 192 + kcn * 32 + q8);
                cp_commit();
            }
            const __half* Bb = (idx & 1) ? (smA + 30720) : smB;
#pragma unroll
            for (int kk = 0; kk < 32; kk += 16) {
                unsigned af[2][4], bbf[3][4];
                ldsm4(af[0], smA + kc * 2560 + wr * 40 + kk + aoff);
                ldsm4(af[1], smA + kc * 2560 + (wr + 16) * 40 + kk + aoff);
#pragma unroll
                for (int p = 0; p < 3; p++)
                    ldsm4(bbf[p], Bb + (wc + 16 * p) * 40 + kk + boff);
#pragma unroll
                for (int m2 = 0; m2 < 2; m2++)
#pragma unroll
                    for (int ni = 0; ni < 6; ni++)
                        mma16(acc[m2][ni], af[m2], bbf[ni >> 1][(ni & 1) * 2], bbf[ni >> 1][(ni & 1) * 2 + 1]);
            }
            cp_wait0();
            __syncthreads();
        }
#pragma unroll
        for (int m2 = 0; m2 < 2; m2++)
#pragma unroll
            for (int ni = 0; ni < 6; ni++) {
                int c = wc + 8 * ni + 2 * tg;
                int h = c >> 5, d = c & 31;
                float2 bv = *(const float2*)(kv_b + kv * 192 + c);
                int row = wr + 16 * m2 + g;
                if (kv == 0) {
                    *(__half2*)(Kh + h * 2560 + row * 40 + d) =
                        __floats2half2_rn(acc[m2][ni][0] + bv.x, acc[m2][ni][1] + bv.y);
                    *(__half2*)(Kh + h * 2560 + (row + 8) * 40 + d) =
                        __floats2half2_rn(acc[m2][ni][2] + bv.x, acc[m2][ni][3] + bv.y);
                } else {
                    __half* vb = Vt + h * 2304 + d * 72;
                    vb[row]          = __float2half_rn(acc[m2][ni][0] + bv.x);
                    vb[72 + row]     = __float2half_rn(acc[m2][ni][1] + bv.y);
                    vb[row + 8]      = __float2half_rn(acc[m2][ni][2] + bv.x);
                    vb[72 + row + 8] = __float2half_rn(acc[m2][ni][3] + bv.y);
                }
            }
    }
    __syncthreads();

    // ---------- attention ----------
    int i0 = 16 * mi + g;
    int w10 = win & 1023;
    bool eh = ((w10 >> 5) == 31), ew = ((w10 & 31) == 31);
    bool edge = eh || ew;
    int ri0 = 0, ri1 = 0, rj0a[8], rj1a[8];
    if (edge) {
        auto region = [&](int n) {
            int a = eh ? (((n >> 3) >= 4) ? 2 : 1) : 0;
            int b = ew ? (((n & 7)  >= 4) ? 2 : 1) : 0;
            return a * 3 + b;
        };
        ri0 = region(i0); ri1 = region(i0 + 8);
#pragma unroll
        for (int ni = 0; ni < 8; ni++) {
            int j0 = 8 * ni + 2 * tg;
            rj0a[ni] = region(j0);
            rj1a[ni] = region(j0 + 1);
        }
    }

#pragma unroll 1
    for (int t = 0; t < 3; t++) {
        int h = 2 * t + hp;
        float s[8][4];
#pragma unroll
        for (int ni = 0; ni < 8; ni++)
#pragma unroll
            for (int e = 0; e < 4; e++) s[ni][e] = 0.f;
        const __half* Khh = Kh + h * 2560;
#pragma unroll
        for (int p = 0; p < 4; p++) {
            unsigned kb0[4], kb1[4];
            ldsm4(kb0, Khh + (16 * p) * 40 + boff);
            ldsm4(kb1, Khh + (16 * p) * 40 + 16 + boff);
            mma16(s[2*p],     aq[t][0], kb0[0], kb0[1]);
            mma16(s[2*p],     aq[t][1], kb1[0], kb1[1]);
            mma16(s[2*p + 1], aq[t][0], kb0[2], kb0[3]);
            mma16(s[2*p + 1], aq[t][1], kb1[2], kb1[3]);
        }
        const __half* bb0 = g_biash + (h * 64 + i0) * 64;
#pragma unroll
        for (int ni = 0; ni < 8; ni++) {
            int j0 = 8 * ni + 2 * tg;
            float2 f0 = __half22float2(*(const __half2*)(bb0 + j0));
            float2 f1 = __half22float2(*(const __half2*)(bb0 + 512 + j0));
            s[ni][0] += f0.x; s[ni][1] += f0.y;
            s[ni][2] += f1.x; s[ni][3] += f1.y;
        }
        if (edge) {
#pragma unroll
            for (int ni = 0; ni < 8; ni++) {
                if (rj0a[ni] != ri0) s[ni][0] -= 100.f;
                if (rj1a[ni] != ri0) s[ni][1] -= 100.f;
                if (rj0a[ni] != ri1) s[ni][2] -= 100.f;
                if (rj1a[ni] != ri1) s[ni][3] -= 100.f;
            }
        }
        float m0 = -1e30f, m1 = -1e30f;
#pragma unroll
        for (int ni = 0; ni < 8; ni++) {
            m0 = fmaxf(m0, fmaxf(s[ni][0], s[ni][1]));
            m1 = fmaxf(m1, fmaxf(s[ni][2], s[ni][3]));
        }
        m0 = fmaxf(m0, __shfl_xor_sync(0xffffffffu, m0, 1));
        m0 = fmaxf(m0, __shfl_xor_sync(0xffffffffu, m0, 2));
        m1 = fmaxf(m1, __shfl_xor_sync(0xffffffffu, m1, 1));
        m1 = fmaxf(m1, __shfl_xor_sync(0xffffffffu, m1, 2));
        float s0 = 0.f, s1 = 0.f;
#pragma unroll
        for (int ni = 0; ni < 8; ni++) {
            s[ni][0] = __expf(s[ni][0] - m0); s0 += s[ni][0];
            s[ni][1] = __expf(s[ni][1] - m0); s0 += s[ni][1];
            s[ni][2] = __expf(s[ni][2] - m1); s1 += s[ni][2];
            s[ni][3] = __expf(s[ni][3] - m1); s1 += s[ni][3];
        }
        s0 += __shfl_xor_sync(0xffffffffu, s0, 1);
        s0 += __shfl_xor_sync(0xffffffffu, s0, 2);
        s1 += __shfl_xor_sync(0xffffffffu, s1, 1);
        s1 += __shfl_xor_sync(0xffffffffu, s1, 2);
        float inv0 = 1.f / s0, inv1 = 1.f / s1;
        unsigned pv[4][4];
#pragma unroll
        for (int js = 0; js < 4; js++) {
            pv[js][0] = h2u(__floats2half2_rn(s[2*js][0]   * inv0, s[2*js][1]   * inv0));
            pv[js][1] = h2u(__floats2half2_rn(s[2*js][2]   * inv1, s[2*js][3]   * inv1));
            pv[js][2] = h2u(__floats2half2_rn(s[2*js+1][0] * inv0, s[2*js+1][1] * inv0));
            pv[js][3] = h2u(__floats2half2_rn(s[2*js+1][2] * inv1, s[2*js+1][3] * inv1));
        }
        float o[4][4];
#pragma unroll
        for (int nd = 0; nd < 4; nd++)
#pragma unroll
            for (int e = 0; e < 4; e++) o[nd][e] = 0.f;
        const __half* Vth = Vt + h * 2304;
#pragma unroll
        for (int p = 0; p < 2; p++)
#pragma unroll
            for (int js = 0; js < 4; js++) {
                unsigned vb[4];
                ldsm4(vb, Vth + (16 * p) * 72 + 16 * js + voff);
                mma16(o[2*p],     pv[js], vb[0], vb[1]);
                mma16(o[2*p + 1], pv[js], vb[2], vb[3]);
            }
#pragma unroll
        for (int nd = 0; nd < 4; nd++) {
            int d0 = 8 * nd + 2 * tg;
            *(__half2*)(smA + h * 2560 + i0 * 40 + d0) =
                __floats2half2_rn(o[nd][0], o[nd][1]);
            *(__half2*)(smA + h * 2560 + (i0 + 8) * 40 + d0) =
                __floats2half2_rn(o[nd][2], o[nd][3]);
        }
    }

    // ---------- fused proj+merge GEMM ----------
    __syncthreads();   // Kh reads (attention) retired before Wc cpa into smB2(=Kh)
#pragma unroll
    for (int i = 0; i < 3; i++)
        cpa16(smB2 + a16 + 2560 * i, w_ch + (size_t)(r16 + 64 * i) * 192 + q8);
    cp_commit();
    cp_wait0();
    __syncthreads();

    {
        float acc[2][6][4];
#pragma unroll
        for (int a = 0; a < 2; a++)
#pragma unroll
            for (int b_ = 0; b_ < 6; b_++)
#pragma unroll
                for (int e = 0; e < 4; e++) acc[a][b_][e] = 0.f;

#pragma unroll 1
        for (int kc = 0; kc < 6; kc++) {
            if (kc + 1 < 6) {
#pragma unroll
                for (int i = 0; i < 3; i++)
                    cpa16(smB2 + ((kc + 1) & 1) * 7680 + a16 + 2560 * i,
                          w_ch + (size_t)(r16 + 64 * i) * 192 + (kc + 1) * 32 + q8);
                cp_commit();
            }
            const __half* Ab = smA + kc * 2560;
            const __half* Bb = smB2 + (kc & 1) * 7680;
#pragma unroll
            for (int kk = 0; kk < 32; kk += 16) {
                unsigned af[2][4], bbf[3][4];
                ldsm4(af[0], Ab + wr * 40 + kk + aoff);
                ldsm4(af[1], Ab + (wr + 16) * 40 + kk + aoff);
#pragma unroll
                for (int p = 0; p < 3; p++)
                    ldsm4(bbf[p], Bb + (wc + 16 * p) * 40 + kk + boff);
#pragma unroll
                for (int m2 = 0; m2 < 2; m2++)
#pragma unroll
                    for (int ni = 0; ni < 6; ni++)
                        mma16(acc[m2][ni], af[m2], bbf[ni >> 1][(ni & 1) * 2], bbf[ni >> 1][(ni & 1) * 2 + 1]);
            }
            cp_wait0();
            __syncthreads();
        }

#pragma unroll
        for (int m2 = 0; m2 < 2; m2++)
#pragma unroll
            for (int ni = 0; ni < 6; ni++) {
                int row = wr + 16 * m2 + g;
                int col = wc + 8 * ni + 2 * tg;
                St[row * 200 + col]           = acc[m2][ni][0];
                St[row * 200 + col + 1]       = acc[m2][ni][1];
                St[(row + 8) * 200 + col]     = acc[m2][ni][2];
                St[(row + 8) * 200 + col + 1] = acc[m2][ni][3];
            }
    }
    __syncthreads();

    // ---------- LN1 + shortcut -> x1h into smA ----------
    int wp = tid >> 5, l = tid & 31;
#pragma unroll 1
    for (int rr = 0; rr < 8; rr++) {
        int n = wp * 8 + rr;
        float vv[6]; float su = 0.f;
#pragma unroll
        for (int u = 0; u < 6; u++) {
            int c = l + 32 * u;
            vv[u] = St[n * 200 + c] + g_bc[c];
            su += vv[u];
        }
        su = warp_sum(su);
        float mean = su * (1.f / 192.f);
        float sq = 0.f;
#pragma unroll
        for (int u = 0; u < 6; u++) { float d = vv[u] - mean; sq += d * d; }
        sq = warp_sum(sq);
        float rstd = rsqrtf(sq * (1.f / 192.f) + 1e-5f);
#pragma unroll
        for (int u = 0; u < 6; u++) {
            int c = l + 32 * u;
            float y = (vv[u] - mean) * rstd * n1g[c] + n1b[c]
                      + __half2float(xsrc[(size_t)n * 192 + c]);
            smA[u * 2560 + n * 40 + l] = __float2half_rn(y);
        }
    }
    __syncthreads();   // St reads retired before smB1m (aliases St) is written
#pragma unroll
    for (int i = 0; i < 3; i++)
        cpa8(smB1m + stsO + 1280 * i, w_f1h + (size_t)(r0 + 32 * i) * 192 + c4);
    cp_commit();
    cp_wait0();
    __syncthreads();

    // ---------- MLP: fc1 + GELU + fc2 ----------
    float acc2[2][6][4];
#pragma unroll
    for (int a = 0; a < 2; a++)
#pragma unroll
        for (int b_ = 0; b_ < 6; b_++)
#pragma unroll
            for (int cc = 0; cc < 4; cc++) acc2[a][b_][cc] = 0.f;

#pragma unroll 1
    for (int oc = 0; oc < 8; oc++) {
        const __half* W1 = w_f1h + (size_t)(oc * 96) * 192;

        float acc1[2][3][4];
#pragma unroll
        for (int a = 0; a < 2; a++)
#pragma unroll
            for (int b_ = 0; b_ < 3; b_++)
#pragma unroll
                for (int cc = 0; cc < 4; cc++) acc1[a][b_][cc] = 0.f;

#pragma unroll 1
        for (int kc = 0; kc < 6; kc++) {
            if (kc + 1 < 6) {
#pragma unroll
                for (int i = 0; i < 3; i++)
                    cpa8(smB1m + ((kc + 1) & 1) * 3840 + stsO + 1280 * i,
                         W1 + (size_t)(r0 + 32 * i) * 192 + (kc + 1) * 32 + c4);
                cp_commit();
            }
            const __half* Ab = smA + kc * 2560;
            const __half* Bb = smB1m + (kc & 1) * 3840;
#pragma unroll
            for (int kk = 0; kk < 32; kk += 16) {
                unsigned af[2][4], b1r[4], b1s[2];
                ldsm4(af[0], Ab + wr * 40 + kk + aoff);
                ldsm4(af[1], Ab + (wr + 16) * 40 + kk + aoff);
                ldsm4(b1r, Bb + wc1 * 40 + kk + boff);
                ldsm2(b1s, Bb + (wc1 + 16) * 40 + kk + b2off);
#pragma unroll
                for (int m2 = 0; m2 < 2; m2++) {
                    mma16(acc1[m2][0], af[m2], b1r[0], b1r[1]);
                    mma16(acc1[m2][1], af[m2], b1r[2], b1r[3]);
                    mma16(acc1[m2][2], af[m2], b1s[0], b1s[1]);
                }
            }
            cp_wait0();
            __syncthreads();
        }

#pragma unroll
        for (int m2 = 0; m2 < 2; m2++)
#pragma unroll
            for (int ni = 0; ni < 3; ni++) {
                int row = wr + 16 * m2 + g;
                int col = wc1 + 8 * ni + 2 * tg;
                float2 bv = *(const float2*)(b1h + oc * 96 + col);
                __half* hp0 = smHm + (col >> 5) * 2560 + row * 40 + (col & 31);
                *(__half2*)hp0 = __floats2half2_rn(
                    gelu_f(acc1[m2][ni][0] + bv.x), gelu_f(acc1[m2][ni][1] + bv.y));
                *(__half2*)(hp0 + 320) = __floats2half2_rn(
                    gelu_f(acc1[m2][ni][2] + bv.x), gelu_f(acc1[m2][ni][3] + bv.y));
            }

        const __half* W2 = w_f2h;
#pragma unroll
        for (int i = 0; i < 3; i++)
            cpa16(smB2m + a16 + 2560 * i,
                  W2 + (size_t)(r16 + 64 * i) * 768 + oc * 96 + q8);
        cp_commit();
        cp_wait0();
        __syncthreads();

#pragma unroll 1
        for (int kc = 0; kc < 3; kc++) {
            bool w1pre = (kc == 2) && (oc + 1 < 8);
            if (kc + 1 < 3) {
#pragma unroll
                for (int i = 0; i < 3; i++)
                    cpa16(smB2m + ((kc + 1) & 1) * 7680 + a16 + 2560 * i,
                          W2 + (size_t)(r16 + 64 * i) * 768 + oc * 96 + (kc + 1) * 32 + q8);
                cp_commit();
            } else if (w1pre) {
#pragma unroll
                for (int i = 0; i < 3; i++)
                    cpa8(smB1m + stsO + 1280 * i,
                         w_f1h + (size_t)((oc + 1) * 96 + r0 + 32 * i) * 192 + c4);
                cp_commit();
            }
            const __half* Ab = smHm + kc * 2560;
            const __half* Bb = smB2m + (kc & 1) * 7680;
#pragma unroll
            for (int kk = 0; kk < 32; kk += 16) {
                unsigned af[2][4], bbf[3][4];
                ldsm4(af[0], Ab + wr * 40 + kk + aoff);
                ldsm4(af[1], Ab + (wr + 16) * 40 + kk + aoff);
#pragma unroll
                for (int p = 0; p < 3; p++)
                    ldsm4(bbf[p], Bb + (wc + 16 * p) * 40 + kk + boff);
#pragma unroll
                for (int m2 = 0; m2 < 2; m2++)
#pragma unroll
                    for (int ni = 0; ni < 6; ni++)
                        mma16(acc2[m2][ni], af[m2], bbf[ni >> 1][(ni & 1) * 2], bbf[ni >> 1][(ni & 1) * 2 + 1]);
            }
            cp_wait0();
            __syncthreads();
        }
    }

    // ---------- final: bias + LN2 + residual(x1h) + pixel scatter ----------
#pragma unroll
    for (int m2 = 0; m2 < 2; m2++)
#pragma unroll
        for (int ni = 0; ni < 6; ni++) {
            int row = wr + 16 * m2 + g;
            int col = wc + 8 * ni + 2 * tg;
            St[row * 200 + col]           = acc2[m2][ni][0];
            St[row * 200 + col + 1]       = acc2[m2][ni][1];
            St[(row + 8) * 200 + col]     = acc2[m2][ni][2];
            St[(row + 8) * 200 + col + 1] = acc2[m2][ni][3];
        }
    __syncthreads();
#pragma unroll 1
    for (int rr = 0; rr < 8; rr++) {
        int n = wp * 8 + rr;
        int hpx = (wh * 8 + (n >> 3) + 4) & 255;
        int wpx = (ww * 8 + (n & 7) + 4) & 255;
        size_t row = ((size_t)bI * HWd + hpx * Wdim + wpx) * Cd;
        float vv[6]; float su = 0.f;
#pragma unroll
        for (int u = 0; u < 6; u++) {
            int c = l + 32 * u;
            vv[u] = St[n * 200 + c] + b2[c];
            su += vv[u];
        }
        su = warp_sum(su);
        float mean = su * (1.f / 192.f);
        float sq = 0.f;
#pragma unroll
        for (int u = 0; u < 6; u++) { float d = vv[u] - mean; sq += d * d; }
        sq = warp_sum(sq);
        float rstd = rsqrtf(sq * (1.f / 192.f) + 1e-5f);
#pragma unroll
        for (int u = 0; u < 6; u++) {
            int c = l + 32 * u;
            float x1v = __half2float(smA[u * 2560 + n * 40 + l]);
            out[row + c] = x1v + (vv[u] - mean) * rstd * g2[c] + bb2[c];
        }
    }
}

// ======================= host =======================
extern "C" void kernel_launch(void* const* d_in, const int* in_sizes, int n_in,
                              void* d_out, int out_size)
{
    const float* x    = (const float*)d_in[0];
    const float* feat = (const float*)d_in[1];
    const int*   ridx = (const int*)  d_in[3];
    const float* rtab = (const float*)d_in[4];
    const float* q_w  = (const float*)d_in[5];
    const float* q_b  = (const float*)d_in[6];
    const float* kv_w = (const float*)d_in[7];
    const float* kv_b = (const float*)d_in[8];
    const float* p_w  = (const float*)d_in[9];
    const float* p_b  = (const float*)d_in[10];
    const float* m_w  = (const float*)d_in[11];
    const float* n1g  = (const float*)d_in[12];
    const float* n1b  = (const float*)d_in[13];
    const float* n2g  = (const float*)d_in[14];
    const float* n2b  = (const float*)d_in[15];
    const float* f1w  = (const float*)d_in[16];
    const float* f1b  = (const float*)d_in[17];
    const float* f2w  = (const float*)d_in[18];
    const float* f2b  = (const float*)d_in[19];
    float* out = (float*)d_out;

    const int smMega = 52224 * 2;                        // 104448
    cudaFuncSetAttribute(k_mega, cudaFuncAttributeMaxDynamicSharedMemorySize, smMega);

    k_prepw<<<1584, 256>>>(q_w, kv_w, f1w, f2w);                      // 0
    k_wcomb<<<144, 256>>>(m_w, p_w, p_b);                             // 1
    k_bias <<<96, 256>>>(ridx, rtab);                                 // 2
    k_transpose<<<dim3(6, 2048, 8), dim3(32, 8)>>>(x, feat);          // 3
    k_mega <<<NWINd, 256, smMega>>>(q_b, kv_b, n1g, n1b, f1b, f2b, n2g, n2b, out);  // 4
}

// round 15
// speedup vs baseline: 1.1977x; 1.1135x over previous
#include <cuda_runtime.h>
#include <cuda_fp16.h>
#include <math.h>
#include <stdint.h>

#define Hd    256
#define Wdim  256
#define HWd   65536
#define Cd    192
#define Bd    4
#define NHd   6
#define HDd   32
#define NWINd 4096
#define MTOKd 262144
#define HIDd  768
#define QSCALE 0.17677669529663687f

// -------- scratch --------
__device__ __half g_xth [(size_t)MTOKd * Cd];
__device__ __half g_fth [(size_t)MTOKd * Cd];
__device__ __half g_biash[NHd * 64 * 64];
__device__ __half w_qh [36864];
__device__ __half w_kvh[73728];
__device__ __half w_ch [36864];
__device__ float  g_bc [192];
__device__ __half w_f1h[147456];
__device__ __half w_f2h[147456];

__device__ __forceinline__ float warp_sum(float v) {
#pragma unroll
    for (int o = 16; o; o >>= 1) v += __shfl_xor_sync(0xffffffffu, v, o);
    return v;
}
__device__ __forceinline__ unsigned h2u(__half2 h) {
    return *reinterpret_cast<unsigned*>(&h);
}
__device__ __forceinline__ float gelu_f(float v) {
    return 0.5f * v * (1.f + erff(v * 0.70710678118654752f));
}
__device__ __forceinline__ void mma16(float* c, const unsigned* a, unsigned b0, unsigned b1) {
    asm volatile(
        "mma.sync.aligned.m16n8k16.row.col.f32.f16.f16.f32 "
        "{%0,%1,%2,%3}, {%4,%5,%6,%7}, {%8,%9}, {%0,%1,%2,%3};"
        : "+f"(c[0]), "+f"(c[1]), "+f"(c[2]), "+f"(c[3])
        : "r"(a[0]), "r"(a[1]), "r"(a[2]), "r"(a[3]), "r"(b0), "r"(b1));
}
__device__ __forceinline__ void ldsm4(unsigned* r, const __half* p) {
    uint32_t a = (uint32_t)__cvta_generic_to_shared(p);
    asm volatile("ldmatrix.sync.aligned.m8n8.x4.shared.b16 {%0,%1,%2,%3}, [%4];"
                 : "=r"(r[0]), "=r"(r[1]), "=r"(r[2]), "=r"(r[3]) : "r"(a));
}
__device__ __forceinline__ void ldsm2(unsigned* r, const __half* p) {
    uint32_t a = (uint32_t)__cvta_generic_to_shared(p);
    asm volatile("ldmatrix.sync.aligned.m8n8.x2.shared.b16 {%0,%1}, [%2];"
                 : "=r"(r[0]), "=r"(r[1]) : "r"(a));
}
__device__ __forceinline__ void cpa16(__half* dst, const __half* src) {
    uint32_t d = (uint32_t)__cvta_generic_to_shared(dst);
    asm volatile("cp.async.cg.shared.global [%0], [%1], 16;" :: "r"(d), "l"(src));
}
__device__ __forceinline__ void cpa8(__half* dst, const __half* src) {
    uint32_t d = (uint32_t)__cvta_generic_to_shared(dst);
    asm volatile("cp.async.ca.shared.global [%0], [%1], 8;" :: "r"(d), "l"(src));
}
__device__ __forceinline__ void cp_commit() {
    asm volatile("cp.async.commit_group;" ::: "memory");
}
__device__ __forceinline__ void cp_wait0() {
    asm volatile("cp.async.wait_group 0;" ::: "memory");
}

// ======================= merged prep kernel =======================
__global__ void k_prep(const float* __restrict__ qw, const float* __restrict__ kvw,
                       const float* __restrict__ f1w, const float* __restrict__ f2w,
                       const float* __restrict__ mw, const float* __restrict__ pw,
                       const float* __restrict__ pb,
                       const int* __restrict__ relidx, const float* __restrict__ table)
{
    int bid = blockIdx.x;
    if (bid < 1584) {
        int i = bid * 256 + threadIdx.x;
        if (i < 36864)        w_qh [i]          = __float2half_rn(qw[i] * QSCALE);
        else if (i < 110592)  w_kvh[i - 36864]  = __float2half_rn(kvw[i - 36864]);
        else if (i < 258048)  w_f1h[i - 110592] = __float2half_rn(f1w[i - 110592]);
        else if (i < 405504)  w_f2h[i - 258048] = __float2half_rn(f2w[i - 258048]);
    } else if (bid < 1728) {
        int e = (bid - 1584) * 256 + threadIdx.x;
        if (e < 36864) {
            int i = e / 192, j = e - (e / 192) * 192;
            float acc = 0.f;
            for (int k = 0; k < 192; k++) acc += mw[i * 192 + k] * pw[k * 192 + j];
            w_ch[e] = __float2half_rn(acc);
        }
        if (e < 192) {
            float acc = 0.f;
            for (int k = 0; k < 192; k++) acc += mw[e * 192 + k] * pb[k];
            g_bc[e] = acc;
        }
    } else {
        int idx = (bid - 1728) * 256 + threadIdx.x;
        if (idx < NHd * 4096) {
            int h = idx >> 12, r = idx & 4095;
            g_biash[idx] = __float2half_rn(table[relidx[r] * NHd + h]);
        }
    }
}

// ======================= K0: vectorized transpose -> fp16 WINDOW order ==========
// tile: 64 channels x 32 pixels. Store: 1 uint4 (8 halves) per thread.
__global__ void k_transpose(const float* __restrict__ x, const float* __restrict__ feat) {
    __shared__ float t[64][33];
    int z = blockIdx.z;
    int b = z & 3, which = z >> 2;
    int c0 = blockIdx.x << 6;
    int p0 = blockIdx.y << 5;
    const float* src = (which ? feat : x) + (size_t)b * Cd * HWd;
    int tx = threadIdx.x & 31, ty = threadIdx.x >> 5;
#pragma unroll
    for (int j = 0; j < 8; j++)
        t[ty + 8 * j][tx] = src[(size_t)(c0 + ty + 8 * j) * HWd + p0 + tx];
    __syncthreads();
    int p = threadIdx.x >> 3, cg = threadIdx.x & 7;
    int pix = p0 + p;
    int h = pix >> 8, wv = pix & 255;
    int h2 = (h - 4) & 255, w2 = (wv - 4) & 255;
    int tok = ((((h2 >> 3) << 5) + (w2 >> 3)) << 6) + ((h2 & 7) << 3) + (w2 & 7);
    __half hv[8];
#pragma unroll
    for (int e = 0; e < 8; e++) hv[e] = __float2half_rn(t[8 * cg + e][p]);
    __half* dh = (which ? g_fth : g_xth) + (size_t)b * HWd * Cd;
    *(uint4*)(dh + (size_t)tok * Cd + c0 + 8 * cg) = *(uint4*)hv;
}

// ======================= MEGA kernel =======================
// smem halves (52224): smA [0,15360) | Kh [15360,30720) | Vt [30720,44544) | smB [44544,52224)
__global__ void __launch_bounds__(256, 2) k_mega(
    const float* __restrict__ q_b, const float* __restrict__ kv_b,
    const float* __restrict__ n1g, const float* __restrict__ n1b,
    const float* __restrict__ b1h, const float* __restrict__ b2,
    const float* __restrict__ g2, const float* __restrict__ bb2,
    float* __restrict__ out)
{
    extern __shared__ float smf[];
    __half* smA = (__half*)smf;
    __half* Kh  = smA + 15360;
    __half* Vt  = smA + 30720;
    __half* smB = smA + 44544;
    __half* QB  = Kh;
    __half* smB2 = Kh;
    float*  St  = smf + 7680;
    __half* smB1m = smA + 15360;
    __half* smHm  = smA + 23040;
    __half* smB2m = smA + 30720;
    int win = blockIdx.x;
    int tid = threadIdx.x;
    int lane = tid & 31, w = tid >> 5;
    int g = lane >> 2, tg = lane & 3;
    int mi = w & 3, hp = w >> 2;
    const int r0 = tid >> 3, c4 = 4 * (tid & 7);
    const int stsO = r0 * 40 + c4;
    const int r16 = tid >> 2, q8 = 8 * (tid & 3);
    const int a16 = r16 * 40 + q8;
    const int wr = (w & 1) * 32, wc = (w >> 1) * 48;
    const int wc1 = (w >> 1) * 24;

    const int aoff  = (lane & 15) * 40 + (lane >> 4) * 8;
    const int boff  = ((lane & 7) + ((lane >> 4) & 1) * 8) * 40 + ((lane >> 3) & 1) * 8;
    const int b2off = (lane & 7) * 40 + ((lane >> 3) & 1) * 8;
    const int voff  = ((lane & 7) + ((lane >> 4) & 1) * 8) * 72 + ((lane >> 3) & 1) * 8;

    int bI = win >> 10, wh = (win >> 5) & 31, ww = win & 31;

    // ---------- async load xw + Wq chunk0 ----------
    const __half* xsrc = g_xth + (size_t)win * 64 * 192;
#pragma unroll
    for (int c = 0; c < 6; c++)
        cpa16(smA + c * 2560 + a16, xsrc + (size_t)r16 * 192 + c * 32 + q8);
#pragma unroll
    for (int i = 0; i < 3; i++)
        cpa16(QB + a16 + 2560 * i, w_qh + (size_t)(r16 + 64 * i) * 192 + q8);
    cp_commit();
    cp_wait0();
    __syncthreads();

    // ---------- Q GEMM ----------
    float qacc[3][4][4];
#pragma unroll
    for (int t = 0; t < 3; t++)
#pragma unroll
        for (int nq = 0; nq < 4; nq++)
#pragma unroll
            for (int e = 0; e < 4; e++) qacc[t][nq][e] = 0.f;
#pragma unroll 1
    for (int kc = 0; kc < 6; kc++) {
        if (kc + 1 < 6) {
#pragma unroll
            for (int i = 0; i < 3; i++)
                cpa16(QB + ((kc + 1) & 1) * 7680 + a16 + 2560 * i,
                      w_qh + (size_t)(r16 + 64 * i) * 192 + (kc + 1) * 32 + q8);
            cp_commit();
        }
        const __half* Bb = QB + (kc & 1) * 7680;
#pragma unroll
        for (int kk = 0; kk < 32; kk += 16) {
            unsigned af[4];
            ldsm4(af, smA + kc * 2560 + 16 * mi * 40 + kk + aoff);
#pragma unroll
            for (int t = 0; t < 3; t++) {
                unsigned bq0[4], bq1[4];
                ldsm4(bq0, Bb + (32 * (2 * t + hp)) * 40 + kk + boff);
                ldsm4(bq1, Bb + (32 * (2 * t + hp) + 16) * 40 + kk + boff);
                mma16(qacc[t][0], af, bq0[0], bq0[1]);
                mma16(qacc[t][1], af, bq0[2], bq0[3]);
                mma16(qacc[t][2], af, bq1[0], bq1[1]);
                mma16(qacc[t][3], af, bq1[2], bq1[3]);
            }
        }
        cp_wait0();
        __syncthreads();
    }

    // ---------- async load fw + Wk chunk0; repack Q meanwhile ----------
    const __half* fsrc = g_fth + (size_t)win * 64 * 192;
#pragma unroll
    for (int c = 0; c < 6; c++)
        cpa16(smA + c * 2560 + a16, fsrc + (size_t)r16 * 192 + c * 32 + q8);
#pragma unroll
    for (int i = 0; i < 3; i++)
        cpa16(smB + a16 + 2560 * i, w_kvh + (size_t)(r16 + 64 * i) * 192 + q8);
    cp_commit();

    unsigned aq[3][2][4];
#pragma unroll
    for (int t = 0; t < 3; t++) {
        int h = 2 * t + hp;
#pragma unroll
        for (int ks = 0; ks < 2; ks++) {
            float2 b0 = *(const float2*)(q_b + 32 * h + 16 * ks + 2 * tg);
            float2 b1 = *(const float2*)(q_b + 32 * h + 16 * ks + 8 + 2 * tg);
            b0.x *= QSCALE; b0.y *= QSCALE; b1.x *= QSCALE; b1.y *= QSCALE;
            aq[t][ks][0] = h2u(__floats2half2_rn(qacc[t][2*ks][0] + b0.x, qacc[t][2*ks][1] + b0.y));
            aq[t][ks][1] = h2u(__floats2half2_rn(qacc[t][2*ks][2] + b0.x, qacc[t][2*ks][3] + b0.y));
            aq[t][ks][2] = h2u(__floats2half2_rn(qacc[t][2*ks+1][0] + b1.x, qacc[t][2*ks+1][1] + b1.y));
            aq[t][ks][3] = h2u(__floats2half2_rn(qacc[t][2*ks+1][2] + b1.x, qacc[t][2*ks+1][3] + b1.y));
        }
    }
    cp_wait0();
    __syncthreads();

    // ---------- K GEMM -> Kh, V GEMM -> Vt ----------
#pragma unroll 1
    for (int kv = 0; kv < 2; kv++) {
        float acc[2][6][4];
#pragma unroll
        for (int a = 0; a < 2; a++)
#pragma unroll
            for (int b_ = 0; b_ < 6; b_++)
#pragma unroll
                for (int e = 0; e < 4; e++) acc[a][b_][e] = 0.f;
#pragma unroll 1
        for (int kc = 0; kc < 6; kc++) {
            int idx = kv * 6 + kc;
            if (idx + 1 < 12) {
                int gn = idx + 1, kvn = gn / 6, kcn = gn - kvn * 6;
                __half* Db = ((idx + 1) & 1) ? (smA + 30720) : smB;
#pragma unroll
                for (int i = 0; i < 3; i++)
                    cpa16(Db + a16 + 2560 * i,
                          w_kvh + (size_t)kvn * 36864 + (size_t)(r16 + 64 * i) * 192 + kcn * 32 + q8);
                cp_commit();
            }
            const __half* Bb = (idx & 1) ? (smA + 30720) : smB;
#pragma unroll
            for (int kk = 0; kk < 32; kk += 16) {
                unsigned af[2][4], bbf[3][4];
                ldsm4(af[0], smA + kc * 2560 + wr * 40 + kk + aoff);
                ldsm4(af[1], smA + kc * 2560 + (wr + 16) * 40 + kk + aoff);
#pragma unroll
                for (int p = 0; p < 3; p++)
                    ldsm4(bbf[p], Bb + (wc + 16 * p) * 40 + kk + boff);
#pragma unroll
                for (int m2 = 0; m2 < 2; m2++)
#pragma unroll
                    for (int ni = 0; ni < 6; ni++)
                        mma16(acc[m2][ni], af[m2], bbf[ni >> 1][(ni & 1) * 2], bbf[ni >> 1][(ni & 1) * 2 + 1]);
            }
            cp_wait0();
            __syncthreads();
        }
#pragma unroll
        for (int m2 = 0; m2 < 2; m2++)
#pragma unroll
            for (int ni = 0; ni < 6; ni++) {
                int c = wc + 8 * ni + 2 * tg;
                int h = c >> 5, d = c & 31;
                float2 bv = *(const float2*)(kv_b + kv * 192 + c);
                int row = wr + 16 * m2 + g;
                if (kv == 0) {
                    *(__half2*)(Kh + h * 2560 + row * 40 + d) =
                        __floats2half2_rn(acc[m2][ni][0] + bv.x, acc[m2][ni][1] + bv.y);
                    *(__half2*)(Kh + h * 2560 + (row + 8) * 40 + d) =
                        __floats2half2_rn(acc[m2][ni][2] + bv.x, acc[m2][ni][3] + bv.y);
                } else {
                    __half* vb = Vt + h * 2304 + d * 72;
                    vb[row]          = __float2half_rn(acc[m2][ni][0] + bv.x);
                    vb[72 + row]     = __float2half_rn(acc[m2][ni][1] + bv.y);
                    vb[row + 8]      = __float2half_rn(acc[m2][ni][2] + bv.x);
                    vb[72 + row + 8] = __float2half_rn(acc[m2][ni][3] + bv.y);
                }
            }
    }
    __syncthreads();

    // ---------- attention ----------
    int i0 = 16 * mi + g;
    int w10 = win & 1023;
    bool eh = ((w10 >> 5) == 31), ew = ((w10 & 31) == 31);
    bool edge = eh || ew;
    int ri0 = 0, ri1 = 0, rj0a[8], rj1a[8];
    if (edge) {
        auto region = [&](int n) {
            int a = eh ? (((n >> 3) >= 4) ? 2 : 1) : 0;
            int b = ew ? (((n & 7)  >= 4) ? 2 : 1) : 0;
            return a * 3 + b;
        };
        ri0 = region(i0); ri1 = region(i0 + 8);
#pragma unroll
        for (int ni = 0; ni < 8; ni++) {
            int j0 = 8 * ni + 2 * tg;
            rj0a[ni] = region(j0);
            rj1a[ni] = region(j0 + 1);
        }
    }

#pragma unroll 1
    for (int t = 0; t < 3; t++) {
        int h = 2 * t + hp;
        float s[8][4];
#pragma unroll
        for (int ni = 0; ni < 8; ni++)
#pragma unroll
            for (int e = 0; e < 4; e++) s[ni][e] = 0.f;
        const __half* Khh = Kh + h * 2560;
#pragma unroll
        for (int p = 0; p < 4; p++) {
            unsigned kb0[4], kb1[4];
            ldsm4(kb0, Khh + (16 * p) * 40 + boff);
            ldsm4(kb1, Khh + (16 * p) * 40 + 16 + boff);
            mma16(s[2*p],     aq[t][0], kb0[0], kb0[1]);
            mma16(s[2*p],     aq[t][1], kb1[0], kb1[1]);
            mma16(s[2*p + 1], aq[t][0], kb0[2], kb0[3]);
            mma16(s[2*p + 1], aq[t][1], kb1[2], kb1[3]);
        }
        const __half* bb0 = g_biash + (h * 64 + i0) * 64;
#pragma unroll
        for (int ni = 0; ni < 8; ni++) {
            int j0 = 8 * ni + 2 * tg;
            float2 f0 = __half22float2(*(const __half2*)(bb0 + j0));
            float2 f1 = __half22float2(*(const __half2*)(bb0 + 512 + j0));
            s[ni][0] += f0.x; s[ni][1] += f0.y;
            s[ni][2] += f1.x; s[ni][3] += f1.y;
        }
        if (edge) {
#pragma unroll
            for (int ni = 0; ni < 8; ni++) {
                if (rj0a[ni] != ri0) s[ni][0] -= 100.f;
                if (rj1a[ni] != ri0) s[ni][1] -= 100.f;
                if (rj0a[ni] != ri1) s[ni][2] -= 100.f;
                if (rj1a[ni] != ri1) s[ni][3] -= 100.f;
            }
        }
        float m0 = -1e30f, m1 = -1e30f;
#pragma unroll
        for (int ni = 0; ni < 8; ni++) {
            m0 = fmaxf(m0, fmaxf(s[ni][0], s[ni][1]));
            m1 = fmaxf(m1, fmaxf(s[ni][2], s[ni][3]));
        }
        m0 = fmaxf(m0, __shfl_xor_sync(0xffffffffu, m0, 1));
        m0 = fmaxf(m0, __shfl_xor_sync(0xffffffffu, m0, 2));
        m1 = fmaxf(m1, __shfl_xor_sync(0xffffffffu, m1, 1));
        m1 = fmaxf(m1, __shfl_xor_sync(0xffffffffu, m1, 2));
        float s0 = 0.f, s1 = 0.f;
#pragma unroll
        for (int ni = 0; ni < 8; ni++) {
            s[ni][0] = __expf(s[ni][0] - m0); s0 += s[ni][0];
            s[ni][1] = __expf(s[ni][1] - m0); s0 += s[ni][1];
            s[ni][2] = __expf(s[ni][2] - m1); s1 += s[ni][2];
            s[ni][3] = __expf(s[ni][3] - m1); s1 += s[ni][3];
        }
        s0 += __shfl_xor_sync(0xffffffffu, s0, 1);
        s0 += __shfl_xor_sync(0xffffffffu, s0, 2);
        s1 += __shfl_xor_sync(0xffffffffu, s1, 1);
        s1 += __shfl_xor_sync(0xffffffffu, s1, 2);
        float inv0 = 1.f / s0, inv1 = 1.f / s1;
        unsigned pv[4][4];
#pragma unroll
        for (int js = 0; js < 4; js++) {
            pv[js][0] = h2u(__floats2half2_rn(s[2*js][0]   * inv0, s[2*js][1]   * inv0));
            pv[js][1] = h2u(__floats2half2_rn(s[2*js][2]   * inv1, s[2*js][3]   * inv1));
            pv[js][2] = h2u(__floats2half2_rn(s[2*js+1][0] * inv0, s[2*js+1][1] * inv0));
            pv[js][3] = h2u(__floats2half2_rn(s[2*js+1][2] * inv1, s[2*js+1][3] * inv1));
        }
        float o[4][4];
#pragma unroll
        for (int nd = 0; nd < 4; nd++)
#pragma unroll
            for (int e = 0; e < 4; e++) o[nd][e] = 0.f;
        const __half* Vth = Vt + h * 2304;
#pragma unroll
        for (int p = 0; p < 2; p++)
#pragma unroll
            for (int js = 0; js < 4; js++) {
                unsigned vb[4];
                ldsm4(vb, Vth + (16 * p) * 72 + 16 * js + voff);
                mma16(o[2*p],     pv[js], vb[0], vb[1]);
                mma16(o[2*p + 1], pv[js], vb[2], vb[3]);
            }
#pragma unroll
        for (int nd = 0; nd < 4; nd++) {
            int d0 = 8 * nd + 2 * tg;
            *(__half2*)(smA + h * 2560 + i0 * 40 + d0) =
                __floats2half2_rn(o[nd][0], o[nd][1]);
            *(__half2*)(smA + h * 2560 + (i0 + 8) * 40 + d0) =
                __floats2half2_rn(o[nd][2], o[nd][3]);
        }
    }

    // ---------- fused proj+merge GEMM ----------
    __syncthreads();   // Kh reads retired before Wc cpa into smB2(=Kh)
#pragma unroll
    for (int i = 0; i < 3; i++)
        cpa16(smB2 + a16 + 2560 * i, w_ch + (size_t)(r16 + 64 * i) * 192 + q8);
    cp_commit();
    cp_wait0();
    __syncthreads();

    {
        float acc[2][6][4];
#pragma unroll
        for (int a = 0; a < 2; a++)
#pragma unroll
            for (int b_ = 0; b_ < 6; b_++)
#pragma unroll
                for (int e = 0; e < 4; e++) acc[a][b_][e] = 0.f;

#pragma unroll 1
        for (int kc = 0; kc < 6; kc++) {
            if (kc + 1 < 6) {
#pragma unroll
                for (int i = 0; i < 3; i++)
                    cpa16(smB2 + ((kc + 1) & 1) * 7680 + a16 + 2560 * i,
                          w_ch + (size_t)(r16 + 64 * i) * 192 + (kc + 1) * 32 + q8);
                cp_commit();
            }
            const __half* Ab = smA + kc * 2560;
            const __half* Bb = smB2 + (kc & 1) * 7680;
#pragma unroll
            for (int kk = 0; kk < 32; kk += 16) {
                unsigned af[2][4], bbf[3][4];
                ldsm4(af[0], Ab + wr * 40 + kk + aoff);
                ldsm4(af[1], Ab + (wr + 16) * 40 + kk + aoff);
#pragma unroll
                for (int p = 0; p < 3; p++)
                    ldsm4(bbf[p], Bb + (wc + 16 * p) * 40 + kk + boff);
#pragma unroll
                for (int m2 = 0; m2 < 2; m2++)
#pragma unroll
                    for (int ni = 0; ni < 6; ni++)
                        mma16(acc[m2][ni], af[m2], bbf[ni >> 1][(ni & 1) * 2], bbf[ni >> 1][(ni & 1) * 2 + 1]);
            }
            cp_wait0();
            __syncthreads();
        }

#pragma unroll
        for (int m2 = 0; m2 < 2; m2++)
#pragma unroll
            for (int ni = 0; ni < 6; ni++) {
                int row = wr + 16 * m2 + g;
                int col = wc + 8 * ni + 2 * tg;
                St[row * 200 + col]           = acc[m2][ni][0];
                St[row * 200 + col + 1]       = acc[m2][ni][1];
                St[(row + 8) * 200 + col]     = acc[m2][ni][2];
                St[(row + 8) * 200 + col + 1] = acc[m2][ni][3];
            }
    }
    __syncthreads();

    // ---------- LN1 + shortcut -> x1h into smA ----------
    int wp = tid >> 5, l = tid & 31;
#pragma unroll 1
    for (int rr = 0; rr < 8; rr++) {
        int n = wp * 8 + rr;
        float vv[6]; float su = 0.f;
#pragma unroll
        for (int u = 0; u < 6; u++) {
            int c = l + 32 * u;
            vv[u] = St[n * 200 + c] + g_bc[c];
            su += vv[u];
        }
        su = warp_sum(su);
        float mean = su * (1.f / 192.f);
        float sq = 0.f;
#pragma unroll
        for (int u = 0; u < 6; u++) { float d = vv[u] - mean; sq += d * d; }
        sq = warp_sum(sq);
        float rstd = rsqrtf(sq * (1.f / 192.f) + 1e-5f);
#pragma unroll
        for (int u = 0; u < 6; u++) {
            int c = l + 32 * u;
            float y = (vv[u] - mean) * rstd * n1g[c] + n1b[c]
                      + __half2float(xsrc[(size_t)n * 192 + c]);
            smA[u * 2560 + n * 40 + l] = __float2half_rn(y);
        }
    }
    __syncthreads();   // St reads retired before smB1m (aliases St) is written
#pragma unroll
    for (int i = 0; i < 3; i++)
        cpa8(smB1m + stsO + 1280 * i, w_f1h + (size_t)(r0 + 32 * i) * 192 + c4);
    cp_commit();
    cp_wait0();
    __syncthreads();

    // ---------- MLP: fc1 + GELU + fc2 ----------
    float acc2[2][6][4];
#pragma unroll
    for (int a = 0; a < 2; a++)
#pragma unroll
        for (int b_ = 0; b_ < 6; b_++)
#pragma unroll
            for (int cc = 0; cc < 4; cc++) acc2[a][b_][cc] = 0.f;

#pragma unroll 1
    for (int oc = 0; oc < 8; oc++) {
        const __half* W1 = w_f1h + (size_t)(oc * 96) * 192;
        const __half* W2 = w_f2h;

        float acc1[2][3][4];
#pragma unroll
        for (int a = 0; a < 2; a++)
#pragma unroll
            for (int b_ = 0; b_ < 3; b_++)
#pragma unroll
                for (int cc = 0; cc < 4; cc++) acc1[a][b_][cc] = 0.f;

#pragma unroll 1
        for (int kc = 0; kc < 6; kc++) {
            if (kc + 1 < 6) {
#pragma unroll
                for (int i = 0; i < 3; i++)
                    cpa8(smB1m + ((kc + 1) & 1) * 3840 + stsO + 1280 * i,
                         W1 + (size_t)(r0 + 32 * i) * 192 + (kc + 1) * 32 + c4);
                cp_commit();
            } else {
                // prefetch W2 oc chunk0 into smB2m buf0 (no readers of smB2m during fc1)
#pragma unroll
                for (int i = 0; i < 3; i++)
                    cpa16(smB2m + a16 + 2560 * i,
                          W2 + (size_t)(r16 + 64 * i) * 768 + oc * 96 + q8);
                cp_commit();
            }
            const __half* Ab = smA + kc * 2560;
            const __half* Bb = smB1m + (kc & 1) * 3840;
#pragma unroll
            for (int kk = 0; kk < 32; kk += 16) {
                unsigned af[2][4], b1r[4], b1s[2];
                ldsm4(af[0], Ab + wr * 40 + kk + aoff);
                ldsm4(af[1], Ab + (wr + 16) * 40 + kk + aoff);
                ldsm4(b1r, Bb + wc1 * 40 + kk + boff);
                ldsm2(b1s, Bb + (wc1 + 16) * 40 + kk + b2off);
#pragma unroll
                for (int m2 = 0; m2 < 2; m2++) {
                    mma16(acc1[m2][0], af[m2], b1r[0], b1r[1]);
                    mma16(acc1[m2][1], af[m2], b1r[2], b1r[3]);
                    mma16(acc1[m2][2], af[m2], b1s[0], b1s[1]);
                }
            }
            cp_wait0();
            __syncthreads();
        }

        // GELU -> smHm (W2 chunk0 already resident in smB2m buf0)
#pragma unroll
        for (int m2 = 0; m2 < 2; m2++)
#pragma unroll
            for (int ni = 0; ni < 3; ni++) {
                int row = wr + 16 * m2 + g;
                int col = wc1 + 8 * ni + 2 * tg;
                float2 bv = *(const float2*)(b1h + oc * 96 + col);
                __half* hp0 = smHm + (col >> 5) * 2560 + row * 40 + (col & 31);
                *(__half2*)hp0 = __floats2half2_rn(
                    gelu_f(acc1[m2][ni][0] + bv.x), gelu_f(acc1[m2][ni][1] + bv.y));
                *(__half2*)(hp0 + 320) = __floats2half2_rn(
                    gelu_f(acc1[m2][ni][2] + bv.x), gelu_f(acc1[m2][ni][3] + bv.y));
            }
        __syncthreads();

#pragma unroll 1
        for (int kc = 0; kc < 3; kc++) {
            bool w1pre = (kc == 2) && (oc + 1 < 8);
            if (kc + 1 < 3) {
#pragma unroll
                for (int i = 0; i < 3; i++)
                    cpa16(smB2m + ((kc + 1) & 1) * 7680 + a16 + 2560 * i,
                          W2 + (size_t)(r16 + 64 * i) * 768 + oc * 96 + (kc + 1) * 32 + q8);
                cp_commit();
            } else if (w1pre) {
#pragma unroll
                for (int i = 0; i < 3; i++)
                    cpa8(smB1m + stsO + 1280 * i,
                         w_f1h + (size_t)((oc + 1) * 96 + r0 + 32 * i) * 192 + c4);
                cp_commit();
            }
            const __half* Ab = smHm + kc * 2560;
            const __half* Bb = smB2m + (kc & 1) * 7680;
#pragma unroll
            for (int kk = 0; kk < 32; kk += 16) {
                unsigned af[2][4], bbf[3][4];
                ldsm4(af[0], Ab + wr * 40 + kk + aoff);
                ldsm4(af[1], Ab + (wr + 16) * 40 + kk + aoff);
#pragma unroll
                for (int p = 0; p < 3; p++)
                    ldsm4(bbf[p], Bb + (wc + 16 * p) * 40 + kk + boff);
#pragma unroll
                for (int m2 = 0; m2 < 2; m2++)
#pragma unroll
                    for (int ni = 0; ni < 6; ni++)
                        mma16(acc2[m2][ni], af[m2], bbf[ni >> 1][(ni & 1) * 2], bbf[ni >> 1][(ni & 1) * 2 + 1]);
            }
            cp_wait0();
            __syncthreads();
        }
    }

    // ---------- final: bias + LN2 + residual(x1h) + pixel scatter ----------
#pragma unroll
    for (int m2 = 0; m2 < 2; m2++)
#pragma unroll
        for (int ni = 0; ni < 6; ni++) {
            int row = wr + 16 * m2 + g;
            int col = wc + 8 * ni + 2 * tg;
            St[row * 200 + col]           = acc2[m2][ni][0];
            St[row * 200 + col + 1]       = acc2[m2][ni][1];
            St[(row + 8) * 200 + col]     = acc2[m2][ni][2];
            St[(row + 8) * 200 + col + 1] = acc2[m2][ni][3];
        }
    __syncthreads();
#pragma unroll 1
    for (int rr = 0; rr < 8; rr++) {
        int n = wp * 8 + rr;
        int hpx = (wh * 8 + (n >> 3) + 4) & 255;
        int wpx = (ww * 8 + (n & 7) + 4) & 255;
        size_t row = ((size_t)bI * HWd + hpx * Wdim + wpx) * Cd;
        float vv[6]; float su = 0.f;
#pragma unroll
        for (int u = 0; u < 6; u++) {
            int c = l + 32 * u;
            vv[u] = St[n * 200 + c] + b2[c];
            su += vv[u];
        }
        su = warp_sum(su);
        float mean = su * (1.f / 192.f);
        float sq = 0.f;
#pragma unroll
        for (int u = 0; u < 6; u++) { float d = vv[u] - mean; sq += d * d; }
        sq = warp_sum(sq);
        float rstd = rsqrtf(sq * (1.f / 192.f) + 1e-5f);
#pragma unroll
        for (int u = 0; u < 6; u++) {
            int c = l + 32 * u;
            float x1v = __half2float(smA[u * 2560 + n * 40 + l]);
            out[row + c] = x1v + (vv[u] - mean) * rstd * g2[c] + bb2[c];
        }
    }
}

// ======================= host =======================
extern "C" void kernel_launch(void* const* d_in, const int* in_sizes, int n_in,
                              void* d_out, int out_size)
{
    const float* x    = (const float*)d_in[0];
    const float* feat = (const float*)d_in[1];
    const int*   ridx = (const int*)  d_in[3];
    const float* rtab = (const float*)d_in[4];
    const float* q_w  = (const float*)d_in[5];
    const float* q_b  = (const float*)d_in[6];
    const float* kv_w = (const float*)d_in[7];
    const float* kv_b = (const float*)d_in[8];
    const float* p_w  = (const float*)d_in[9];
    const float* p_b  = (const float*)d_in[10];
    const float* m_w  = (const float*)d_in[11];
    const float* n1g  = (const float*)d_in[12];
    const float* n1b  = (const float*)d_in[13];
    const float* n2g  = (const float*)d_in[14];
    const float* n2b  = (const float*)d_in[15];
    const float* f1w  = (const float*)d_in[16];
    const float* f1b  = (const float*)d_in[17];
    const float* f2w  = (const float*)d_in[18];
    const float* f2b  = (const float*)d_in[19];
    float* out = (float*)d_out;

    const int smMega = 52224 * 2;                        // 104448
    cudaFuncSetAttribute(k_mega, cudaFuncAttributeMaxDynamicSharedMemorySize, smMega);

    k_prep<<<1824, 256>>>(q_w, kv_w, f1w, f2w, m_w, p_w, p_b, ridx, rtab);  // 0
    k_transpose<<<dim3(3, 2048, 8), 256>>>(x, feat);                        // 1
    k_mega <<<NWINd, 256, smMega>>>(q_b, kv_b, n1g, n1b, f1b, f2b, n2g, n2b, out);  // 2
}

// round 16
// speedup vs baseline: 1.2306x; 1.0275x over previous
#include <cuda_runtime.h>
#include <cuda_fp16.h>
#include <math.h>
#include <stdint.h>

#define Hd    256
#define Wdim  256
#define HWd   65536
#define Cd    192
#define Bd    4
#define NHd   6
#define HDd   32
#define NWINd 4096
#define MTOKd 262144
#define HIDd  768
#define QSCALE 0.17677669529663687f

// -------- scratch --------
__device__ __half g_xth [(size_t)MTOKd * Cd];
__device__ __half g_fth [(size_t)MTOKd * Cd];
__device__ __half g_biash[NHd * 64 * 64];
__device__ __half w_qh [36864];
__device__ __half w_kvh[73728];
__device__ __half w_ch [36864];
__device__ float  g_bc [192];
__device__ __half w_f1h[147456];
__device__ __half w_f2h[147456];

__device__ __forceinline__ float warp_sum(float v) {
#pragma unroll
    for (int o = 16; o; o >>= 1) v += __shfl_xor_sync(0xffffffffu, v, o);
    return v;
}
__device__ __forceinline__ unsigned h2u(__half2 h) {
    return *reinterpret_cast<unsigned*>(&h);
}
__device__ __forceinline__ float gelu_f(float v) {
    return 0.5f * v * (1.f + erff(v * 0.70710678118654752f));
}
__device__ __forceinline__ void mma16(float* c, const unsigned* a, unsigned b0, unsigned b1) {
    asm volatile(
        "mma.sync.aligned.m16n8k16.row.col.f32.f16.f16.f32 "
        "{%0,%1,%2,%3}, {%4,%5,%6,%7}, {%8,%9}, {%0,%1,%2,%3};"
        : "+f"(c[0]), "+f"(c[1]), "+f"(c[2]), "+f"(c[3])
        : "r"(a[0]), "r"(a[1]), "r"(a[2]), "r"(a[3]), "r"(b0), "r"(b1));
}
__device__ __forceinline__ void ldsm4(unsigned* r, const __half* p) {
    uint32_t a = (uint32_t)__cvta_generic_to_shared(p);
    asm volatile("ldmatrix.sync.aligned.m8n8.x4.shared.b16 {%0,%1,%2,%3}, [%4];"
                 : "=r"(r[0]), "=r"(r[1]), "=r"(r[2]), "=r"(r[3]) : "r"(a));
}
__device__ __forceinline__ void ldsm2(unsigned* r, const __half* p) {
    uint32_t a = (uint32_t)__cvta_generic_to_shared(p);
    asm volatile("ldmatrix.sync.aligned.m8n8.x2.shared.b16 {%0,%1}, [%2];"
                 : "=r"(r[0]), "=r"(r[1]) : "r"(a));
}
__device__ __forceinline__ void cpa16(__half* dst, const __half* src) {
    uint32_t d = (uint32_t)__cvta_generic_to_shared(dst);
    asm volatile("cp.async.cg.shared.global [%0], [%1], 16;" :: "r"(d), "l"(src));
}
__device__ __forceinline__ void cpa8(__half* dst, const __half* src) {
    uint32_t d = (uint32_t)__cvta_generic_to_shared(dst);
    asm volatile("cp.async.ca.shared.global [%0], [%1], 8;" :: "r"(d), "l"(src));
}
__device__ __forceinline__ void cp_commit() {
    asm volatile("cp.async.commit_group;" ::: "memory");
}
__device__ __forceinline__ void cp_wait0() {
    asm volatile("cp.async.wait_group 0;" ::: "memory");
}

// ======================= K0: merged prep + transpose =======================
// blocks [0,1824): weight cvt / wcomb / bias    blocks [1824, 1824+49152): transpose
__global__ void k_pre(
    const float* __restrict__ x, const float* __restrict__ feat,
    const float* __restrict__ qw, const float* __restrict__ kvw,
    const float* __restrict__ f1w, const float* __restrict__ f2w,
    const float* __restrict__ mw, const float* __restrict__ pw,
    const float* __restrict__ pb,
    const int* __restrict__ relidx, const float* __restrict__ table)
{
    __shared__ float t[64][33];
    int bid = blockIdx.x;
    if (bid < 1584) {
        int i = bid * 256 + threadIdx.x;
        if (i < 36864)        w_qh [i]          = __float2half_rn(qw[i] * QSCALE);
        else if (i < 110592)  w_kvh[i - 36864]  = __float2half_rn(kvw[i - 36864]);
        else if (i < 258048)  w_f1h[i - 110592] = __float2half_rn(f1w[i - 110592]);
        else if (i < 405504)  w_f2h[i - 258048] = __float2half_rn(f2w[i - 258048]);
        return;
    }
    if (bid < 1728) {
        int e = (bid - 1584) * 256 + threadIdx.x;
        if (e < 36864) {
            int i = e / 192, j = e - (e / 192) * 192;
            float acc = 0.f;
            for (int k = 0; k < 192; k++) acc += mw[i * 192 + k] * pw[k * 192 + j];
            w_ch[e] = __float2half_rn(acc);
        }
        if (e < 192) {
            float acc = 0.f;
            for (int k = 0; k < 192; k++) acc += mw[e * 192 + k] * pb[k];
            g_bc[e] = acc;
        }
        return;
    }
    if (bid < 1824) {
        int idx = (bid - 1728) * 256 + threadIdx.x;
        if (idx < NHd * 4096) {
            int h = idx >> 12, r = idx & 4095;
            g_biash[idx] = __float2half_rn(table[relidx[r] * NHd + h]);
        }
        return;
    }
    // ---- transpose: tile 64 channels x 32 pixels ----
    int tb = bid - 1824;            // 0 .. 49151  (3 cx * 2048 py * 8 z)
    int z  = tb / 6144;
    int rem = tb - z * 6144;
    int cx = rem % 3, py = rem / 3;
    int b = z & 3, which = z >> 2;
    int c0 = cx << 6;
    int p0 = py << 5;
    const float* src = (which ? feat : x) + (size_t)b * Cd * HWd;
    int tx = threadIdx.x & 31, ty = threadIdx.x >> 5;
#pragma unroll
    for (int j = 0; j < 8; j++)
        t[ty + 8 * j][tx] = src[(size_t)(c0 + ty + 8 * j) * HWd + p0 + tx];
    __syncthreads();
    int p = threadIdx.x >> 3, cg = threadIdx.x & 7;
    int pix = p0 + p;
    int h = pix >> 8, wv = pix & 255;
    int h2 = (h - 4) & 255, w2 = (wv - 4) & 255;
    int tok = ((((h2 >> 3) << 5) + (w2 >> 3)) << 6) + ((h2 & 7) << 3) + (w2 & 7);
    __half hv[8];
#pragma unroll
    for (int e = 0; e < 8; e++) hv[e] = __float2half_rn(t[8 * cg + e][p]);
    __half* dh = (which ? g_fth : g_xth) + (size_t)b * HWd * Cd;
    *(uint4*)(dh + (size_t)tok * Cd + c0 + 8 * cg) = *(uint4*)hv;
}

// ======================= MEGA kernel =======================
// smem halves (52224): smA [0,15360) | Kh [15360,30720) | Vt [30720,44544) | smB [44544,52224)
__global__ void __launch_bounds__(256, 2) k_mega(
    const float* __restrict__ q_b, const float* __restrict__ kv_b,
    const float* __restrict__ n1g, const float* __restrict__ n1b,
    const float* __restrict__ b1h, const float* __restrict__ b2,
    const float* __restrict__ g2, const float* __restrict__ bb2,
    float* __restrict__ out)
{
    extern __shared__ float smf[];
    __half* smA = (__half*)smf;
    __half* Kh  = smA + 15360;
    __half* Vt  = smA + 30720;
    __half* smB = smA + 44544;
    __half* QB  = Kh;
    __half* smB2 = Kh;
    float*  St  = smf + 7680;
    __half* smB1m = smA + 15360;
    __half* smHm  = smA + 23040;
    __half* smB2m = smA + 30720;
    int win = blockIdx.x;
    int tid = threadIdx.x;
    int lane = tid & 31, w = tid >> 5;
    int g = lane >> 2, tg = lane & 3;
    int mi = w & 3, hp = w >> 2;
    const int r0 = tid >> 3, c4 = 4 * (tid & 7);
    const int stsO = r0 * 40 + c4;
    const int r16 = tid >> 2, q8 = 8 * (tid & 3);
    const int a16 = r16 * 40 + q8;
    const int wr = (w & 1) * 32, wc = (w >> 1) * 48;
    const int wc1 = (w >> 1) * 24;

    const int aoff  = (lane & 15) * 40 + (lane >> 4) * 8;
    const int boff  = ((lane & 7) + ((lane >> 4) & 1) * 8) * 40 + ((lane >> 3) & 1) * 8;
    const int b2off = (lane & 7) * 40 + ((lane >> 3) & 1) * 8;
    const int voff  = ((lane & 7) + ((lane >> 4) & 1) * 8) * 72 + ((lane >> 3) & 1) * 8;

    int bI = win >> 10, wh = (win >> 5) & 31, ww = win & 31;

    // ---------- async load xw + Wq chunk0 ----------
    const __half* xsrc = g_xth + (size_t)win * 64 * 192;
#pragma unroll
    for (int c = 0; c < 6; c++)
        cpa16(smA + c * 2560 + a16, xsrc + (size_t)r16 * 192 + c * 32 + q8);
#pragma unroll
    for (int i = 0; i < 3; i++)
        cpa16(QB + a16 + 2560 * i, w_qh + (size_t)(r16 + 64 * i) * 192 + q8);
    cp_commit();
    cp_wait0();
    __syncthreads();

    // ---------- Q GEMM ----------
    float qacc[3][4][4];
#pragma unroll
    for (int t = 0; t < 3; t++)
#pragma unroll
        for (int nq = 0; nq < 4; nq++)
#pragma unroll
            for (int e = 0; e < 4; e++) qacc[t][nq][e] = 0.f;
#pragma unroll 1
    for (int kc = 0; kc < 6; kc++) {
        if (kc + 1 < 6) {
#pragma unroll
            for (int i = 0; i < 3; i++)
                cpa16(QB + ((kc + 1) & 1) * 7680 + a16 + 2560 * i,
                      w_qh + (size_t)(r16 + 64 * i) * 192 + (kc + 1) * 32 + q8);
            cp_commit();
        }
        const __half* Bb = QB + (kc & 1) * 7680;
#pragma unroll
        for (int kk = 0; kk < 32; kk += 16) {
            unsigned af[4];
            ldsm4(af, smA + kc * 2560 + 16 * mi * 40 + kk + aoff);
#pragma unroll
            for (int t = 0; t < 3; t++) {
                unsigned bq0[4], bq1[4];
                ldsm4(bq0, Bb + (32 * (2 * t + hp)) * 40 + kk + boff);
                ldsm4(bq1, Bb + (32 * (2 * t + hp) + 16) * 40 + kk + boff);
                mma16(qacc[t][0], af, bq0[0], bq0[1]);
                mma16(qacc[t][1], af, bq0[2], bq0[3]);
                mma16(qacc[t][2], af, bq1[0], bq1[1]);
                mma16(qacc[t][3], af, bq1[2], bq1[3]);
            }
        }
        cp_wait0();
        __syncthreads();
    }

    // ---------- async load fw + Wk chunk0; repack Q meanwhile ----------
    const __half* fsrc = g_fth + (size_t)win * 64 * 192;
#pragma unroll
    for (int c = 0; c < 6; c++)
        cpa16(smA + c * 2560 + a16, fsrc + (size_t)r16 * 192 + c * 32 + q8);
#pragma unroll
    for (int i = 0; i < 3; i++)
        cpa16(smB + a16 + 2560 * i, w_kvh + (size_t)(r16 + 64 * i) * 192 + q8);
    cp_commit();

    unsigned aq[3][2][4];
#pragma unroll
    for (int t = 0; t < 3; t++) {
        int h = 2 * t + hp;
#pragma unroll
        for (int ks = 0; ks < 2; ks++) {
            float2 b0 = *(const float2*)(q_b + 32 * h + 16 * ks + 2 * tg);
            float2 b1 = *(const float2*)(q_b + 32 * h + 16 * ks + 8 + 2 * tg);
            b0.x *= QSCALE; b0.y *= QSCALE; b1.x *= QSCALE; b1.y *= QSCALE;
            aq[t][ks][0] = h2u(__floats2half2_rn(qacc[t][2*ks][0] + b0.x, qacc[t][2*ks][1] + b0.y));
            aq[t][ks][1] = h2u(__floats2half2_rn(qacc[t][2*ks][2] + b0.x, qacc[t][2*ks][3] + b0.y));
            aq[t][ks][2] = h2u(__floats2half2_rn(qacc[t][2*ks+1][0] + b1.x, qacc[t][2*ks+1][1] + b1.y));
            aq[t][ks][3] = h2u(__floats2half2_rn(qacc[t][2*ks+1][2] + b1.x, qacc[t][2*ks+1][3] + b1.y));
        }
    }
    cp_wait0();
    __syncthreads();

    // ---------- K GEMM -> Kh, V GEMM -> Vt ----------
#pragma unroll 1
    for (int kv = 0; kv < 2; kv++) {
        float acc[2][6][4];
#pragma unroll
        for (int a = 0; a < 2; a++)
#pragma unroll
            for (int b_ = 0; b_ < 6; b_++)
#pragma unroll
                for (int e = 0; e < 4; e++) acc[a][b_][e] = 0.f;
#pragma unroll 1
        for (int kc = 0; kc < 6; kc++) {
            int idx = kv * 6 + kc;
            if (idx + 1 < 12) {
                int gn = idx + 1, kvn = gn / 6, kcn = gn - kvn * 6;
                __half* Db = ((idx + 1) & 1) ? (smA + 30720) : smB;
#pragma unroll
                for (int i = 0; i < 3; i++)
                    cpa16(Db + a16 + 2560 * i,
                          w_kvh + (size_t)kvn * 36864 + (size_t)(r16 + 64 * i) * 192 + kcn * 32 + q8);
                cp_commit();
            }
            const __half* Bb = (idx & 1) ? (smA + 30720) : smB;
#pragma unroll
            for (int kk = 0; kk < 32; kk += 16) {
                unsigned af[2][4], bbf[3][4];
                ldsm4(af[0], smA + kc * 2560 + wr * 40 + kk + aoff);
                ldsm4(af[1], smA + kc * 2560 + (wr + 16) * 40 + kk + aoff);
#pragma unroll
                for (int p = 0; p < 3; p++)
                    ldsm4(bbf[p], Bb + (wc + 16 * p) * 40 + kk + boff);
#pragma unroll
                for (int m2 = 0; m2 < 2; m2++)
#pragma unroll
                    for (int ni = 0; ni < 6; ni++)
                        mma16(acc[m2][ni], af[m2], bbf[ni >> 1][(ni & 1) * 2], bbf[ni >> 1][(ni & 1) * 2 + 1]);
            }
            cp_wait0();
            __syncthreads();
        }
#pragma unroll
        for (int m2 = 0; m2 < 2; m2++)
#pragma unroll
            for (int ni = 0; ni < 6; ni++) {
                int c = wc + 8 * ni + 2 * tg;
                int h = c >> 5, d = c & 31;
                float2 bv = *(const float2*)(kv_b + kv * 192 + c);
                int row = wr + 16 * m2 + g;
                if (kv == 0) {
                    *(__half2*)(Kh + h * 2560 + row * 40 + d) =
                        __floats2half2_rn(acc[m2][ni][0] + bv.x, acc[m2][ni][1] + bv.y);
                    *(__half2*)(Kh + h * 2560 + (row + 8) * 40 + d) =
                        __floats2half2_rn(acc[m2][ni][2] + bv.x, acc[m2][ni][3] + bv.y);
                } else {
                    __half* vb = Vt + h * 2304 + d * 72;
                    vb[row]          = __float2half_rn(acc[m2][ni][0] + bv.x);
                    vb[72 + row]     = __float2half_rn(acc[m2][ni][1] + bv.y);
                    vb[row + 8]      = __float2half_rn(acc[m2][ni][2] + bv.x);
                    vb[72 + row + 8] = __float2half_rn(acc[m2][ni][3] + bv.y);
                }
            }
    }
    __syncthreads();

    // ---------- attention ----------
    int i0 = 16 * mi + g;
    int w10 = win & 1023;
    bool eh = ((w10 >> 5) == 31), ew = ((w10 & 31) == 31);
    bool edge = eh || ew;
    int ri0 = 0, ri1 = 0, rj0a[8], rj1a[8];
    if (edge) {
        auto region = [&](int n) {
            int a = eh ? (((n >> 3) >= 4) ? 2 : 1) : 0;
            int b = ew ? (((n & 7)  >= 4) ? 2 : 1) : 0;
            return a * 3 + b;
        };
        ri0 = region(i0); ri1 = region(i0 + 8);
#pragma unroll
        for (int ni = 0; ni < 8; ni++) {
            int j0 = 8 * ni + 2 * tg;
            rj0a[ni] = region(j0);
            rj1a[ni] = region(j0 + 1);
        }
    }

#pragma unroll 1
    for (int t = 0; t < 3; t++) {
        int h = 2 * t + hp;
        float s[8][4];
#pragma unroll
        for (int ni = 0; ni < 8; ni++)
#pragma unroll
            for (int e = 0; e < 4; e++) s[ni][e] = 0.f;
        const __half* Khh = Kh + h * 2560;
#pragma unroll
        for (int p = 0; p < 4; p++) {
            unsigned kb0[4], kb1[4];
            ldsm4(kb0, Khh + (16 * p) * 40 + boff);
            ldsm4(kb1, Khh + (16 * p) * 40 + 16 + boff);
            mma16(s[2*p],     aq[t][0], kb0[0], kb0[1]);
            mma16(s[2*p],     aq[t][1], kb1[0], kb1[1]);
            mma16(s[2*p + 1], aq[t][0], kb0[2], kb0[3]);
            mma16(s[2*p + 1], aq[t][1], kb1[2], kb1[3]);
        }
        const __half* bb0 = g_biash + (h * 64 + i0) * 64;
#pragma unroll
        for (int ni = 0; ni < 8; ni++) {
            int j0 = 8 * ni + 2 * tg;
            float2 f0 = __half22float2(*(const __half2*)(bb0 + j0));
            float2 f1 = __half22float2(*(const __half2*)(bb0 + 512 + j0));
            s[ni][0] += f0.x; s[ni][1] += f0.y;
            s[ni][2] += f1.x; s[ni][3] += f1.y;
        }
        if (edge) {
#pragma unroll
            for (int ni = 0; ni < 8; ni++) {
                if (rj0a[ni] != ri0) s[ni][0] -= 100.f;
                if (rj1a[ni] != ri0) s[ni][1] -= 100.f;
                if (rj0a[ni] != ri1) s[ni][2] -= 100.f;
                if (rj1a[ni] != ri1) s[ni][3] -= 100.f;
            }
        }
        float m0 = -1e30f, m1 = -1e30f;
#pragma unroll
        for (int ni = 0; ni < 8; ni++) {
            m0 = fmaxf(m0, fmaxf(s[ni][0], s[ni][1]));
            m1 = fmaxf(m1, fmaxf(s[ni][2], s[ni][3]));
        }
        m0 = fmaxf(m0, __shfl_xor_sync(0xffffffffu, m0, 1));
        m0 = fmaxf(m0, __shfl_xor_sync(0xffffffffu, m0, 2));
        m1 = fmaxf(m1, __shfl_xor_sync(0xffffffffu, m1, 1));
        m1 = fmaxf(m1, __shfl_xor_sync(0xffffffffu, m1, 2));
        float s0 = 0.f, s1 = 0.f;
#pragma unroll
        for (int ni = 0; ni < 8; ni++) {
            s[ni][0] = __expf(s[ni][0] - m0); s0 += s[ni][0];
            s[ni][1] = __expf(s[ni][1] - m0); s0 += s[ni][1];
            s[ni][2] = __expf(s[ni][2] - m1); s1 += s[ni][2];
            s[ni][3] = __expf(s[ni][3] - m1); s1 += s[ni][3];
        }
        s0 += __shfl_xor_sync(0xffffffffu, s0, 1);
        s0 += __shfl_xor_sync(0xffffffffu, s0, 2);
        s1 += __shfl_xor_sync(0xffffffffu, s1, 1);
        s1 += __shfl_xor_sync(0xffffffffu, s1, 2);
        float inv0 = 1.f / s0, inv1 = 1.f / s1;
        unsigned pv[4][4];
#pragma unroll
        for (int js = 0; js < 4; js++) {
            pv[js][0] = h2u(__floats2half2_rn(s[2*js][0]   * inv0, s[2*js][1]   * inv0));
            pv[js][1] = h2u(__floats2half2_rn(s[2*js][2]   * inv1, s[2*js][3]   * inv1));
            pv[js][2] = h2u(__floats2half2_rn(s[2*js+1][0] * inv0, s[2*js+1][1] * inv0));
            pv[js][3] = h2u(__floats2half2_rn(s[2*js+1][2] * inv1, s[2*js+1][3] * inv1));
        }
        float o[4][4];
#pragma unroll
        for (int nd = 0; nd < 4; nd++)
#pragma unroll
            for (int e = 0; e < 4; e++) o[nd][e] = 0.f;
        const __half* Vth = Vt + h * 2304;
#pragma unroll
        for (int p = 0; p < 2; p++)
#pragma unroll
            for (int js = 0; js < 4; js++) {
                unsigned vb[4];
                ldsm4(vb, Vth + (16 * p) * 72 + 16 * js + voff);
                mma16(o[2*p],     pv[js], vb[0], vb[1]);
                mma16(o[2*p + 1], pv[js], vb[2], vb[3]);
            }
#pragma unroll
        for (int nd = 0; nd < 4; nd++) {
            int d0 = 8 * nd + 2 * tg;
            *(__half2*)(smA + h * 2560 + i0 * 40 + d0) =
                __floats2half2_rn(o[nd][0], o[nd][1]);
            *(__half2*)(smA + h * 2560 + (i0 + 8) * 40 + d0) =
                __floats2half2_rn(o[nd][2], o[nd][3]);
        }
    }

    // ---------- fused proj+merge GEMM ----------
    __syncthreads();   // Kh reads retired before Wc cpa into smB2(=Kh)
#pragma unroll
    for (int i = 0; i < 3; i++)
        cpa16(smB2 + a16 + 2560 * i, w_ch + (size_t)(r16 + 64 * i) * 192 + q8);
    cp_commit();
    cp_wait0();
    __syncthreads();

    {
        float acc[2][6][4];
#pragma unroll
        for (int a = 0; a < 2; a++)
#pragma unroll
            for (int b_ = 0; b_ < 6; b_++)
#pragma unroll
                for (int e = 0; e < 4; e++) acc[a][b_][e] = 0.f;

#pragma unroll 1
        for (int kc = 0; kc < 6; kc++) {
            if (kc + 1 < 6) {
#pragma unroll
                for (int i = 0; i < 3; i++)
                    cpa16(smB2 + ((kc + 1) & 1) * 7680 + a16 + 2560 * i,
                          w_ch + (size_t)(r16 + 64 * i) * 192 + (kc + 1) * 32 + q8);
                cp_commit();
            }
            const __half* Ab = smA + kc * 2560;
            const __half* Bb = smB2 + (kc & 1) * 7680;
#pragma unroll
            for (int kk = 0; kk < 32; kk += 16) {
                unsigned af[2][4], bbf[3][4];
                ldsm4(af[0], Ab + wr * 40 + kk + aoff);
                ldsm4(af[1], Ab + (wr + 16) * 40 + kk + aoff);
#pragma unroll
                for (int p = 0; p < 3; p++)
                    ldsm4(bbf[p], Bb + (wc + 16 * p) * 40 + kk + boff);
#pragma unroll
                for (int m2 = 0; m2 < 2; m2++)
#pragma unroll
                    for (int ni = 0; ni < 6; ni++)
                        mma16(acc[m2][ni], af[m2], bbf[ni >> 1][(ni & 1) * 2], bbf[ni >> 1][(ni & 1) * 2 + 1]);
            }
            cp_wait0();
            __syncthreads();
        }

#pragma unroll
        for (int m2 = 0; m2 < 2; m2++)
#pragma unroll
            for (int ni = 0; ni < 6; ni++) {
                int row = wr + 16 * m2 + g;
                int col = wc + 8 * ni + 2 * tg;
                St[row * 200 + col]           = acc[m2][ni][0];
                St[row * 200 + col + 1]       = acc[m2][ni][1];
                St[(row + 8) * 200 + col]     = acc[m2][ni][2];
                St[(row + 8) * 200 + col + 1] = acc[m2][ni][3];
            }
    }
    __syncthreads();

    // ---------- LN1 + shortcut -> x1h into smA ----------
    int wp = tid >> 5, l = tid & 31;
#pragma unroll 1
    for (int rr = 0; rr < 8; rr++) {
        int n = wp * 8 + rr;
        float vv[6]; float su = 0.f;
#pragma unroll
        for (int u = 0; u < 6; u++) {
            int c = l + 32 * u;
            vv[u] = St[n * 200 + c] + g_bc[c];
            su += vv[u];
        }
        su = warp_sum(su);
        float mean = su * (1.f / 192.f);
        float sq = 0.f;
#pragma unroll
        for (int u = 0; u < 6; u++) { float d = vv[u] - mean; sq += d * d; }
        sq = warp_sum(sq);
        float rstd = rsqrtf(sq * (1.f / 192.f) + 1e-5f);
#pragma unroll
        for (int u = 0; u < 6; u++) {
            int c = l + 32 * u;
            float y = (vv[u] - mean) * rstd * n1g[c] + n1b[c]
                      + __half2float(xsrc[(size_t)n * 192 + c]);
            smA[u * 2560 + n * 40 + l] = __float2half_rn(y);
        }
    }
    __syncthreads();   // St reads retired before smB1m (aliases St) is written
#pragma unroll
    for (int i = 0; i < 3; i++)
        cpa8(smB1m + stsO + 1280 * i, w_f1h + (size_t)(r0 + 32 * i) * 192 + c4);
    cp_commit();
    cp_wait0();
    __syncthreads();

    // ---------- MLP: fc1 + GELU + fc2 ----------
    float acc2[2][6][4];
#pragma unroll
    for (int a = 0; a < 2; a++)
#pragma unroll
        for (int b_ = 0; b_ < 6; b_++)
#pragma unroll
            for (int cc = 0; cc < 4; cc++) acc2[a][b_][cc] = 0.f;

#pragma unroll 1
    for (int oc = 0; oc < 8; oc++) {
        const __half* W1 = w_f1h + (size_t)(oc * 96) * 192;
        const __half* W2 = w_f2h;

        float acc1[2][3][4];
#pragma unroll
        for (int a = 0; a < 2; a++)
#pragma unroll
            for (int b_ = 0; b_ < 3; b_++)
#pragma unroll
                for (int cc = 0; cc < 4; cc++) acc1[a][b_][cc] = 0.f;

#pragma unroll 1
        for (int kc = 0; kc < 6; kc++) {
            if (kc + 1 < 6) {
#pragma unroll
                for (int i = 0; i < 3; i++)
                    cpa8(smB1m + ((kc + 1) & 1) * 3840 + stsO + 1280 * i,
                         W1 + (size_t)(r0 + 32 * i) * 192 + (kc + 1) * 32 + c4);
                cp_commit();
            } else {
#pragma unroll
                for (int i = 0; i < 3; i++)
                    cpa16(smB2m + a16 + 2560 * i,
                          W2 + (size_t)(r16 + 64 * i) * 768 + oc * 96 + q8);
                cp_commit();
            }
            const __half* Ab = smA + kc * 2560;
            const __half* Bb = smB1m + (kc & 1) * 3840;
#pragma unroll
            for (int kk = 0; kk < 32; kk += 16) {
                unsigned af[2][4], b1r[4], b1s[2];
                ldsm4(af[0], Ab + wr * 40 + kk + aoff);
                ldsm4(af[1], Ab + (wr + 16) * 40 + kk + aoff);
                ldsm4(b1r, Bb + wc1 * 40 + kk + boff);
                ldsm2(b1s, Bb + (wc1 + 16) * 40 + kk + b2off);
#pragma unroll
                for (int m2 = 0; m2 < 2; m2++) {
                    mma16(acc1[m2][0], af[m2], b1r[0], b1r[1]);
                    mma16(acc1[m2][1], af[m2], b1r[2], b1r[3]);
                    mma16(acc1[m2][2], af[m2], b1s[0], b1s[1]);
                }
            }
            cp_wait0();
            __syncthreads();
        }

        // GELU -> smHm (W2 chunk0 already resident in smB2m buf0)
#pragma unroll
        for (int m2 = 0; m2 < 2; m2++)
#pragma unroll
            for (int ni = 0; ni < 3; ni++) {
                int row = wr + 16 * m2 + g;
                int col = wc1 + 8 * ni + 2 * tg;
                float2 bv = *(const float2*)(b1h + oc * 96 + col);
                __half* hp0 = smHm + (col >> 5) * 2560 + row * 40 + (col & 31);
                *(__half2*)hp0 = __floats2half2_rn(
                    gelu_f(acc1[m2][ni][0] + bv.x), gelu_f(acc1[m2][ni][1] + bv.y));
                *(__half2*)(hp0 + 320) = __floats2half2_rn(
                    gelu_f(acc1[m2][ni][2] + bv.x), gelu_f(acc1[m2][ni][3] + bv.y));
            }
        __syncthreads();

#pragma unroll 1
        for (int kc = 0; kc < 3; kc++) {
            bool w1pre = (kc == 2) && (oc + 1 < 8);
            if (kc + 1 < 3) {
#pragma unroll
                for (int i = 0; i < 3; i++)
                    cpa16(smB2m + ((kc + 1) & 1) * 7680 + a16 + 2560 * i,
                          W2 + (size_t)(r16 + 64 * i) * 768 + oc * 96 + (kc + 1) * 32 + q8);
                cp_commit();
            } else if (w1pre) {
#pragma unroll
                for (int i = 0; i < 3; i++)
                    cpa8(smB1m + stsO + 1280 * i,
                         w_f1h + (size_t)((oc + 1) * 96 + r0 + 32 * i) * 192 + c4);
                cp_commit();
            }
            const __half* Ab = smHm + kc * 2560;
            const __half* Bb = smB2m + (kc & 1) * 7680;
#pragma unroll
            for (int kk = 0; kk < 32; kk += 16) {
                unsigned af[2][4], bbf[3][4];
                ldsm4(af[0], Ab + wr * 40 + kk + aoff);
                ldsm4(af[1], Ab + (wr + 16) * 40 + kk + aoff);
#pragma unroll
                for (int p = 0; p < 3; p++)
                    ldsm4(bbf[p], Bb + (wc + 16 * p) * 40 + kk + boff);
#pragma unroll
                for (int m2 = 0; m2 < 2; m2++)
#pragma unroll
                    for (int ni = 0; ni < 6; ni++)
                        mma16(acc2[m2][ni], af[m2], bbf[ni >> 1][(ni & 1) * 2], bbf[ni >> 1][(ni & 1) * 2 + 1]);
            }
            cp_wait0();
            __syncthreads();
        }
    }

    // ---------- final: bias + LN2 + residual(x1h) + pixel scatter ----------
#pragma unroll
    for (int m2 = 0; m2 < 2; m2++)
#pragma unroll
        for (int ni = 0; ni < 6; ni++) {
            int row = wr + 16 * m2 + g;
            int col = wc + 8 * ni + 2 * tg;
            St[row * 200 + col]           = acc2[m2][ni][0];
            St[row * 200 + col + 1]       = acc2[m2][ni][1];
            St[(row + 8) * 200 + col]     = acc2[m2][ni][2];
            St[(row + 8) * 200 + col + 1] = acc2[m2][ni][3];
        }
    __syncthreads();
#pragma unroll 1
    for (int rr = 0; rr < 8; rr++) {
        int n = wp * 8 + rr;
        int hpx = (wh * 8 + (n >> 3) + 4) & 255;
        int wpx = (ww * 8 + (n & 7) + 4) & 255;
        size_t row = ((size_t)bI * HWd + hpx * Wdim + wpx) * Cd;
        float vv[6]; float su = 0.f;
#pragma unroll
        for (int u = 0; u < 6; u++) {
            int c = l + 32 * u;
            vv[u] = St[n * 200 + c] + b2[c];
            su += vv[u];
        }
        su = warp_sum(su);
        float mean = su * (1.f / 192.f);
        float sq = 0.f;
#pragma unroll
        for (int u = 0; u < 6; u++) { float d = vv[u] - mean; sq += d * d; }
        sq = warp_sum(sq);
        float rstd = rsqrtf(sq * (1.f / 192.f) + 1e-5f);
#pragma unroll
        for (int u = 0; u < 6; u++) {
            int c = l + 32 * u;
            float x1v = __half2float(smA[u * 2560 + n * 40 + l]);
            out[row + c] = x1v + (vv[u] - mean) * rstd * g2[c] + bb2[c];
        }
    }
}

// ======================= host =======================
extern "C" void kernel_launch(void* const* d_in, const int* in_sizes, int n_in,
                              void* d_out, int out_size)
{
    const float* x    = (const float*)d_in[0];
    const float* feat = (const float*)d_in[1];
    const int*   ridx = (const int*)  d_in[3];
    const float* rtab = (const float*)d_in[4];
    const float* q_w  = (const float*)d_in[5];
    const float* q_b  = (const float*)d_in[6];
    const float* kv_w = (const float*)d_in[7];
    const float* kv_b = (const float*)d_in[8];
    const float* p_w  = (const float*)d_in[9];
    const float* p_b  = (const float*)d_in[10];
    const float* m_w  = (const float*)d_in[11];
    const float* n1g  = (const float*)d_in[12];
    const float* n1b  = (const float*)d_in[13];
    const float* n2g  = (const float*)d_in[14];
    const float* n2b  = (const float*)d_in[15];
    const float* f1w  = (const float*)d_in[16];
    const float* f1b  = (const float*)d_in[17];
    const float* f2w  = (const float*)d_in[18];
    const float* f2b  = (const float*)d_in[19];
    float* out = (float*)d_out;

    const int smMega = 52224 * 2;                        // 104448
    cudaFuncSetAttribute(k_mega, cudaFuncAttributeMaxDynamicSharedMemorySize, smMega);

    k_pre <<<1824 + 49152, 256>>>(x, feat, q_w, kv_w, f1w, f2w,
                                  m_w, p_w, p_b, ridx, rtab);               // 0
    k_mega<<<NWINd, 256, smMega>>>(q_b, kv_b, n1g, n1b, f1b, f2b, n2g, n2b, out);  // 1
}

// round 17
// speedup vs baseline: 1.2729x; 1.0344x over previous
#include <cuda_runtime.h>
#include <cuda_fp16.h>
#include <math.h>
#include <stdint.h>

#define Hd    256
#define Wdim  256
#define HWd   65536
#define Cd    192
#define Bd    4
#define NHd   6
#define HDd   32
#define NWINd 4096
#define MTOKd 262144
#define HIDd  768
#define QSCALE 0.17677669529663687f

// -------- scratch --------
__device__ __half g_xth [(size_t)MTOKd * Cd];
__device__ __half g_fth [(size_t)MTOKd * Cd];
__device__ __half g_biash[NHd * 64 * 64];
__device__ __half w_qh [36864];
__device__ __half w_kvh[73728];
__device__ __half w_ch [36864];
__device__ float  g_bc [192];
__device__ __half w_f1h[147456];
__device__ __half w_f2h[147456];

__device__ __forceinline__ unsigned h2u(__half2 h) {
    return *reinterpret_cast<unsigned*>(&h);
}
__device__ __forceinline__ float gelu_f(float v) {
    return 0.5f * v * (1.f + erff(v * 0.70710678118654752f));
}
__device__ __forceinline__ float quad_sum(float v) {
    v += __shfl_xor_sync(0xffffffffu, v, 1);
    v += __shfl_xor_sync(0xffffffffu, v, 2);
    return v;
}
__device__ __forceinline__ void mma16(float* c, const unsigned* a, unsigned b0, unsigned b1) {
    asm volatile(
        "mma.sync.aligned.m16n8k16.row.col.f32.f16.f16.f32 "
        "{%0,%1,%2,%3}, {%4,%5,%6,%7}, {%8,%9}, {%0,%1,%2,%3};"
        : "+f"(c[0]), "+f"(c[1]), "+f"(c[2]), "+f"(c[3])
        : "r"(a[0]), "r"(a[1]), "r"(a[2]), "r"(a[3]), "r"(b0), "r"(b1));
}
__device__ __forceinline__ void ldsm4(unsigned* r, const __half* p) {
    uint32_t a = (uint32_t)__cvta_generic_to_shared(p);
    asm volatile("ldmatrix.sync.aligned.m8n8.x4.shared.b16 {%0,%1,%2,%3}, [%4];"
                 : "=r"(r[0]), "=r"(r[1]), "=r"(r[2]), "=r"(r[3]) : "r"(a));
}
__device__ __forceinline__ void ldsm2(unsigned* r, const __half* p) {
    uint32_t a = (uint32_t)__cvta_generic_to_shared(p);
    asm volatile("ldmatrix.sync.aligned.m8n8.x2.shared.b16 {%0,%1}, [%2];"
                 : "=r"(r[0]), "=r"(r[1]) : "r"(a));
}
__device__ __forceinline__ void cpa16(__half* dst, const __half* src) {
    uint32_t d = (uint32_t)__cvta_generic_to_shared(dst);
    asm volatile("cp.async.cg.shared.global [%0], [%1], 16;" :: "r"(d), "l"(src));
}
__device__ __forceinline__ void cpa8(__half* dst, const __half* src) {
    uint32_t d = (uint32_t)__cvta_generic_to_shared(dst);
    asm volatile("cp.async.ca.shared.global [%0], [%1], 8;" :: "r"(d), "l"(src));
}
__device__ __forceinline__ void cp_commit() {
    asm volatile("cp.async.commit_group;" ::: "memory");
}
__device__ __forceinline__ void cp_wait0() {
    asm volatile("cp.async.wait_group 0;" ::: "memory");
}

// ======================= K0: merged prep + transpose =======================
__global__ void k_pre(
    const float* __restrict__ x, const float* __restrict__ feat,
    const float* __restrict__ qw, const float* __restrict__ kvw,
    const float* __restrict__ f1w, const float* __restrict__ f2w,
    const float* __restrict__ mw, const float* __restrict__ pw,
    const float* __restrict__ pb,
    const int* __restrict__ relidx, const float* __restrict__ table)
{
    __shared__ float t[64][33];
    int bid = blockIdx.x;
    if (bid < 1584) {
        int i = bid * 256 + threadIdx.x;
        if (i < 36864)        w_qh [i]          = __float2half_rn(qw[i] * QSCALE);
        else if (i < 110592)  w_kvh[i - 36864]  = __float2half_rn(kvw[i - 36864]);
        else if (i < 258048)  w_f1h[i - 110592] = __float2half_rn(f1w[i - 110592]);
        else if (i < 405504)  w_f2h[i - 258048] = __float2half_rn(f2w[i - 258048]);
        return;
    }
    if (bid < 1728) {
        int e = (bid - 1584) * 256 + threadIdx.x;
        if (e < 36864) {
            int i = e / 192, j = e - (e / 192) * 192;
            float acc = 0.f;
            for (int k = 0; k < 192; k++) acc += mw[i * 192 + k] * pw[k * 192 + j];
            w_ch[e] = __float2half_rn(acc);
        }
        if (e < 192) {
            float acc = 0.f;
            for (int k = 0; k < 192; k++) acc += mw[e * 192 + k] * pb[k];
            g_bc[e] = acc;
        }
        return;
    }
    if (bid < 1824) {
        int idx = (bid - 1728) * 256 + threadIdx.x;
        if (idx < NHd * 4096) {
            int h = idx >> 12, r = idx & 4095;
            g_biash[idx] = __float2half_rn(table[relidx[r] * NHd + h]);
        }
        return;
    }
    int tb = bid - 1824;
    int z  = tb / 6144;
    int rem = tb - z * 6144;
    int cx = rem % 3, py = rem / 3;
    int b = z & 3, which = z >> 2;
    int c0 = cx << 6;
    int p0 = py << 5;
    const float* src = (which ? feat : x) + (size_t)b * Cd * HWd;
    int tx = threadIdx.x & 31, ty = threadIdx.x >> 5;
#pragma unroll
    for (int j = 0; j < 8; j++)
        t[ty + 8 * j][tx] = src[(size_t)(c0 + ty + 8 * j) * HWd + p0 + tx];
    __syncthreads();
    int p = threadIdx.x >> 3, cg = threadIdx.x & 7;
    int pix = p0 + p;
    int h = pix >> 8, wv = pix & 255;
    int h2 = (h - 4) & 255, w2 = (wv - 4) & 255;
    int tok = ((((h2 >> 3) << 5) + (w2 >> 3)) << 6) + ((h2 & 7) << 3) + (w2 & 7);
    __half hv[8];
#pragma unroll
    for (int e = 0; e < 8; e++) hv[e] = __float2half_rn(t[8 * cg + e][p]);
    __half* dh = (which ? g_fth : g_xth) + (size_t)b * HWd * Cd;
    *(uint4*)(dh + (size_t)tok * Cd + c0 + 8 * cg) = *(uint4*)hv;
}

// ======================= MEGA kernel =======================
// smem halves (52224): smA [0,15360) | Kh [15360,30720) | Vt [30720,44544) | smB [44544,52224)
__global__ void __launch_bounds__(256, 2) k_mega(
    const float* __restrict__ q_b, const float* __restrict__ kv_b,
    const float* __restrict__ n1g, const float* __restrict__ n1b,
    const float* __restrict__ b1h, const float* __restrict__ b2,
    const float* __restrict__ g2, const float* __restrict__ bb2,
    float* __restrict__ out)
{
    extern __shared__ float smf[];
    __half* smA = (__half*)smf;
    __half* Kh  = smA + 15360;
    __half* Vt  = smA + 30720;
    __half* smB = smA + 44544;
    __half* QB  = Kh;
    __half* smB2 = Kh;
    float*  ps  = smf + 7680;        // LN partial sums [4][64] (dead Kh/smB1m region)
    float*  pq  = smf + 7936;        // LN partial sumsq [4][64]
    __half* smB1m = smA + 15360;
    __half* smHm  = smA + 23040;
    __half* smB2m = smA + 30720;
    int win = blockIdx.x;
    int tid = threadIdx.x;
    int lane = tid & 31, w = tid >> 5;
    int g = lane >> 2, tg = lane & 3;
    int mi = w & 3, hp = w >> 2;
    const int r0 = tid >> 3, c4 = 4 * (tid & 7);
    const int stsO = r0 * 40 + c4;
    const int r16 = tid >> 2, q8 = 8 * (tid & 3);
    const int a16 = r16 * 40 + q8;
    const int wr = (w & 1) * 32, wc = (w >> 1) * 48;
    const int wc1 = (w >> 1) * 24;
    const int cg64 = (w >> 1) * 64;

    const int aoff  = (lane & 15) * 40 + (lane >> 4) * 8;
    const int boff  = ((lane & 7) + ((lane >> 4) & 1) * 8) * 40 + ((lane >> 3) & 1) * 8;
    const int b2off = (lane & 7) * 40 + ((lane >> 3) & 1) * 8;
    const int voff  = ((lane & 7) + ((lane >> 4) & 1) * 8) * 72 + ((lane >> 3) & 1) * 8;

    int bI = win >> 10, wh = (win >> 5) & 31, ww = win & 31;

    // ---------- async load xw + Wq chunk0 ----------
    const __half* xsrc = g_xth + (size_t)win * 64 * 192;
#pragma unroll
    for (int c = 0; c < 6; c++)
        cpa16(smA + c * 2560 + a16, xsrc + (size_t)r16 * 192 + c * 32 + q8);
#pragma unroll
    for (int i = 0; i < 3; i++)
        cpa16(QB + a16 + 2560 * i, w_qh + (size_t)(r16 + 64 * i) * 192 + q8);
    cp_commit();
    cp_wait0();
    __syncthreads();

    // ---------- Q GEMM ----------
    float qacc[3][4][4];
#pragma unroll
    for (int t = 0; t < 3; t++)
#pragma unroll
        for (int nq = 0; nq < 4; nq++)
#pragma unroll
            for (int e = 0; e < 4; e++) qacc[t][nq][e] = 0.f;
#pragma unroll 1
    for (int kc = 0; kc < 6; kc++) {
        if (kc + 1 < 6) {
#pragma unroll
            for (int i = 0; i < 3; i++)
                cpa16(QB + ((kc + 1) & 1) * 7680 + a16 + 2560 * i,
                      w_qh + (size_t)(r16 + 64 * i) * 192 + (kc + 1) * 32 + q8);
            cp_commit();
        }
        const __half* Bb = QB + (kc & 1) * 7680;
#pragma unroll
        for (int kk = 0; kk < 32; kk += 16) {
            unsigned af[4];
            ldsm4(af, smA + kc * 2560 + 16 * mi * 40 + kk + aoff);
#pragma unroll
            for (int t = 0; t < 3; t++) {
                unsigned bq0[4], bq1[4];
                ldsm4(bq0, Bb + (32 * (2 * t + hp)) * 40 + kk + boff);
                ldsm4(bq1, Bb + (32 * (2 * t + hp) + 16) * 40 + kk + boff);
                mma16(qacc[t][0], af, bq0[0], bq0[1]);
                mma16(qacc[t][1], af, bq0[2], bq0[3]);
                mma16(qacc[t][2], af, bq1[0], bq1[1]);
                mma16(qacc[t][3], af, bq1[2], bq1[3]);
            }
        }
        cp_wait0();
        __syncthreads();
    }

    // ---------- async load fw + Wk chunk0; repack Q meanwhile ----------
    const __half* fsrc = g_fth + (size_t)win * 64 * 192;
#pragma unroll
    for (int c = 0; c < 6; c++)
        cpa16(smA + c * 2560 + a16, fsrc + (size_t)r16 * 192 + c * 32 + q8);
#pragma unroll
    for (int i = 0; i < 3; i++)
        cpa16(smB + a16 + 2560 * i, w_kvh + (size_t)(r16 + 64 * i) * 192 + q8);
    cp_commit();

    unsigned aq[3][2][4];
#pragma unroll
    for (int t = 0; t < 3; t++) {
        int h = 2 * t + hp;
#pragma unroll
        for (int ks = 0; ks < 2; ks++) {
            float2 b0 = *(const float2*)(q_b + 32 * h + 16 * ks + 2 * tg);
            float2 b1 = *(const float2*)(q_b + 32 * h + 16 * ks + 8 + 2 * tg);
            b0.x *= QSCALE; b0.y *= QSCALE; b1.x *= QSCALE; b1.y *= QSCALE;
            aq[t][ks][0] = h2u(__floats2half2_rn(qacc[t][2*ks][0] + b0.x, qacc[t][2*ks][1] + b0.y));
            aq[t][ks][1] = h2u(__floats2half2_rn(qacc[t][2*ks][2] + b0.x, qacc[t][2*ks][3] + b0.y));
            aq[t][ks][2] = h2u(__floats2half2_rn(qacc[t][2*ks+1][0] + b1.x, qacc[t][2*ks+1][1] + b1.y));
            aq[t][ks][3] = h2u(__floats2half2_rn(qacc[t][2*ks+1][2] + b1.x, qacc[t][2*ks+1][3] + b1.y));
        }
    }
    cp_wait0();
    __syncthreads();

    // ---------- K GEMM -> Kh, V GEMM -> Vt ----------
#pragma unroll 1
    for (int kv = 0; kv < 2; kv++) {
        float acc[2][6][4];
#pragma unroll
        for (int a = 0; a < 2; a++)
#pragma unroll
            for (int b_ = 0; b_ < 6; b_++)
#pragma unroll
                for (int e = 0; e < 4; e++) acc[a][b_][e] = 0.f;
#pragma unroll 1
        for (int kc = 0; kc < 6; kc++) {
            int idx = kv * 6 + kc;
            if (idx + 1 < 12) {
                int gn = idx + 1, kvn = gn / 6, kcn = gn - kvn * 6;
                __half* Db = ((idx + 1) & 1) ? (smA + 30720) : smB;
#pragma unroll
                for (int i = 0; i < 3; i++)
                    cpa16(Db + a16 + 2560 * i,
                          w_kvh + (size_t)kvn * 36864 + (size_t)(r16 + 64 * i) * 192 + kcn * 32 + q8);
                cp_commit();
            }
            const __half* Bb = (idx & 1) ? (smA + 30720) : smB;
#pragma unroll
            for (int kk = 0; kk < 32; kk += 16) {
                unsigned af[2][4], bbf[3][4];
                ldsm4(af[0], smA + kc * 2560 + wr * 40 + kk + aoff);
                ldsm4(af[1], smA + kc * 2560 + (wr + 16) * 40 + kk + aoff);
#pragma unroll
                for (int p = 0; p < 3; p++)
                    ldsm4(bbf[p], Bb + (wc + 16 * p) * 40 + kk + boff);
#pragma unroll
                for (int m2 = 0; m2 < 2; m2++)
#pragma unroll
                    for (int ni = 0; ni < 6; ni++)
                        mma16(acc[m2][ni], af[m2], bbf[ni >> 1][(ni & 1) * 2], bbf[ni >> 1][(ni & 1) * 2 + 1]);
            }
            cp_wait0();
            __syncthreads();
        }
#pragma unroll
        for (int m2 = 0; m2 < 2; m2++)
#pragma unroll
            for (int ni = 0; ni < 6; ni++) {
                int c = wc + 8 * ni + 2 * tg;
                int h = c >> 5, d = c & 31;
                float2 bv = *(const float2*)(kv_b + kv * 192 + c);
                int row = wr + 16 * m2 + g;
                if (kv == 0) {
                    *(__half2*)(Kh + h * 2560 + row * 40 + d) =
                        __floats2half2_rn(acc[m2][ni][0] + bv.x, acc[m2][ni][1] + bv.y);
                    *(__half2*)(Kh + h * 2560 + (row + 8) * 40 + d) =
                        __floats2half2_rn(acc[m2][ni][2] + bv.x, acc[m2][ni][3] + bv.y);
                } else {
                    __half* vb = Vt + h * 2304 + d * 72;
                    vb[row]          = __float2half_rn(acc[m2][ni][0] + bv.x);
                    vb[72 + row]     = __float2half_rn(acc[m2][ni][1] + bv.y);
                    vb[row + 8]      = __float2half_rn(acc[m2][ni][2] + bv.x);
                    vb[72 + row + 8] = __float2half_rn(acc[m2][ni][3] + bv.y);
                }
            }
    }
    __syncthreads();

    // ---------- attention ----------
    int i0 = 16 * mi + g;
    int w10 = win & 1023;
    bool eh = ((w10 >> 5) == 31), ew = ((w10 & 31) == 31);
    bool edge = eh || ew;
    int ri0 = 0, ri1 = 0, rj0a[8], rj1a[8];
    if (edge) {
        auto region = [&](int n) {
            int a = eh ? (((n >> 3) >= 4) ? 2 : 1) : 0;
            int b = ew ? (((n & 7)  >= 4) ? 2 : 1) : 0;
            return a * 3 + b;
        };
        ri0 = region(i0); ri1 = region(i0 + 8);
#pragma unroll
        for (int ni = 0; ni < 8; ni++) {
            int j0 = 8 * ni + 2 * tg;
            rj0a[ni] = region(j0);
            rj1a[ni] = region(j0 + 1);
        }
    }

#pragma unroll 1
    for (int t = 0; t < 3; t++) {
        int h = 2 * t + hp;
        float s[8][4];
#pragma unroll
        for (int ni = 0; ni < 8; ni++)
#pragma unroll
            for (int e = 0; e < 4; e++) s[ni][e] = 0.f;
        const __half* Khh = Kh + h * 2560;
#pragma unroll
        for (int p = 0; p < 4; p++) {
            unsigned kb0[4], kb1[4];
            ldsm4(kb0, Khh + (16 * p) * 40 + boff);
            ldsm4(kb1, Khh + (16 * p) * 40 + 16 + boff);
            mma16(s[2*p],     aq[t][0], kb0[0], kb0[1]);
            mma16(s[2*p],     aq[t][1], kb1[0], kb1[1]);
            mma16(s[2*p + 1], aq[t][0], kb0[2], kb0[3]);
            mma16(s[2*p + 1], aq[t][1], kb1[2], kb1[3]);
        }
        const __half* bb0 = g_biash + (h * 64 + i0) * 64;
#pragma unroll
        for (int ni = 0; ni < 8; ni++) {
            int j0 = 8 * ni + 2 * tg;
            float2 f0 = __half22float2(*(const __half2*)(bb0 + j0));
            float2 f1 = __half22float2(*(const __half2*)(bb0 + 512 + j0));
            s[ni][0] += f0.x; s[ni][1] += f0.y;
            s[ni][2] += f1.x; s[ni][3] += f1.y;
        }
        if (edge) {
#pragma unroll
            for (int ni = 0; ni < 8; ni++) {
                if (rj0a[ni] != ri0) s[ni][0] -= 100.f;
                if (rj1a[ni] != ri0) s[ni][1] -= 100.f;
                if (rj0a[ni] != ri1) s[ni][2] -= 100.f;
                if (rj1a[ni] != ri1) s[ni][3] -= 100.f;
            }
        }
        float m0 = -1e30f, m1 = -1e30f;
#pragma unroll
        for (int ni = 0; ni < 8; ni++) {
            m0 = fmaxf(m0, fmaxf(s[ni][0], s[ni][1]));
            m1 = fmaxf(m1, fmaxf(s[ni][2], s[ni][3]));
        }
        m0 = fmaxf(m0, __shfl_xor_sync(0xffffffffu, m0, 1));
        m0 = fmaxf(m0, __shfl_xor_sync(0xffffffffu, m0, 2));
        m1 = fmaxf(m1, __shfl_xor_sync(0xffffffffu, m1, 1));
        m1 = fmaxf(m1, __shfl_xor_sync(0xffffffffu, m1, 2));
        float s0 = 0.f, s1 = 0.f;
#pragma unroll
        for (int ni = 0; ni < 8; ni++) {
            s[ni][0] = __expf(s[ni][0] - m0); s0 += s[ni][0];
            s[ni][1] = __expf(s[ni][1] - m0); s0 += s[ni][1];
            s[ni][2] = __expf(s[ni][2] - m1); s1 += s[ni][2];
            s[ni][3] = __expf(s[ni][3] - m1); s1 += s[ni][3];
        }
        s0 += __shfl_xor_sync(0xffffffffu, s0, 1);
        s0 += __shfl_xor_sync(0xffffffffu, s0, 2);
        s1 += __shfl_xor_sync(0xffffffffu, s1, 1);
        s1 += __shfl_xor_sync(0xffffffffu, s1, 2);
        float inv0 = 1.f / s0, inv1 = 1.f / s1;
        unsigned pv[4][4];
#pragma unroll
        for (int js = 0; js < 4; js++) {
            pv[js][0] = h2u(__floats2half2_rn(s[2*js][0]   * inv0, s[2*js][1]   * inv0));
            pv[js][1] = h2u(__floats2half2_rn(s[2*js][2]   * inv1, s[2*js][3]   * inv1));
            pv[js][2] = h2u(__floats2half2_rn(s[2*js+1][0] * inv0, s[2*js+1][1] * inv0));
            pv[js][3] = h2u(__floats2half2_rn(s[2*js+1][2] * inv1, s[2*js+1][3] * inv1));
        }
        float o[4][4];
#pragma unroll
        for (int nd = 0; nd < 4; nd++)
#pragma unroll
            for (int e = 0; e < 4; e++) o[nd][e] = 0.f;
        const __half* Vth = Vt + h * 2304;
#pragma unroll
        for (int p = 0; p < 2; p++)
#pragma unroll
            for (int js = 0; js < 4; js++) {
                unsigned vb[4];
                ldsm4(vb, Vth + (16 * p) * 72 + 16 * js + voff);
                mma16(o[2*p],     pv[js], vb[0], vb[1]);
                mma16(o[2*p + 1], pv[js], vb[2], vb[3]);
            }
#pragma unroll
        for (int nd = 0; nd < 4; nd++) {
            int d0 = 8 * nd + 2 * tg;
            *(__half2*)(smA + h * 2560 + i0 * 40 + d0) =
                __floats2half2_rn(o[nd][0], o[nd][1]);
            *(__half2*)(smA + h * 2560 + (i0 + 8) * 40 + d0) =
                __floats2half2_rn(o[nd][2], o[nd][3]);
        }
    }

    // ---------- fused proj+merge GEMM + fragment LN1 ----------
    __syncthreads();   // Kh reads retired before Wc cpa into smB2(=Kh)
#pragma unroll
    for (int i = 0; i < 3; i++)
        cpa16(smB2 + a16 + 2560 * i, w_ch + (size_t)(r16 + 64 * i) * 192 + q8);
    cp_commit();
    cp_wait0();
    __syncthreads();

    {
        float acc[2][6][4];
#pragma unroll
        for (int a = 0; a < 2; a++)
#pragma unroll
            for (int b_ = 0; b_ < 6; b_++)
#pragma unroll
                for (int e = 0; e < 4; e++) acc[a][b_][e] = 0.f;

#pragma unroll 1
        for (int kc = 0; kc < 6; kc++) {
            if (kc + 1 < 6) {
#pragma unroll
                for (int i = 0; i < 3; i++)
                    cpa16(smB2 + ((kc + 1) & 1) * 7680 + a16 + 2560 * i,
                          w_ch + (size_t)(r16 + 64 * i) * 192 + (kc + 1) * 32 + q8);
                cp_commit();
            }
            const __half* Ab = smA + kc * 2560;
            const __half* Bb = smB2 + (kc & 1) * 7680;
#pragma unroll
            for (int kk = 0; kk < 32; kk += 16) {
                unsigned af[2][4], bbf[3][4];
                ldsm4(af[0], Ab + wr * 40 + kk + aoff);
                ldsm4(af[1], Ab + (wr + 16) * 40 + kk + aoff);
#pragma unroll
                for (int p = 0; p < 3; p++)
                    ldsm4(bbf[p], Bb + (wc + 16 * p) * 40 + kk + boff);
#pragma unroll
                for (int m2 = 0; m2 < 2; m2++)
#pragma unroll
                    for (int ni = 0; ni < 6; ni++)
                        mma16(acc[m2][ni], af[m2], bbf[ni >> 1][(ni & 1) * 2], bbf[ni >> 1][(ni & 1) * 2 + 1]);
            }
            cp_wait0();
            __syncthreads();
        }

        // bias(bc) + per-row partials
        float sm_[2][2] = {{0.f,0.f},{0.f,0.f}}, sq_[2][2] = {{0.f,0.f},{0.f,0.f}};
#pragma unroll
        for (int m2 = 0; m2 < 2; m2++)
#pragma unroll
            for (int ni = 0; ni < 6; ni++) {
                float2 bc = *(const float2*)(g_bc + wc + 8 * ni + 2 * tg);
                acc[m2][ni][0] += bc.x; acc[m2][ni][1] += bc.y;
                acc[m2][ni][2] += bc.x; acc[m2][ni][3] += bc.y;
                sm_[m2][0] += acc[m2][ni][0] + acc[m2][ni][1];
                sq_[m2][0] += acc[m2][ni][0]*acc[m2][ni][0] + acc[m2][ni][1]*acc[m2][ni][1];
                sm_[m2][1] += acc[m2][ni][2] + acc[m2][ni][3];
                sq_[m2][1] += acc[m2][ni][2]*acc[m2][ni][2] + acc[m2][ni][3]*acc[m2][ni][3];
            }
#pragma unroll
        for (int m2 = 0; m2 < 2; m2++)
#pragma unroll
            for (int hh = 0; hh < 2; hh++) {
                float sv = quad_sum(sm_[m2][hh]);
                float qv = quad_sum(sq_[m2][hh]);
                if (tg == 0) {
                    int r = wr + 16 * m2 + g + 8 * hh;
                    ps[cg64 + r] = sv;
                    pq[cg64 + r] = qv;
                }
            }
        __syncthreads();

        // apply LN1 + shortcut, store x1h frags to smA
#pragma unroll
        for (int m2 = 0; m2 < 2; m2++)
#pragma unroll
            for (int hh = 0; hh < 2; hh++) {
                int r = wr + 16 * m2 + g + 8 * hh;
                float S = ps[r] + ps[64 + r] + ps[128 + r] + ps[192 + r];
                float Q = pq[r] + pq[64 + r] + pq[128 + r] + pq[192 + r];
                float mean = S * (1.f / 192.f);
                float rstd = rsqrtf(Q * (1.f / 192.f) - mean * mean + 1e-5f);
#pragma unroll
                for (int ni = 0; ni < 6; ni++) {
                    int c = wc + 8 * ni + 2 * tg;
                    float2 gg = *(const float2*)(n1g + c);
                    float2 bb = *(const float2*)(n1b + c);
                    float2 xf = __half22float2(*(const __half2*)(xsrc + (size_t)r * 192 + c));
                    float y0 = (acc[m2][ni][2*hh]   - mean) * rstd * gg.x + bb.x + xf.x;
                    float y1 = (acc[m2][ni][2*hh+1] - mean) * rstd * gg.y + bb.y + xf.y;
                    *(__half2*)(smA + (c >> 5) * 2560 + r * 40 + (c & 31)) =
                        __floats2half2_rn(y0, y1);
                }
            }
    }
    __syncthreads();   // ps/pq reads retired before smB1m (aliases) is written
#pragma unroll
    for (int i = 0; i < 3; i++)
        cpa8(smB1m + stsO + 1280 * i, w_f1h + (size_t)(r0 + 32 * i) * 192 + c4);
    cp_commit();
    cp_wait0();
    __syncthreads();

    // ---------- MLP: fc1 + GELU + fc2 ----------
    float acc2[2][6][4];
#pragma unroll
    for (int a = 0; a < 2; a++)
#pragma unroll
        for (int b_ = 0; b_ < 6; b_++)
#pragma unroll
            for (int cc = 0; cc < 4; cc++) acc2[a][b_][cc] = 0.f;

#pragma unroll 1
    for (int oc = 0; oc < 8; oc++) {
        const __half* W1 = w_f1h + (size_t)(oc * 96) * 192;
        const __half* W2 = w_f2h;

        float acc1[2][3][4];
#pragma unroll
        for (int a = 0; a < 2; a++)
#pragma unroll
            for (int b_ = 0; b_ < 3; b_++)
#pragma unroll
                for (int cc = 0; cc < 4; cc++) acc1[a][b_][cc] = 0.f;

#pragma unroll 1
        for (int kc = 0; kc < 6; kc++) {
            if (kc + 1 < 6) {
#pragma unroll
                for (int i = 0; i < 3; i++)
                    cpa8(smB1m + ((kc + 1) & 1) * 3840 + stsO + 1280 * i,
                         W1 + (size_t)(r0 + 32 * i) * 192 + (kc + 1) * 32 + c4);
                cp_commit();
            } else {
#pragma unroll
                for (int i = 0; i < 3; i++)
                    cpa16(smB2m + a16 + 2560 * i,
                          W2 + (size_t)(r16 + 64 * i) * 768 + oc * 96 + q8);
                cp_commit();
            }
            const __half* Ab = smA + kc * 2560;
            const __half* Bb = smB1m + (kc & 1) * 3840;
#pragma unroll
            for (int kk = 0; kk < 32; kk += 16) {
                unsigned af[2][4], b1r[4], b1s[2];
                ldsm4(af[0], Ab + wr * 40 + kk + aoff);
                ldsm4(af[1], Ab + (wr + 16) * 40 + kk + aoff);
                ldsm4(b1r, Bb + wc1 * 40 + kk + boff);
                ldsm2(b1s, Bb + (wc1 + 16) * 40 + kk + b2off);
#pragma unroll
                for (int m2 = 0; m2 < 2; m2++) {
                    mma16(acc1[m2][0], af[m2], b1r[0], b1r[1]);
                    mma16(acc1[m2][1], af[m2], b1r[2], b1r[3]);
                    mma16(acc1[m2][2], af[m2], b1s[0], b1s[1]);
                }
            }
            cp_wait0();
            __syncthreads();
        }

#pragma unroll
        for (int m2 = 0; m2 < 2; m2++)
#pragma unroll
            for (int ni = 0; ni < 3; ni++) {
                int row = wr + 16 * m2 + g;
                int col = wc1 + 8 * ni + 2 * tg;
                float2 bv = *(const float2*)(b1h + oc * 96 + col);
                __half* hp0 = smHm + (col >> 5) * 2560 + row * 40 + (col & 31);
                *(__half2*)hp0 = __floats2half2_rn(
                    gelu_f(acc1[m2][ni][0] + bv.x), gelu_f(acc1[m2][ni][1] + bv.y));
                *(__half2*)(hp0 + 320) = __floats2half2_rn(
                    gelu_f(acc1[m2][ni][2] + bv.x), gelu_f(acc1[m2][ni][3] + bv.y));
            }
        __syncthreads();

#pragma unroll 1
        for (int kc = 0; kc < 3; kc++) {
            bool w1pre = (kc == 2) && (oc + 1 < 8);
            if (kc + 1 < 3) {
#pragma unroll
                for (int i = 0; i < 3; i++)
                    cpa16(smB2m + ((kc + 1) & 1) * 7680 + a16 + 2560 * i,
                          W2 + (size_t)(r16 + 64 * i) * 768 + oc * 96 + (kc + 1) * 32 + q8);
                cp_commit();
            } else if (w1pre) {
#pragma unroll
                for (int i = 0; i < 3; i++)
                    cpa8(smB1m + stsO + 1280 * i,
                         w_f1h + (size_t)((oc + 1) * 96 + r0 + 32 * i) * 192 + c4);
                cp_commit();
            }
            const __half* Ab = smHm + kc * 2560;
            const __half* Bb = smB2m + (kc & 1) * 7680;
#pragma unroll
            for (int kk = 0; kk < 32; kk += 16) {
                unsigned af[2][4], bbf[3][4];
                ldsm4(af[0], Ab + wr * 40 + kk + aoff);
                ldsm4(af[1], Ab + (wr + 16) * 40 + kk + aoff);
#pragma unroll
                for (int p = 0; p < 3; p++)
                    ldsm4(bbf[p], Bb + (wc + 16 * p) * 40 + kk + boff);
#pragma unroll
                for (int m2 = 0; m2 < 2; m2++)
#pragma unroll
                    for (int ni = 0; ni < 6; ni++)
                        mma16(acc2[m2][ni], af[m2], bbf[ni >> 1][(ni & 1) * 2], bbf[ni >> 1][(ni & 1) * 2 + 1]);
            }
            cp_wait0();
            __syncthreads();
        }
    }

    // ---------- final: fragment LN2 + residual(x1h) + pixel scatter ----------
    {
        float sm_[2][2] = {{0.f,0.f},{0.f,0.f}}, sq_[2][2] = {{0.f,0.f},{0.f,0.f}};
#pragma unroll
        for (int m2 = 0; m2 < 2; m2++)
#pragma unroll
            for (int ni = 0; ni < 6; ni++) {
                float2 bv = *(const float2*)(b2 + wc + 8 * ni + 2 * tg);
                acc2[m2][ni][0] += bv.x; acc2[m2][ni][1] += bv.y;
                acc2[m2][ni][2] += bv.x; acc2[m2][ni][3] += bv.y;
                sm_[m2][0] += acc2[m2][ni][0] + acc2[m2][ni][1];
                sq_[m2][0] += acc2[m2][ni][0]*acc2[m2][ni][0] + acc2[m2][ni][1]*acc2[m2][ni][1];
                sm_[m2][1] += acc2[m2][ni][2] + acc2[m2][ni][3];
                sq_[m2][1] += acc2[m2][ni][2]*acc2[m2][ni][2] + acc2[m2][ni][3]*acc2[m2][ni][3];
            }
#pragma unroll
        for (int m2 = 0; m2 < 2; m2++)
#pragma unroll
            for (int hh = 0; hh < 2; hh++) {
                float sv = quad_sum(sm_[m2][hh]);
                float qv = quad_sum(sq_[m2][hh]);
                if (tg == 0) {
                    int r = wr + 16 * m2 + g + 8 * hh;
                    ps[cg64 + r] = sv;
                    pq[cg64 + r] = qv;
                }
            }
        __syncthreads();

#pragma unroll
        for (int m2 = 0; m2 < 2; m2++)
#pragma unroll
            for (int hh = 0; hh < 2; hh++) {
                int r = wr + 16 * m2 + g + 8 * hh;
                float S = ps[r] + ps[64 + r] + ps[128 + r] + ps[192 + r];
                float Q = pq[r] + pq[64 + r] + pq[128 + r] + pq[192 + r];
                float mean = S * (1.f / 192.f);
                float rstd = rsqrtf(Q * (1.f / 192.f) - mean * mean + 1e-5f);
                int hpx = (wh * 8 + (r >> 3) + 4) & 255;
                int wpx = (ww * 8 + (r & 7) + 4) & 255;
                size_t rowb = ((size_t)bI * HWd + hpx * Wdim + wpx) * Cd;
#pragma unroll
                for (int ni = 0; ni < 6; ni++) {
                    int c = wc + 8 * ni + 2 * tg;
                    float2 gg = *(const float2*)(g2 + c);
                    float2 bb = *(const float2*)(bb2 + c);
                    float2 x1 = __half22float2(*(const __half2*)(smA + (c >> 5) * 2560 + r * 40 + (c & 31)));
                    float2 yo;
                    yo.x = x1.x + (acc2[m2][ni][2*hh]   - mean) * rstd * gg.x + bb.x;
                    yo.y = x1.y + (acc2[m2][ni][2*hh+1] - mean) * rstd * gg.y + bb.y;
                    *(float2*)(out + rowb + c) = yo;
                }
            }
    }
}

// ======================= host =======================
extern "C" void kernel_launch(void* const* d_in, const int* in_sizes, int n_in,
                              void* d_out, int out_size)
{
    const float* x    = (const float*)d_in[0];
    const float* feat = (const float*)d_in[1];
    const int*   ridx = (const int*)  d_in[3];
    const float* rtab = (const float*)d_in[4];
    const float* q_w  = (const float*)d_in[5];
    const float* q_b  = (const float*)d_in[6];
    const float* kv_w = (const float*)d_in[7];
    const float* kv_b = (const float*)d_in[8];
    const float* p_w  = (const float*)d_in[9];
    const float* p_b  = (const float*)d_in[10];
    const float* m_w  = (const float*)d_in[11];
    const float* n1g  = (const float*)d_in[12];
    const float* n1b  = (const float*)d_in[13];
    const float* n2g  = (const float*)d_in[14];
    const float* n2b  = (const float*)d_in[15];
    const float* f1w  = (const float*)d_in[16];
    const float* f1b  = (const float*)d_in[17];
    const float* f2w  = (const float*)d_in[18];
    const float* f2b  = (const float*)d_in[19];
    float* out = (float*)d_out;

    const int smMega = 52224 * 2;                        // 104448
    cudaFuncSetAttribute(k_mega, cudaFuncAttributeMaxDynamicSharedMemorySize, smMega);

    k_pre <<<1824 + 49152, 256>>>(x, feat, q_w, kv_w, f1w, f2w,
                                  m_w, p_w, p_b, ridx, rtab);               // 0
    k_mega<<<NWINd, 256, smMega>>>(q_b, kv_b, n1g, n1b, f1b, f2b, n2g, n2b, out);  // 1
}